// round 4
// baseline (speedup 1.0000x reference)
#include <cuda_runtime.h>
#include <math.h>

#define LNUM 4
#define DM   256
#define NH   8
#define DHH  32
#define DI   1024
#define SEG  1024
#define MEML 1024
#define KL   2048
#define BSZ  2
#define NLD  12
#define H3   768          // 3*H*DH
#define PRED_N (BSZ*NLD*SEG)
#define SCALE 0.17677669529663687f   // 1/sqrt(32)

// ---------------- scratch (static device globals; no runtime allocation) ----------------
__device__ float g_core [SEG*BSZ*DM];
__device__ float g_heads[KL*BSZ*H3];
__device__ float g_r    [KL*DM];
__device__ float g_rk   [KL*DM];
__device__ float g_vec  [SEG*BSZ*DM];
__device__ float g_mid  [SEG*BSZ*DI];
__device__ float g_BD   [(size_t)BSZ*NH*SEG*KL];   // pre-shift BD (BDpre)

__device__ __forceinline__ float* bufsel(int id) {
    switch (id) {
        case 1: return g_r;
        case 2: return g_vec;
        case 3: return g_core;
        case 4: return g_mid;
        case 5: return g_heads;
        case 6: return g_rk;
    }
    return g_core;
}

// ---------------- tf32 helpers ----------------
__device__ __forceinline__ unsigned f2tf(float x) {
    unsigned u;
    asm("cvt.rna.tf32.f32 %0, %1;" : "=r"(u) : "f"(x));
    return u;
}
__device__ __forceinline__ void mma_tf32(float& c0, float& c1, float& c2, float& c3,
                                         unsigned a0, unsigned a1, unsigned a2, unsigned a3,
                                         unsigned b0, unsigned b1) {
    asm volatile(
        "mma.sync.aligned.m16n8k8.row.col.f32.tf32.tf32.f32 "
        "{%0,%1,%2,%3},{%4,%5,%6,%7},{%8,%9},{%0,%1,%2,%3};\n"
        : "+f"(c0), "+f"(c1), "+f"(c2), "+f"(c3)
        : "r"(a0), "r"(a1), "r"(a2), "r"(a3), "r"(b0), "r"(b1));
}

// ---------------- input projection: core = src^T @ W_in + b_in ; also mems_out[0] ----------------
__global__ void k_input_proj(const float* __restrict__ src, const float* __restrict__ W_in,
                             const float* __restrict__ b_in, float* __restrict__ memout) {
    int idx = blockIdx.x * blockDim.x + threadIdx.x;
    if (idx >= SEG*BSZ*DM) return;
    int d  = idx & (DM - 1);
    int sb = idx >> 8;
    int b  = sb & 1;
    int s  = sb >> 1;
    float acc = b_in[d];
#pragma unroll
    for (int l = 0; l < NLD; l++)
        acc += src[((size_t)b * NLD + l) * SEG + s] * W_in[l * DM + d];
    g_core[idx] = acc;
    memout[idx] = acc;   // new_mems[0] == hids[0]
}

// ---------------- positional embedding r[KLEN, D] ----------------
__global__ void k_pos() {
    int idx = blockIdx.x * blockDim.x + threadIdx.x;
    if (idx >= KL * DM) return;
    int d = idx & (DM - 1);
    int j = idx >> 8;
    float pos = (float)(KL - 1 - j);
    int f = (d < 128) ? d : d - 128;
    float inv = powf(10000.f, -(float)f / 128.f);
    float v = pos * inv;
    g_r[idx] = (d < 128) ? sinf(v) : cosf(v);
}

// ---------------- tf32 GEMM: C[M,N] = A[M,K] @ B[K,N] (+bias)(+relu) ----------------
// BM=128, BN=64, BK=16, 256 threads (8 warps: 4(M) x 2(N), warp tile 32x32).
// aid==100: virtual cat A: rows < MEML*BSZ from mems_i, else g_core.
__global__ void k_gemm_tf32(const float* __restrict__ mems_i, int aid,
                            const float* __restrict__ Bw, int cid,
                            int M, int N, int K,
                            const float* __restrict__ bias, int relu) {
    const float* A = bufsel(aid);
    float* C = bufsel(cid);
    __shared__ unsigned As[128][20];
    __shared__ unsigned Bs[16][72];
    int t = threadIdx.x;
    int m0 = blockIdx.y * 128, n0 = blockIdx.x * 64;
    int lane = t & 31, g = lane >> 2, tg = lane & 3;
    int w = t >> 5;
    int wm = (w >> 1) * 32, wn = (w & 1) * 32;
    float c[2][4][4];
#pragma unroll
    for (int i = 0; i < 2; i++)
#pragma unroll
        for (int j = 0; j < 4; j++)
#pragma unroll
            for (int q = 0; q < 4; q++) c[i][j][q] = 0.f;

    for (int k0 = 0; k0 < K; k0 += 16) {
#pragma unroll
        for (int i = 0; i < 2; i++) {
            int f = t + i * 256;
            int r = f >> 2, c4 = (f & 3) * 4;
            int rg = m0 + r;
            const float* Arow;
            if (aid == 100)
                Arow = (rg < MEML*BSZ) ? (mems_i + (size_t)rg * K)
                                       : (g_core + (size_t)(rg - MEML*BSZ) * K);
            else
                Arow = A + (size_t)rg * K;
            float4 v = *(const float4*)(Arow + k0 + c4);
            As[r][c4]   = f2tf(v.x); As[r][c4+1] = f2tf(v.y);
            As[r][c4+2] = f2tf(v.z); As[r][c4+3] = f2tf(v.w);
        }
        {
            int br = t >> 4, bc4 = (t & 15) * 4;
            float4 v = *(const float4*)(Bw + (size_t)(k0 + br) * N + n0 + bc4);
            Bs[br][bc4]   = f2tf(v.x); Bs[br][bc4+1] = f2tf(v.y);
            Bs[br][bc4+2] = f2tf(v.z); Bs[br][bc4+3] = f2tf(v.w);
        }
        __syncthreads();
#pragma unroll
        for (int ks = 0; ks < 16; ks += 8) {
            unsigned a[2][4], bfrag[4][2];
#pragma unroll
            for (int mt = 0; mt < 2; mt++) {
                int r = wm + mt * 16 + g;
                a[mt][0] = As[r][ks + tg];
                a[mt][1] = As[r + 8][ks + tg];
                a[mt][2] = As[r][ks + tg + 4];
                a[mt][3] = As[r + 8][ks + tg + 4];
            }
#pragma unroll
            for (int nt = 0; nt < 4; nt++) {
                int col = wn + nt * 8 + g;
                bfrag[nt][0] = Bs[ks + tg][col];
                bfrag[nt][1] = Bs[ks + tg + 4][col];
            }
#pragma unroll
            for (int mt = 0; mt < 2; mt++)
#pragma unroll
                for (int nt = 0; nt < 4; nt++)
                    mma_tf32(c[mt][nt][0], c[mt][nt][1], c[mt][nt][2], c[mt][nt][3],
                             a[mt][0], a[mt][1], a[mt][2], a[mt][3],
                             bfrag[nt][0], bfrag[nt][1]);
        }
        __syncthreads();
    }
#pragma unroll
    for (int mt = 0; mt < 2; mt++) {
#pragma unroll
        for (int nt = 0; nt < 4; nt++) {
            int row = m0 + wm + mt * 16 + g;
            int col = n0 + wn + nt * 8 + 2 * tg;
            float b0 = 0.f, b1 = 0.f;
            if (bias) { b0 = bias[col]; b1 = bias[col + 1]; }
            float v0 = c[mt][nt][0] + b0, v1 = c[mt][nt][1] + b1;
            float v2 = c[mt][nt][2] + b0, v3 = c[mt][nt][3] + b1;
            if (relu) {
                v0 = fmaxf(v0, 0.f); v1 = fmaxf(v1, 0.f);
                v2 = fmaxf(v2, 0.f); v3 = fmaxf(v3, 0.f);
            }
            *(float2*)(C + (size_t)row * N + col)       = make_float2(v0, v1);
            *(float2*)(C + (size_t)(row + 8) * N + col) = make_float2(v2, v3);
        }
    }
}

// ---------------- tf32 BDpre: per (b,h): BDpre[i,m] = (q_i + rrb) . rk[m] ----------------
// BM=128, BN=64, 256 threads (8 warps: 4x2, warp tile 32x32). K=DH=32 single smem shot.
__global__ void k_bd_tf32(const float* __restrict__ rrb) {
    int bh = blockIdx.z, b = bh >> 3, h = bh & 7;
    int i0 = blockIdx.y * 128, j0 = blockIdx.x * 64;
    const float* Qp = g_heads + (size_t)(MEML*BSZ + b) * H3 + h*DHH;
    const float* Kp = g_rk + h*DHH;
    float* Cp = g_BD + (size_t)bh * SEG * KL;
    const float* qb = rrb + h*DHH;

    __shared__ unsigned Qs[128][36];
    __shared__ unsigned Ks[64][36];
    int t = threadIdx.x;
    int lane = t & 31, g = lane >> 2, tg = lane & 3;
    int w = t >> 5;
    int wm = (w >> 1) * 32, wn = (w & 1) * 32;

#pragma unroll
    for (int i = 0; i < 4; i++) {
        int f = t + i * 256;
        int r = f >> 3, c4 = (f & 7) * 4;
        float4 v = *(const float4*)(Qp + (size_t)(i0 + r) * (BSZ*H3) + c4);
        Qs[r][c4]   = f2tf(v.x + qb[c4]);   Qs[r][c4+1] = f2tf(v.y + qb[c4+1]);
        Qs[r][c4+2] = f2tf(v.z + qb[c4+2]); Qs[r][c4+3] = f2tf(v.w + qb[c4+3]);
    }
#pragma unroll
    for (int i = 0; i < 2; i++) {
        int f = t + i * 256;
        int r = f >> 3, c4 = (f & 7) * 4;
        float4 v = *(const float4*)(Kp + (size_t)(j0 + r) * DM + c4);
        Ks[r][c4]   = f2tf(v.x); Ks[r][c4+1] = f2tf(v.y);
        Ks[r][c4+2] = f2tf(v.z); Ks[r][c4+3] = f2tf(v.w);
    }
    __syncthreads();

    float c[2][4][4];
#pragma unroll
    for (int i = 0; i < 2; i++)
#pragma unroll
        for (int j = 0; j < 4; j++)
#pragma unroll
            for (int q = 0; q < 4; q++) c[i][j][q] = 0.f;

#pragma unroll
    for (int ks = 0; ks < 32; ks += 8) {
        unsigned a[2][4], bfrag[4][2];
#pragma unroll
        for (int mt = 0; mt < 2; mt++) {
            int r = wm + mt * 16 + g;
            a[mt][0] = Qs[r][ks + tg];
            a[mt][1] = Qs[r + 8][ks + tg];
            a[mt][2] = Qs[r][ks + tg + 4];
            a[mt][3] = Qs[r + 8][ks + tg + 4];
        }
#pragma unroll
        for (int nt = 0; nt < 4; nt++) {
            int col = wn + nt * 8 + g;
            bfrag[nt][0] = Ks[col][ks + tg];
            bfrag[nt][1] = Ks[col][ks + tg + 4];
        }
#pragma unroll
        for (int mt = 0; mt < 2; mt++)
#pragma unroll
            for (int nt = 0; nt < 4; nt++)
                mma_tf32(c[mt][nt][0], c[mt][nt][1], c[mt][nt][2], c[mt][nt][3],
                         a[mt][0], a[mt][1], a[mt][2], a[mt][3],
                         bfrag[nt][0], bfrag[nt][1]);
    }
#pragma unroll
    for (int mt = 0; mt < 2; mt++)
#pragma unroll
        for (int nt = 0; nt < 4; nt++) {
            int row = i0 + wm + mt * 16 + g;
            int col = j0 + wn + nt * 8 + 2 * tg;
            *(float2*)(Cp + (size_t)row * KL + col)       = make_float2(c[mt][nt][0], c[mt][nt][1]);
            *(float2*)(Cp + (size_t)(row + 8) * KL + col) = make_float2(c[mt][nt][2], c[mt][nt][3]);
        }
}

// ---------------- flash attention: AC-QK + shifted BD + online softmax + PV ----------------
// grid (SEG/64, BSZ*NH), 256 threads, dynamic smem.
// i-tile = 64 rows, j-tile = 128.
#define FL_QS   (64*36)
#define FL_KS   (128*36)
#define FL_VST  (32*132)
#define FL_SM   (64*132)
#define FL_SMEM ((FL_QS + FL_KS + FL_VST + FL_SM)*4 + 3*64*4)

__global__ void __launch_bounds__(256)
k_flash(const unsigned char* __restrict__ mask, const float* __restrict__ rwb) {
    extern __shared__ unsigned smem_u[];
    unsigned* Qs  = smem_u;                   // [64][36]
    unsigned* Ks  = Qs + FL_QS;               // [128][36]
    unsigned* Vst = Ks + FL_KS;               // [32][132] (V transposed: [d][j])
    unsigned* Sm  = Vst + FL_VST;             // [64][132] float bits / tf32 probs
    float* rowm = (float*)(Sm + FL_SM);
    float* rowl = rowm + 64;
    float* rsc  = rowl + 64;

    int bh = blockIdx.y, b = bh >> 3, h = bh & 7;
    int i0 = blockIdx.x * 64;
    int t = threadIdx.x;
    int lane = t & 31, g = lane >> 2, tg = lane & 3;
    int w = t >> 5;

    const float* Qp  = g_heads + (size_t)(MEML*BSZ + b) * H3 + h*DHH;
    const float* Kp  = g_heads + (size_t)b * H3 + DM + h*DHH;
    const float* Vp  = g_heads + (size_t)b * H3 + 2*DM + h*DHH;
    const float* BDp = g_BD + (size_t)bh * SEG * KL;
    const float* qb  = rwb + h*DHH;

    // load Q (+ r_w_bias)
    for (int f = t; f < 512; f += 256) {
        int r = f >> 3, c4 = (f & 7) * 4;
        float4 v = *(const float4*)(Qp + (size_t)(i0 + r) * (BSZ*H3) + c4);
        Qs[r*36 + c4]   = f2tf(v.x + qb[c4]);   Qs[r*36 + c4+1] = f2tf(v.y + qb[c4+1]);
        Qs[r*36 + c4+2] = f2tf(v.z + qb[c4+2]); Qs[r*36 + c4+3] = f2tf(v.w + qb[c4+3]);
    }
    if (t < 64) { rowm[t] = -INFINITY; rowl[t] = 0.f; }

    // warp layouts
    int wmA = (w & 1) * 32, wnA = (w >> 1) * 32;   // AC: 2(M) x 4(N), warp 32x32
    int wm2 = (w >> 1) * 16, wn2 = (w & 1) * 16;   // PV: 4(M) x 2(N), warp 16x16

    float o[2][4];
#pragma unroll
    for (int i = 0; i < 2; i++)
#pragma unroll
        for (int q = 0; q < 4; q++) o[i][q] = 0.f;

    // softmax thread mapping: row r = t>>2, quad qd = t&3, cols qd + 4*cc
    int sr = t >> 2, qd = t & 3;
    int gi = i0 + sr;

    for (int j0 = 0; j0 < KL; j0 += 128) {
        __syncthreads();   // protect Ks/Vst/Sm from previous iteration's readers
        // load K and V tiles
        for (int f = t; f < 1024; f += 256) {
            int r = f >> 3, c4 = (f & 7) * 4;
            float4 kv = *(const float4*)(Kp + (size_t)(j0 + r) * (BSZ*H3) + c4);
            Ks[r*36 + c4]   = f2tf(kv.x); Ks[r*36 + c4+1] = f2tf(kv.y);
            Ks[r*36 + c4+2] = f2tf(kv.z); Ks[r*36 + c4+3] = f2tf(kv.w);
            float4 vv = *(const float4*)(Vp + (size_t)(j0 + r) * (BSZ*H3) + c4);
            Vst[(c4  )*132 + r] = f2tf(vv.x);
            Vst[(c4+1)*132 + r] = f2tf(vv.y);
            Vst[(c4+2)*132 + r] = f2tf(vv.z);
            Vst[(c4+3)*132 + r] = f2tf(vv.w);
        }
        __syncthreads();

        // AC mma: S = Q . K^T (64x128, K=32)
        float c[2][4][4];
#pragma unroll
        for (int i = 0; i < 2; i++)
#pragma unroll
            for (int j = 0; j < 4; j++)
#pragma unroll
                for (int q = 0; q < 4; q++) c[i][j][q] = 0.f;
#pragma unroll
        for (int ks = 0; ks < 32; ks += 8) {
            unsigned a[2][4], bfrag[4][2];
#pragma unroll
            for (int mt = 0; mt < 2; mt++) {
                int r = wmA + mt * 16 + g;
                a[mt][0] = Qs[r*36 + ks + tg];
                a[mt][1] = Qs[(r+8)*36 + ks + tg];
                a[mt][2] = Qs[r*36 + ks + tg + 4];
                a[mt][3] = Qs[(r+8)*36 + ks + tg + 4];
            }
#pragma unroll
            for (int nt = 0; nt < 4; nt++) {
                int col = wnA + nt * 8 + g;
                bfrag[nt][0] = Ks[col*36 + ks + tg];
                bfrag[nt][1] = Ks[col*36 + ks + tg + 4];
            }
#pragma unroll
            for (int mt = 0; mt < 2; mt++)
#pragma unroll
                for (int nt = 0; nt < 4; nt++)
                    mma_tf32(c[mt][nt][0], c[mt][nt][1], c[mt][nt][2], c[mt][nt][3],
                             a[mt][0], a[mt][1], a[mt][2], a[mt][3],
                             bfrag[nt][0], bfrag[nt][1]);
        }
        // stage scores to smem
#pragma unroll
        for (int mt = 0; mt < 2; mt++)
#pragma unroll
            for (int nt = 0; nt < 4; nt++) {
                int row = wmA + mt * 16 + g;
                int col = wnA + nt * 8 + 2 * tg;
                Sm[row*132 + col]     = __float_as_uint(c[mt][nt][0]);
                Sm[row*132 + col + 1] = __float_as_uint(c[mt][nt][1]);
                Sm[(row+8)*132 + col]     = __float_as_uint(c[mt][nt][2]);
                Sm[(row+8)*132 + col + 1] = __float_as_uint(c[mt][nt][3]);
            }
        __syncthreads();

        // softmax: add shifted BD, scale, mask; online max/sum
        float mloc = -INFINITY;
#pragma unroll
        for (int cc = 0; cc < 32; cc++) {
            int col = qd + 4 * cc;
            int j = j0 + col;
            int u = MEML + j - gi;             // 1024 + j - i
            float bd;
            if (u <= KL) bd = BDp[(size_t)gi * KL + (u - 1)];
            else {
                int p = u - (KL + 1);
                bd = p ? BDp[(size_t)(gi + 1) * KL + (p - 1)] : 0.f;
            }
            float s = (__uint_as_float(Sm[sr*132 + col]) + bd) * SCALE;
            if (mask[(size_t)gi * KL + j]) s = -INFINITY;
            Sm[sr*132 + col] = __float_as_uint(s);
            mloc = fmaxf(mloc, s);
        }
        mloc = fmaxf(mloc, __shfl_xor_sync(0xffffffffu, mloc, 1));
        mloc = fmaxf(mloc, __shfl_xor_sync(0xffffffffu, mloc, 2));
        float mold = rowm[sr];
        float mnew = fmaxf(mold, mloc);
        float fac = __expf(mold - mnew);
        float lloc = 0.f;
#pragma unroll
        for (int cc = 0; cc < 32; cc++) {
            int col = qd + 4 * cc;
            float p = __expf(__uint_as_float(Sm[sr*132 + col]) - mnew);
            lloc += p;
            Sm[sr*132 + col] = f2tf(p);
        }
        lloc += __shfl_xor_sync(0xffffffffu, lloc, 1);
        lloc += __shfl_xor_sync(0xffffffffu, lloc, 2);
        if (qd == 0) { rowm[sr] = mnew; rowl[sr] = rowl[sr] * fac + lloc; rsc[sr] = fac; }
        __syncthreads();

        // rescale O accumulators
        float f0 = rsc[wm2 + g], f1 = rsc[wm2 + g + 8];
#pragma unroll
        for (int nt2 = 0; nt2 < 2; nt2++) {
            o[nt2][0] *= f0; o[nt2][1] *= f0;
            o[nt2][2] *= f1; o[nt2][3] *= f1;
        }
        // PV mma: O += P . V (64x32, K=128)
#pragma unroll
        for (int ks = 0; ks < 128; ks += 8) {
            unsigned a0 = Sm[(wm2+g)*132 + ks + tg];
            unsigned a1 = Sm[(wm2+g+8)*132 + ks + tg];
            unsigned a2 = Sm[(wm2+g)*132 + ks + tg + 4];
            unsigned a3 = Sm[(wm2+g+8)*132 + ks + tg + 4];
#pragma unroll
            for (int nt2 = 0; nt2 < 2; nt2++) {
                int col = wn2 + nt2 * 8 + g;
                unsigned b0 = Vst[col*132 + ks + tg];
                unsigned b1 = Vst[col*132 + ks + tg + 4];
                mma_tf32(o[nt2][0], o[nt2][1], o[nt2][2], o[nt2][3], a0, a1, a2, a3, b0, b1);
            }
        }
    }
    // epilogue: divide by l, write g_vec
    float inv0 = 1.f / rowl[wm2 + g], inv1 = 1.f / rowl[wm2 + g + 8];
#pragma unroll
    for (int nt2 = 0; nt2 < 2; nt2++) {
        int row = i0 + wm2 + g;
        int col = h*DHH + wn2 + nt2 * 8 + 2 * tg;
        *(float2*)(g_vec + (size_t)(row * BSZ + b) * DM + col) =
            make_float2(o[nt2][0] * inv0, o[nt2][1] * inv0);
        *(float2*)(g_vec + (size_t)((row + 8) * BSZ + b) * DM + col) =
            make_float2(o[nt2][2] * inv1, o[nt2][3] * inv1);
    }
}

// ---------------- residual add + LayerNorm; optional write to mems output ----------------
__global__ void k_addln(int did, const float* __restrict__ gamma, const float* __restrict__ beta,
                        float* __restrict__ memout) {
    const float* delta = bufsel(did);
    int row = blockIdx.x, d = threadIdx.x;
    size_t off = (size_t)row * DM + d;
    float x = g_core[off] + delta[off];
    __shared__ float red[DM];
    red[d] = x; __syncthreads();
    for (int s = 128; s > 0; s >>= 1) { if (d < s) red[d] += red[d+s]; __syncthreads(); }
    float mu = red[0] * (1.f/DM); __syncthreads();
    float c = x - mu;
    red[d] = c * c; __syncthreads();
    for (int s = 128; s > 0; s >>= 1) { if (d < s) red[d] += red[d+s]; __syncthreads(); }
    float var = red[0] * (1.f/DM);
    float y = c * (1.f / sqrtf(var + 1e-5f)) * gamma[d] + beta[d];
    g_core[off] = y;
    if (memout) memout[off] = y;
}

// ---------------- decoder ----------------
__global__ void k_dec(const float* __restrict__ Wd, const float* __restrict__ bd,
                      float* __restrict__ pred) {
    __shared__ float Wds[DM * NLD];
    int t = threadIdx.x;
    for (int i = t; i < DM * NLD; i += 256) Wds[i] = Wd[i];
    __syncthreads();
    int lane = t & 31, w = t >> 5;
    int row = blockIdx.x * 8 + w;          // row = s*BSZ + b
    int b = row & 1, s = row >> 1;
    const float* crow = g_core + (size_t)row * DM;
    float v[8];
#pragma unroll
    for (int i = 0; i < 8; i++) v[i] = crow[lane + i * 32];
#pragma unroll
    for (int l = 0; l < NLD; l++) {
        float acc = 0.f;
#pragma unroll
        for (int i = 0; i < 8; i++) acc += v[i] * Wds[(lane + i * 32) * NLD + l];
#pragma unroll
        for (int o = 16; o > 0; o >>= 1) acc += __shfl_down_sync(0xffffffffu, acc, o);
        if (lane == 0)
            pred[((size_t)b * NLD + l) * SEG + s] = acc + bd[l];
    }
}

// ---------------- host launcher ----------------
extern "C" void kernel_launch(void* const* d_in, const int* in_sizes, int n_in,
                              void* d_out, int out_size) {
    (void)in_sizes; (void)n_in; (void)out_size;
    const float* src      = (const float*)d_in[0];
    const float* mems     = (const float*)d_in[1];
    const unsigned char* mask = (const unsigned char*)d_in[2];
    const float* W_in     = (const float*)d_in[3];
    const float* b_in     = (const float*)d_in[4];
    const float* qkv_w    = (const float*)d_in[5];
    const float* r_net_w  = (const float*)d_in[6];
    const float* o_w      = (const float*)d_in[7];
    const float* ln1_g    = (const float*)d_in[8];
    const float* ln1_b    = (const float*)d_in[9];
    const float* ff_w1    = (const float*)d_in[10];
    const float* ff_b1    = (const float*)d_in[11];
    const float* ff_w2    = (const float*)d_in[12];
    const float* ff_b2    = (const float*)d_in[13];
    const float* ln2_g    = (const float*)d_in[14];
    const float* ln2_b    = (const float*)d_in[15];
    const float* W_dec    = (const float*)d_in[16];
    const float* b_dec    = (const float*)d_in[17];
    const float* r_w_bias = (const float*)d_in[18];
    const float* r_r_bias = (const float*)d_in[19];

    float* out    = (float*)d_out;
    float* pred   = out;
    float* memout = out + PRED_N;

    cudaFuncSetAttribute(k_flash, cudaFuncAttributeMaxDynamicSharedMemorySize, FL_SMEM);

    k_input_proj<<<(SEG*BSZ*DM + 255)/256, 256>>>(src, W_in, b_in, memout);
    k_pos<<<(KL*DM + 255)/256, 256>>>();

    for (int i = 0; i < LNUM; i++) {
        // heads = [mems_i ; core] @ qkv_w[i]   [4096 x 768 x 256], cat fused
        k_gemm_tf32<<<dim3(H3/64, (KL*BSZ)/128), 256>>>(mems + (size_t)i * MEML*BSZ*DM, 100,
                                                        qkv_w + (size_t)i*DM*H3, 5,
                                                        KL*BSZ, H3, DM, nullptr, 0);
        // rk = r @ r_net_w[i]      [2048 x 256 x 256]
        k_gemm_tf32<<<dim3(DM/64, KL/128), 256>>>(nullptr, 1, r_net_w + (size_t)i*DM*DM, 6,
                                                  KL, DM, DM, nullptr, 0);
        // BDpre
        k_bd_tf32<<<dim3(KL/64, SEG/128, BSZ*NH), 256>>>(r_r_bias);
        // fused attention
        k_flash<<<dim3(SEG/64, BSZ*NH), 256, FL_SMEM>>>(mask, r_w_bias);
        // attn output projection     [2048 x 256 x 256]
        k_gemm_tf32<<<dim3(DM/64, (SEG*BSZ)/128), 256>>>(nullptr, 2, o_w + (size_t)i*DM*DM, 4,
                                                         SEG*BSZ, DM, DM, nullptr, 0);
        k_addln<<<SEG*BSZ, DM>>>(4, ln1_g + i*DM, ln1_b + i*DM, nullptr);
        // ff1 + bias + relu          [2048 x 1024 x 256]
        k_gemm_tf32<<<dim3(DI/64, (SEG*BSZ)/128), 256>>>(nullptr, 3, ff_w1 + (size_t)i*DM*DI, 4,
                                                         SEG*BSZ, DI, DM, ff_b1 + i*DI, 1);
        // ff2 + bias                 [2048 x 256 x 1024]
        k_gemm_tf32<<<dim3(DM/64, (SEG*BSZ)/128), 256>>>(nullptr, 4, ff_w2 + (size_t)i*DI*DM, 2,
                                                         SEG*BSZ, DM, DI, ff_b2 + i*DM, 0);
        k_addln<<<SEG*BSZ, DM>>>(2, ln2_g + i*DM, ln2_b + i*DM,
                                 memout + (size_t)(i+1)*SEG*BSZ*DM);
    }
    k_dec<<<(SEG*BSZ)/8, 256>>>(W_dec, b_dec, pred);
}

// round 5
// speedup vs baseline: 1.0521x; 1.0521x over previous
#include <cuda_runtime.h>
#include <math.h>

#define LNUM 4
#define DM   256
#define NH   8
#define DHH  32
#define DI   1024
#define SEG  1024
#define MEML 1024
#define KL   2048
#define BSZ  2
#define NLD  12
#define H3   768          // 3*H*DH
#define PRED_N (BSZ*NLD*SEG)
#define SCALE 0.17677669529663687f   // 1/sqrt(32)

// ---------------- scratch (static device globals; no runtime allocation) ----------------
__device__ float g_core [SEG*BSZ*DM];
__device__ float g_heads[KL*BSZ*H3];
__device__ float g_r    [KL*DM];
__device__ float g_rk   [KL*DM];
__device__ float g_vec  [SEG*BSZ*DM];
__device__ float g_mid  [SEG*BSZ*DI];
__device__ float g_AC   [(size_t)BSZ*NH*SEG*KL];   // AC scores
__device__ float g_BD   [(size_t)BSZ*NH*SEG*KL];   // pre-shift BD (BDpre)

__device__ __forceinline__ float* bufsel(int id) {
    switch (id) {
        case 1: return g_r;
        case 2: return g_vec;
        case 3: return g_core;
        case 4: return g_mid;
        case 5: return g_heads;
        case 6: return g_rk;
    }
    return g_core;
}

// ---------------- tf32 helpers ----------------
__device__ __forceinline__ unsigned f2tf(float x) {
    unsigned u;
    asm("cvt.rna.tf32.f32 %0, %1;" : "=r"(u) : "f"(x));
    return u;
}
__device__ __forceinline__ void mma_tf32(float& c0, float& c1, float& c2, float& c3,
                                         unsigned a0, unsigned a1, unsigned a2, unsigned a3,
                                         unsigned b0, unsigned b1) {
    asm volatile(
        "mma.sync.aligned.m16n8k8.row.col.f32.tf32.tf32.f32 "
        "{%0,%1,%2,%3},{%4,%5,%6,%7},{%8,%9},{%0,%1,%2,%3};\n"
        : "+f"(c0), "+f"(c1), "+f"(c2), "+f"(c3)
        : "r"(a0), "r"(a1), "r"(a2), "r"(a3), "r"(b0), "r"(b1));
}

// ---------------- input projection: core = src^T @ W_in + b_in ; also mems_out[0] ----------------
__global__ void k_input_proj(const float* __restrict__ src, const float* __restrict__ W_in,
                             const float* __restrict__ b_in, float* __restrict__ memout) {
    int idx = blockIdx.x * blockDim.x + threadIdx.x;
    if (idx >= SEG*BSZ*DM) return;
    int d  = idx & (DM - 1);
    int sb = idx >> 8;
    int b  = sb & 1;
    int s  = sb >> 1;
    float acc = b_in[d];
#pragma unroll
    for (int l = 0; l < NLD; l++)
        acc += src[((size_t)b * NLD + l) * SEG + s] * W_in[l * DM + d];
    g_core[idx] = acc;
    memout[idx] = acc;   // new_mems[0] == hids[0]
}

// ---------------- positional embedding r[KLEN, D] ----------------
__global__ void k_pos() {
    int idx = blockIdx.x * blockDim.x + threadIdx.x;
    if (idx >= KL * DM) return;
    int d = idx & (DM - 1);
    int j = idx >> 8;
    float pos = (float)(KL - 1 - j);
    int f = (d < 128) ? d : d - 128;
    float inv = powf(10000.f, -(float)f / 128.f);
    float v = pos * inv;
    g_r[idx] = (d < 128) ? sinf(v) : cosf(v);
}

// ---------------- tf32 GEMM: C[M,N] = A[M,K] @ B[K,N] (+bias)(+relu) ----------------
// BM in {128,64}, BN=64, BK=16, 256 threads (8 warps: 4(M) x 2(N)).
// aid==100: virtual cat A: rows < MEML*BSZ from mems_i, else g_core.
template<int BM>
__global__ void k_gemm_tf32(const float* __restrict__ mems_i, int aid,
                            const float* __restrict__ Bw, int cid,
                            int M, int N, int K,
                            const float* __restrict__ bias, int relu) {
    constexpr int MT = BM / 64;
    const float* A = bufsel(aid);
    float* C = bufsel(cid);
    __shared__ unsigned As[BM][20];
    __shared__ unsigned Bs[16][72];
    int t = threadIdx.x;
    int m0 = blockIdx.y * BM, n0 = blockIdx.x * 64;
    int lane = t & 31, g = lane >> 2, tg = lane & 3;
    int w = t >> 5;
    int wm = (w >> 1) * 16 * MT, wn = (w & 1) * 32;
    float c[MT][4][4];
#pragma unroll
    for (int i = 0; i < MT; i++)
#pragma unroll
        for (int j = 0; j < 4; j++)
#pragma unroll
            for (int q = 0; q < 4; q++) c[i][j][q] = 0.f;

    for (int k0 = 0; k0 < K; k0 += 16) {
#pragma unroll
        for (int i = 0; i < MT; i++) {
            int f = t + i * 256;
            int r = f >> 2, c4 = (f & 3) * 4;
            int rg = m0 + r;
            const float* Arow;
            if (aid == 100)
                Arow = (rg < MEML*BSZ) ? (mems_i + (size_t)rg * K)
                                       : (g_core + (size_t)(rg - MEML*BSZ) * K);
            else
                Arow = A + (size_t)rg * K;
            float4 v = *(const float4*)(Arow + k0 + c4);
            As[r][c4]   = f2tf(v.x); As[r][c4+1] = f2tf(v.y);
            As[r][c4+2] = f2tf(v.z); As[r][c4+3] = f2tf(v.w);
        }
        {
            int br = t >> 4, bc4 = (t & 15) * 4;
            float4 v = *(const float4*)(Bw + (size_t)(k0 + br) * N + n0 + bc4);
            Bs[br][bc4]   = f2tf(v.x); Bs[br][bc4+1] = f2tf(v.y);
            Bs[br][bc4+2] = f2tf(v.z); Bs[br][bc4+3] = f2tf(v.w);
        }
        __syncthreads();
#pragma unroll
        for (int ks = 0; ks < 16; ks += 8) {
            unsigned a[MT][4], bfrag[4][2];
#pragma unroll
            for (int mt = 0; mt < MT; mt++) {
                int r = wm + mt * 16 + g;
                a[mt][0] = As[r][ks + tg];
                a[mt][1] = As[r + 8][ks + tg];
                a[mt][2] = As[r][ks + tg + 4];
                a[mt][3] = As[r + 8][ks + tg + 4];
            }
#pragma unroll
            for (int nt = 0; nt < 4; nt++) {
                int col = wn + nt * 8 + g;
                bfrag[nt][0] = Bs[ks + tg][col];
                bfrag[nt][1] = Bs[ks + tg + 4][col];
            }
#pragma unroll
            for (int mt = 0; mt < MT; mt++)
#pragma unroll
                for (int nt = 0; nt < 4; nt++)
                    mma_tf32(c[mt][nt][0], c[mt][nt][1], c[mt][nt][2], c[mt][nt][3],
                             a[mt][0], a[mt][1], a[mt][2], a[mt][3],
                             bfrag[nt][0], bfrag[nt][1]);
        }
        __syncthreads();
    }
#pragma unroll
    for (int mt = 0; mt < MT; mt++) {
#pragma unroll
        for (int nt = 0; nt < 4; nt++) {
            int row = m0 + wm + mt * 16 + g;
            int col = n0 + wn + nt * 8 + 2 * tg;
            float b0 = 0.f, b1 = 0.f;
            if (bias) { b0 = bias[col]; b1 = bias[col + 1]; }
            float v0 = c[mt][nt][0] + b0, v1 = c[mt][nt][1] + b1;
            float v2 = c[mt][nt][2] + b0, v3 = c[mt][nt][3] + b1;
            if (relu) {
                v0 = fmaxf(v0, 0.f); v1 = fmaxf(v1, 0.f);
                v2 = fmaxf(v2, 0.f); v3 = fmaxf(v3, 0.f);
            }
            *(float2*)(C + (size_t)row * N + col)       = make_float2(v0, v1);
            *(float2*)(C + (size_t)(row + 8) * N + col) = make_float2(v2, v3);
        }
    }
}

// ---------------- tf32 QK^T: mode 0 -> AC (K from heads), mode 1 -> BDpre (K from rk) ----------------
// per (b,h): C[i,j] = sum_d (Q[i,d]+qbias[d]) * Kmat[j,d] ; K=DH=32 single smem shot.
// BM=128, BN=64, 256 threads (8 warps: 4x2, warp tile 32x32).
__global__ void k_qk_tf32(int mode, const float* __restrict__ qbias) {
    int bh = blockIdx.z, b = bh >> 3, h = bh & 7;
    int i0 = blockIdx.y * 128, j0 = blockIdx.x * 64;
    const float* Qp = g_heads + (size_t)(MEML*BSZ + b) * H3 + h*DHH;
    const float* Kp; int kstr;
    float* Cp;
    if (mode == 0) { Kp = g_heads + (size_t)b*H3 + DM + h*DHH; kstr = BSZ*H3; Cp = g_AC; }
    else           { Kp = g_rk + h*DHH;                        kstr = DM;     Cp = g_BD; }
    Cp += (size_t)bh * SEG * KL;
    const float* qb = qbias + h*DHH;

    __shared__ unsigned Qs[128][36];
    __shared__ unsigned Ks[64][36];
    int t = threadIdx.x;
    int lane = t & 31, g = lane >> 2, tg = lane & 3;
    int w = t >> 5;
    int wm = (w >> 1) * 32, wn = (w & 1) * 32;

#pragma unroll
    for (int i = 0; i < 4; i++) {
        int f = t + i * 256;
        int r = f >> 3, c4 = (f & 7) * 4;
        float4 v = *(const float4*)(Qp + (size_t)(i0 + r) * (BSZ*H3) + c4);
        Qs[r][c4]   = f2tf(v.x + qb[c4]);   Qs[r][c4+1] = f2tf(v.y + qb[c4+1]);
        Qs[r][c4+2] = f2tf(v.z + qb[c4+2]); Qs[r][c4+3] = f2tf(v.w + qb[c4+3]);
    }
#pragma unroll
    for (int i = 0; i < 2; i++) {
        int f = t + i * 256;
        int r = f >> 3, c4 = (f & 7) * 4;
        float4 v = *(const float4*)(Kp + (size_t)(j0 + r) * kstr + c4);
        Ks[r][c4]   = f2tf(v.x); Ks[r][c4+1] = f2tf(v.y);
        Ks[r][c4+2] = f2tf(v.z); Ks[r][c4+3] = f2tf(v.w);
    }
    __syncthreads();

    float c[2][4][4];
#pragma unroll
    for (int i = 0; i < 2; i++)
#pragma unroll
        for (int j = 0; j < 4; j++)
#pragma unroll
            for (int q = 0; q < 4; q++) c[i][j][q] = 0.f;

#pragma unroll
    for (int ks = 0; ks < 32; ks += 8) {
        unsigned a[2][4], bfrag[4][2];
#pragma unroll
        for (int mt = 0; mt < 2; mt++) {
            int r = wm + mt * 16 + g;
            a[mt][0] = Qs[r][ks + tg];
            a[mt][1] = Qs[r + 8][ks + tg];
            a[mt][2] = Qs[r][ks + tg + 4];
            a[mt][3] = Qs[r + 8][ks + tg + 4];
        }
#pragma unroll
        for (int nt = 0; nt < 4; nt++) {
            int col = wn + nt * 8 + g;
            bfrag[nt][0] = Ks[col][ks + tg];
            bfrag[nt][1] = Ks[col][ks + tg + 4];
        }
#pragma unroll
        for (int mt = 0; mt < 2; mt++)
#pragma unroll
            for (int nt = 0; nt < 4; nt++)
                mma_tf32(c[mt][nt][0], c[mt][nt][1], c[mt][nt][2], c[mt][nt][3],
                         a[mt][0], a[mt][1], a[mt][2], a[mt][3],
                         bfrag[nt][0], bfrag[nt][1]);
    }
#pragma unroll
    for (int mt = 0; mt < 2; mt++)
#pragma unroll
        for (int nt = 0; nt < 4; nt++) {
            int row = i0 + wm + mt * 16 + g;
            int col = j0 + wn + nt * 8 + 2 * tg;
            *(float2*)(Cp + (size_t)row * KL + col)       = make_float2(c[mt][nt][0], c[mt][nt][1]);
            *(float2*)(Cp + (size_t)(row + 8) * KL + col) = make_float2(c[mt][nt][2], c[mt][nt][3]);
        }
}

// ---------------- fused shift+softmax+PV: reads g_AC/g_BD, writes g_vec ----------------
// grid (SEG/64, BSZ*NH), 256 threads, ~51KB dyn smem -> ~4 blocks/SM.
#define SP_SM   (64*132)
#define SP_VST  (32*132)
#define SP_SMEM ((SP_SM + SP_VST)*4 + 3*64*4)

__global__ void __launch_bounds__(256)
k_spv(const unsigned char* __restrict__ mask, const float* __restrict__ dummy) {
    extern __shared__ unsigned smem_u[];
    unsigned* Sm  = smem_u;                   // [64][132] score bits / tf32 probs
    unsigned* Vst = Sm + SP_SM;               // [32][132] V transposed [d][j]
    float* rowm = (float*)(Vst + SP_VST);
    float* rowl = rowm + 64;
    float* rsc  = rowl + 64;

    int bh = blockIdx.y, b = bh >> 3, h = bh & 7;
    int i0 = blockIdx.x * 64;
    int t = threadIdx.x;
    int lane = t & 31, g = lane >> 2, tg = lane & 3;
    int w = t >> 5;

    const float* ACp = g_AC + (size_t)bh * SEG * KL;
    const float* BDp = g_BD + (size_t)bh * SEG * KL;
    const float* Vp  = g_heads + (size_t)b * H3 + 2*DM + h*DHH;

    if (t < 64) { rowm[t] = -INFINITY; rowl[t] = 0.f; }

    // PV warp layout: 4(M) x 2(N), warp tile 16x16
    int wm2 = (w >> 1) * 16, wn2 = (w & 1) * 16;
    float o[2][4];
#pragma unroll
    for (int i = 0; i < 2; i++)
#pragma unroll
        for (int q = 0; q < 4; q++) o[i][q] = 0.f;

    // softmax mapping: row sr = t>>2, quad qd = t&3, cols qd + 4*cc (bank-conflict-free)
    int sr = t >> 2, qd = t & 3;
    int gi = i0 + sr;

    for (int j0 = 0; j0 < KL; j0 += 128) {
        __syncthreads();   // Sm/Vst free (prev PV done)
        // load AC tile 64x128 -> Sm (raw float bits)
#pragma unroll
        for (int i = 0; i < 8; i++) {
            int f = t + i * 256;
            int r = f >> 5, c4 = (f & 31) * 4;
            float4 v = *(const float4*)(ACp + (size_t)(i0 + r) * KL + j0 + c4);
            Sm[r*132 + c4]   = __float_as_uint(v.x);
            Sm[r*132 + c4+1] = __float_as_uint(v.y);
            Sm[r*132 + c4+2] = __float_as_uint(v.z);
            Sm[r*132 + c4+3] = __float_as_uint(v.w);
        }
        // load V tile 128x32 -> Vst transposed
#pragma unroll
        for (int i = 0; i < 4; i++) {
            int f = t + i * 256;
            int r = f >> 3, c4 = (f & 7) * 4;
            float4 vv = *(const float4*)(Vp + (size_t)(j0 + r) * (BSZ*H3) + c4);
            Vst[(c4  )*132 + r] = f2tf(vv.x);
            Vst[(c4+1)*132 + r] = f2tf(vv.y);
            Vst[(c4+2)*132 + r] = f2tf(vv.z);
            Vst[(c4+3)*132 + r] = f2tf(vv.w);
        }
        __syncthreads();

        // softmax: add shifted BD, scale, mask; online max/sum
        float mloc = -INFINITY;
#pragma unroll
        for (int cc = 0; cc < 32; cc++) {
            int col = qd + 4 * cc;
            int j = j0 + col;
            int u = MEML + j - gi;             // 1024 + j - i
            float bd;
            if (u <= KL) bd = BDp[(size_t)gi * KL + (u - 1)];
            else {
                int p = u - (KL + 1);
                bd = p ? BDp[(size_t)(gi + 1) * KL + (p - 1)] : 0.f;
            }
            float s = (__uint_as_float(Sm[sr*132 + col]) + bd) * SCALE;
            if (mask[(size_t)gi * KL + j]) s = -INFINITY;
            Sm[sr*132 + col] = __float_as_uint(s);
            mloc = fmaxf(mloc, s);
        }
        mloc = fmaxf(mloc, __shfl_xor_sync(0xffffffffu, mloc, 1));
        mloc = fmaxf(mloc, __shfl_xor_sync(0xffffffffu, mloc, 2));
        float mold = rowm[sr];
        float mnew = fmaxf(mold, mloc);
        float fac = __expf(mold - mnew);
        float lloc = 0.f;
#pragma unroll
        for (int cc = 0; cc < 32; cc++) {
            int col = qd + 4 * cc;
            float p = __expf(__uint_as_float(Sm[sr*132 + col]) - mnew);
            lloc += p;
            Sm[sr*132 + col] = f2tf(p);
        }
        lloc += __shfl_xor_sync(0xffffffffu, lloc, 1);
        lloc += __shfl_xor_sync(0xffffffffu, lloc, 2);
        if (qd == 0) { rowm[sr] = mnew; rowl[sr] = rowl[sr] * fac + lloc; rsc[sr] = fac; }
        __syncthreads();

        // rescale O accumulators
        float f0 = rsc[wm2 + g], f1 = rsc[wm2 + g + 8];
#pragma unroll
        for (int nt2 = 0; nt2 < 2; nt2++) {
            o[nt2][0] *= f0; o[nt2][1] *= f0;
            o[nt2][2] *= f1; o[nt2][3] *= f1;
        }
        // PV mma: O += P . V (64x32, K=128)
#pragma unroll
        for (int ks = 0; ks < 128; ks += 8) {
            unsigned a0 = Sm[(wm2+g)*132 + ks + tg];
            unsigned a1 = Sm[(wm2+g+8)*132 + ks + tg];
            unsigned a2 = Sm[(wm2+g)*132 + ks + tg + 4];
            unsigned a3 = Sm[(wm2+g+8)*132 + ks + tg + 4];
#pragma unroll
            for (int nt2 = 0; nt2 < 2; nt2++) {
                int col = wn2 + nt2 * 8 + g;
                unsigned b0 = Vst[col*132 + ks + tg];
                unsigned b1 = Vst[col*132 + ks + tg + 4];
                mma_tf32(o[nt2][0], o[nt2][1], o[nt2][2], o[nt2][3], a0, a1, a2, a3, b0, b1);
            }
        }
    }
    // epilogue: divide by l, write g_vec
    float inv0 = 1.f / rowl[wm2 + g], inv1 = 1.f / rowl[wm2 + g + 8];
#pragma unroll
    for (int nt2 = 0; nt2 < 2; nt2++) {
        int row = i0 + wm2 + g;
        int col = h*DHH + wn2 + nt2 * 8 + 2 * tg;
        *(float2*)(g_vec + (size_t)(row * BSZ + b) * DM + col) =
            make_float2(o[nt2][0] * inv0, o[nt2][1] * inv0);
        *(float2*)(g_vec + (size_t)((row + 8) * BSZ + b) * DM + col) =
            make_float2(o[nt2][2] * inv1, o[nt2][3] * inv1);
    }
}

// ---------------- residual add + LayerNorm; optional write to mems output ----------------
__global__ void k_addln(int did, const float* __restrict__ gamma, const float* __restrict__ beta,
                        float* __restrict__ memout) {
    const float* delta = bufsel(did);
    int row = blockIdx.x, d = threadIdx.x;
    size_t off = (size_t)row * DM + d;
    float x = g_core[off] + delta[off];
    __shared__ float red[DM];
    red[d] = x; __syncthreads();
    for (int s = 128; s > 0; s >>= 1) { if (d < s) red[d] += red[d+s]; __syncthreads(); }
    float mu = red[0] * (1.f/DM); __syncthreads();
    float c = x - mu;
    red[d] = c * c; __syncthreads();
    for (int s = 128; s > 0; s >>= 1) { if (d < s) red[d] += red[d+s]; __syncthreads(); }
    float var = red[0] * (1.f/DM);
    float y = c * (1.f / sqrtf(var + 1e-5f)) * gamma[d] + beta[d];
    g_core[off] = y;
    if (memout) memout[off] = y;
}

// ---------------- decoder ----------------
__global__ void k_dec(const float* __restrict__ Wd, const float* __restrict__ bd,
                      float* __restrict__ pred) {
    __shared__ float Wds[DM * NLD];
    int t = threadIdx.x;
    for (int i = t; i < DM * NLD; i += 256) Wds[i] = Wd[i];
    __syncthreads();
    int lane = t & 31, w = t >> 5;
    int row = blockIdx.x * 8 + w;          // row = s*BSZ + b
    int b = row & 1, s = row >> 1;
    const float* crow = g_core + (size_t)row * DM;
    float v[8];
#pragma unroll
    for (int i = 0; i < 8; i++) v[i] = crow[lane + i * 32];
#pragma unroll
    for (int l = 0; l < NLD; l++) {
        float acc = 0.f;
#pragma unroll
        for (int i = 0; i < 8; i++) acc += v[i] * Wds[(lane + i * 32) * NLD + l];
#pragma unroll
        for (int o = 16; o > 0; o >>= 1) acc += __shfl_down_sync(0xffffffffu, acc, o);
        if (lane == 0)
            pred[((size_t)b * NLD + l) * SEG + s] = acc + bd[l];
    }
}

// ---------------- host launcher ----------------
extern "C" void kernel_launch(void* const* d_in, const int* in_sizes, int n_in,
                              void* d_out, int out_size) {
    (void)in_sizes; (void)n_in; (void)out_size;
    const float* src      = (const float*)d_in[0];
    const float* mems     = (const float*)d_in[1];
    const unsigned char* mask = (const unsigned char*)d_in[2];
    const float* W_in     = (const float*)d_in[3];
    const float* b_in     = (const float*)d_in[4];
    const float* qkv_w    = (const float*)d_in[5];
    const float* r_net_w  = (const float*)d_in[6];
    const float* o_w      = (const float*)d_in[7];
    const float* ln1_g    = (const float*)d_in[8];
    const float* ln1_b    = (const float*)d_in[9];
    const float* ff_w1    = (const float*)d_in[10];
    const float* ff_b1    = (const float*)d_in[11];
    const float* ff_w2    = (const float*)d_in[12];
    const float* ff_b2    = (const float*)d_in[13];
    const float* ln2_g    = (const float*)d_in[14];
    const float* ln2_b    = (const float*)d_in[15];
    const float* W_dec    = (const float*)d_in[16];
    const float* b_dec    = (const float*)d_in[17];
    const float* r_w_bias = (const float*)d_in[18];
    const float* r_r_bias = (const float*)d_in[19];

    float* out    = (float*)d_out;
    float* pred   = out;
    float* memout = out + PRED_N;

    cudaFuncSetAttribute(k_spv, cudaFuncAttributeMaxDynamicSharedMemorySize, SP_SMEM);

    k_input_proj<<<(SEG*BSZ*DM + 255)/256, 256>>>(src, W_in, b_in, memout);
    k_pos<<<(KL*DM + 255)/256, 256>>>();

    for (int i = 0; i < LNUM; i++) {
        // heads = [mems_i ; core] @ qkv_w[i]   [4096 x 768 x 256], cat fused
        k_gemm_tf32<128><<<dim3(H3/64, (KL*BSZ)/128), 256>>>(mems + (size_t)i * MEML*BSZ*DM, 100,
                                                             qkv_w + (size_t)i*DM*H3, 5,
                                                             KL*BSZ, H3, DM, nullptr, 0);
        // rk = r @ r_net_w[i]      [2048 x 256 x 256]
        k_gemm_tf32<64><<<dim3(DM/64, KL/64), 256>>>(nullptr, 1, r_net_w + (size_t)i*DM*DM, 6,
                                                     KL, DM, DM, nullptr, 0);
        // AC and BDpre
        k_qk_tf32<<<dim3(KL/64, SEG/128, BSZ*NH), 256>>>(0, r_w_bias);
        k_qk_tf32<<<dim3(KL/64, SEG/128, BSZ*NH), 256>>>(1, r_r_bias);
        // fused shift+softmax+PV
        k_spv<<<dim3(SEG/64, BSZ*NH), 256, SP_SMEM>>>(mask, nullptr);
        // attn output projection     [2048 x 256 x 256]
        k_gemm_tf32<64><<<dim3(DM/64, (SEG*BSZ)/64), 256>>>(nullptr, 2, o_w + (size_t)i*DM*DM, 4,
                                                            SEG*BSZ, DM, DM, nullptr, 0);
        k_addln<<<SEG*BSZ, DM>>>(4, ln1_g + i*DM, ln1_b + i*DM, nullptr);
        // ff1 + bias + relu          [2048 x 1024 x 256]
        k_gemm_tf32<128><<<dim3(DI/64, (SEG*BSZ)/128), 256>>>(nullptr, 3, ff_w1 + (size_t)i*DM*DI, 4,
                                                              SEG*BSZ, DI, DM, ff_b1 + i*DI, 1);
        // ff2 + bias                 [2048 x 256 x 1024]
        k_gemm_tf32<64><<<dim3(DM/64, (SEG*BSZ)/64), 256>>>(nullptr, 4, ff_w2 + (size_t)i*DI*DM, 2,
                                                            SEG*BSZ, DM, DI, ff_b2 + i*DM, 0);
        k_addln<<<SEG*BSZ, DM>>>(2, ln2_g + i*DM, ln2_b + i*DM,
                                 memout + (size_t)(i+1)*SEG*BSZ*DM);
    }
    k_dec<<<(SEG*BSZ)/8, 256>>>(W_dec, b_dec, pred);
}

// round 6
// speedup vs baseline: 1.4611x; 1.3888x over previous
#include <cuda_runtime.h>
#include <math.h>

#define LNUM 4
#define DM   256
#define NH   8
#define DHH  32
#define DI   1024
#define SEG  1024
#define MEML 1024
#define KL   2048
#define BSZ  2
#define NLD  12
#define H3   768          // 3*H*DH
#define PRED_N (BSZ*NLD*SEG)
#define CORE_N (SEG*BSZ*DM)
#define SCALE 0.17677669529663687f   // 1/sqrt(32)

// ---------------- scratch (static device globals; no runtime allocation) ----------------
__device__ float g_core [CORE_N];
__device__ float g_heads[KL*BSZ*H3];
__device__ float g_r    [KL*DM];
__device__ float g_rk   [LNUM*KL*DM];              // all layers, batched upfront
__device__ float g_vec  [CORE_N];
__device__ float g_mid  [SEG*BSZ*DI];
__device__ float g_AC   [(size_t)BSZ*NH*SEG*KL];   // AC scores / probs (in-place)
__device__ float g_BD   [(size_t)BSZ*NH*SEG*KL];   // pre-shift BD (BDpre)
__device__ float g_pvp  [4*CORE_N];                // PV split-K partials

__device__ __forceinline__ float* bufsel(int id) {
    switch (id) {
        case 1: return g_r;
        case 2: return g_vec;
        case 3: return g_core;
        case 4: return g_mid;
        case 5: return g_heads;
        case 6: return g_rk;
    }
    return g_core;
}

// ---------------- tf32 helpers ----------------
__device__ __forceinline__ unsigned f2tf(float x) {
    unsigned u;
    asm("cvt.rna.tf32.f32 %0, %1;" : "=r"(u) : "f"(x));
    return u;
}
__device__ __forceinline__ void mma_tf32(float& c0, float& c1, float& c2, float& c3,
                                         unsigned a0, unsigned a1, unsigned a2, unsigned a3,
                                         unsigned b0, unsigned b1) {
    asm volatile(
        "mma.sync.aligned.m16n8k8.row.col.f32.tf32.tf32.f32 "
        "{%0,%1,%2,%3},{%4,%5,%6,%7},{%8,%9},{%0,%1,%2,%3};\n"
        : "+f"(c0), "+f"(c1), "+f"(c2), "+f"(c3)
        : "r"(a0), "r"(a1), "r"(a2), "r"(a3), "r"(b0), "r"(b1));
}

// ---------------- input projection: core = src^T @ W_in + b_in ; also mems_out[0] ----------------
__global__ void k_input_proj(const float* __restrict__ src, const float* __restrict__ W_in,
                             const float* __restrict__ b_in, float* __restrict__ memout) {
    int idx = blockIdx.x * blockDim.x + threadIdx.x;
    if (idx >= CORE_N) return;
    int d  = idx & (DM - 1);
    int sb = idx >> 8;
    int b  = sb & 1;
    int s  = sb >> 1;
    float acc = b_in[d];
#pragma unroll
    for (int l = 0; l < NLD; l++)
        acc += src[((size_t)b * NLD + l) * SEG + s] * W_in[l * DM + d];
    g_core[idx] = acc;
    memout[idx] = acc;   // new_mems[0] == hids[0]
}

// ---------------- positional embedding r[KLEN, D] ----------------
__global__ void k_pos() {
    int idx = blockIdx.x * blockDim.x + threadIdx.x;
    if (idx >= KL * DM) return;
    int d = idx & (DM - 1);
    int j = idx >> 8;
    float pos = (float)(KL - 1 - j);
    int f = (d < 128) ? d : d - 128;
    float inv = powf(10000.f, -(float)f / 128.f);
    float v = pos * inv;
    g_r[idx] = (d < 128) ? sinf(v) : cosf(v);
}

// ---------------- tf32 GEMM: C[M,N] = A[M,K] @ B[K,N] (+bias)(+relu) ----------------
// BM in {128,64}, BN=64, BK=16, 256 threads (8 warps: 4(M) x 2(N)).
// aid==100: virtual cat A (rows < MEML*BSZ from mems_i, else g_core).
// blockIdx.z batches B/C by bstride/cstride (for the rk all-layers GEMM).
template<int BM>
__global__ void k_gemm_tf32(const float* __restrict__ mems_i, int aid,
                            const float* __restrict__ Bw, int cid,
                            int M, int N, int K,
                            const float* __restrict__ bias, int relu,
                            size_t bstride, size_t cstride) {
    constexpr int MT = BM / 64;
    const float* A = bufsel(aid);
    float* C = bufsel(cid) + (size_t)blockIdx.z * cstride;
    Bw += (size_t)blockIdx.z * bstride;
    __shared__ unsigned As[BM][20];
    __shared__ unsigned Bs[16][72];
    int t = threadIdx.x;
    int m0 = blockIdx.y * BM, n0 = blockIdx.x * 64;
    int lane = t & 31, g = lane >> 2, tg = lane & 3;
    int w = t >> 5;
    int wm = (w >> 1) * 16 * MT, wn = (w & 1) * 32;
    float c[MT][4][4];
#pragma unroll
    for (int i = 0; i < MT; i++)
#pragma unroll
        for (int j = 0; j < 4; j++)
#pragma unroll
            for (int q = 0; q < 4; q++) c[i][j][q] = 0.f;

    for (int k0 = 0; k0 < K; k0 += 16) {
#pragma unroll
        for (int i = 0; i < MT; i++) {
            int f = t + i * 256;
            int r = f >> 2, c4 = (f & 3) * 4;
            int rg = m0 + r;
            const float* Arow;
            if (aid == 100)
                Arow = (rg < MEML*BSZ) ? (mems_i + (size_t)rg * K)
                                       : (g_core + (size_t)(rg - MEML*BSZ) * K);
            else
                Arow = A + (size_t)rg * K;
            float4 v = *(const float4*)(Arow + k0 + c4);
            As[r][c4]   = f2tf(v.x); As[r][c4+1] = f2tf(v.y);
            As[r][c4+2] = f2tf(v.z); As[r][c4+3] = f2tf(v.w);
        }
        {
            int br = t >> 4, bc4 = (t & 15) * 4;
            float4 v = *(const float4*)(Bw + (size_t)(k0 + br) * N + n0 + bc4);
            Bs[br][bc4]   = f2tf(v.x); Bs[br][bc4+1] = f2tf(v.y);
            Bs[br][bc4+2] = f2tf(v.z); Bs[br][bc4+3] = f2tf(v.w);
        }
        __syncthreads();
#pragma unroll
        for (int ks = 0; ks < 16; ks += 8) {
            unsigned a[MT][4], bfrag[4][2];
#pragma unroll
            for (int mt = 0; mt < MT; mt++) {
                int r = wm + mt * 16 + g;
                a[mt][0] = As[r][ks + tg];
                a[mt][1] = As[r + 8][ks + tg];
                a[mt][2] = As[r][ks + tg + 4];
                a[mt][3] = As[r + 8][ks + tg + 4];
            }
#pragma unroll
            for (int nt = 0; nt < 4; nt++) {
                int col = wn + nt * 8 + g;
                bfrag[nt][0] = Bs[ks + tg][col];
                bfrag[nt][1] = Bs[ks + tg + 4][col];
            }
#pragma unroll
            for (int mt = 0; mt < MT; mt++)
#pragma unroll
                for (int nt = 0; nt < 4; nt++)
                    mma_tf32(c[mt][nt][0], c[mt][nt][1], c[mt][nt][2], c[mt][nt][3],
                             a[mt][0], a[mt][1], a[mt][2], a[mt][3],
                             bfrag[nt][0], bfrag[nt][1]);
        }
        __syncthreads();
    }
#pragma unroll
    for (int mt = 0; mt < MT; mt++) {
#pragma unroll
        for (int nt = 0; nt < 4; nt++) {
            int row = m0 + wm + mt * 16 + g;
            int col = n0 + wn + nt * 8 + 2 * tg;
            float b0 = 0.f, b1 = 0.f;
            if (bias) { b0 = bias[col]; b1 = bias[col + 1]; }
            float v0 = c[mt][nt][0] + b0, v1 = c[mt][nt][1] + b1;
            float v2 = c[mt][nt][2] + b0, v3 = c[mt][nt][3] + b1;
            if (relu) {
                v0 = fmaxf(v0, 0.f); v1 = fmaxf(v1, 0.f);
                v2 = fmaxf(v2, 0.f); v3 = fmaxf(v3, 0.f);
            }
            *(float2*)(C + (size_t)row * N + col)       = make_float2(v0, v1);
            *(float2*)(C + (size_t)(row + 8) * N + col) = make_float2(v2, v3);
        }
    }
}

// ---------------- tf32 QK^T: z = bh*2 + mode; mode 0 -> AC, mode 1 -> BDpre ----------------
// per (b,h): C[i,j] = sum_d (Q[i,d]+qbias[d]) * Kmat[j,d] ; K=DH=32 single smem shot.
__global__ void k_qk_tf32(const float* __restrict__ rwb, const float* __restrict__ rrb,
                          const float* __restrict__ rk_l) {
    int z = blockIdx.z;
    int mode = z & 1, bh = z >> 1, b = bh >> 3, h = bh & 7;
    int i0 = blockIdx.y * 128, j0 = blockIdx.x * 64;
    const float* Qp = g_heads + (size_t)(MEML*BSZ + b) * H3 + h*DHH;
    const float* Kp; int kstr;
    float* Cp;
    const float* qb;
    if (mode == 0) { Kp = g_heads + (size_t)b*H3 + DM + h*DHH; kstr = BSZ*H3; Cp = g_AC; qb = rwb + h*DHH; }
    else           { Kp = rk_l + h*DHH;                        kstr = DM;     Cp = g_BD; qb = rrb + h*DHH; }
    Cp += (size_t)bh * SEG * KL;

    __shared__ unsigned Qs[128][36];
    __shared__ unsigned Ks[64][36];
    int t = threadIdx.x;
    int lane = t & 31, g = lane >> 2, tg = lane & 3;
    int w = t >> 5;
    int wm = (w >> 1) * 32, wn = (w & 1) * 32;

#pragma unroll
    for (int i = 0; i < 4; i++) {
        int f = t + i * 256;
        int r = f >> 3, c4 = (f & 7) * 4;
        float4 v = *(const float4*)(Qp + (size_t)(i0 + r) * (BSZ*H3) + c4);
        Qs[r][c4]   = f2tf(v.x + qb[c4]);   Qs[r][c4+1] = f2tf(v.y + qb[c4+1]);
        Qs[r][c4+2] = f2tf(v.z + qb[c4+2]); Qs[r][c4+3] = f2tf(v.w + qb[c4+3]);
    }
#pragma unroll
    for (int i = 0; i < 2; i++) {
        int f = t + i * 256;
        int r = f >> 3, c4 = (f & 7) * 4;
        float4 v = *(const float4*)(Kp + (size_t)(j0 + r) * kstr + c4);
        Ks[r][c4]   = f2tf(v.x); Ks[r][c4+1] = f2tf(v.y);
        Ks[r][c4+2] = f2tf(v.z); Ks[r][c4+3] = f2tf(v.w);
    }
    __syncthreads();

    float c[2][4][4];
#pragma unroll
    for (int i = 0; i < 2; i++)
#pragma unroll
        for (int j = 0; j < 4; j++)
#pragma unroll
            for (int q = 0; q < 4; q++) c[i][j][q] = 0.f;

#pragma unroll
    for (int ks = 0; ks < 32; ks += 8) {
        unsigned a[2][4], bfrag[4][2];
#pragma unroll
        for (int mt = 0; mt < 2; mt++) {
            int r = wm + mt * 16 + g;
            a[mt][0] = Qs[r][ks + tg];
            a[mt][1] = Qs[r + 8][ks + tg];
            a[mt][2] = Qs[r][ks + tg + 4];
            a[mt][3] = Qs[r + 8][ks + tg + 4];
        }
#pragma unroll
        for (int nt = 0; nt < 4; nt++) {
            int col = wn + nt * 8 + g;
            bfrag[nt][0] = Ks[col][ks + tg];
            bfrag[nt][1] = Ks[col][ks + tg + 4];
        }
#pragma unroll
        for (int mt = 0; mt < 2; mt++)
#pragma unroll
            for (int nt = 0; nt < 4; nt++)
                mma_tf32(c[mt][nt][0], c[mt][nt][1], c[mt][nt][2], c[mt][nt][3],
                         a[mt][0], a[mt][1], a[mt][2], a[mt][3],
                         bfrag[nt][0], bfrag[nt][1]);
    }
#pragma unroll
    for (int mt = 0; mt < 2; mt++)
#pragma unroll
        for (int nt = 0; nt < 4; nt++) {
            int row = i0 + wm + mt * 16 + g;
            int col = j0 + wn + nt * 8 + 2 * tg;
            *(float2*)(Cp + (size_t)row * KL + col)       = make_float2(c[mt][nt][0], c[mt][nt][1]);
            *(float2*)(Cp + (size_t)(row + 8) * KL + col) = make_float2(c[mt][nt][2], c[mt][nt][3]);
        }
}

// ---------------- fused rel_shift + combine + mask + softmax; prob in-place over AC ----------------
__global__ void k_softmax(const unsigned char* __restrict__ mask) {
    int i = blockIdx.x, bh = blockIdx.y;
    int t = threadIdx.x;
    size_t rowoff = ((size_t)bh * SEG + i) * KL;
    float* ac = g_AC + rowoff;
    float vals[8];
    float mx = -INFINITY;
#pragma unroll
    for (int r2 = 0; r2 < 8; r2++) {
        int j = t + r2 * 256;
        int f = SEG + i * KL + j;              // rel_shift flat index
        int a = f / (KL + 1);
        int p = f - a * (KL + 1);
        float bd = (p == 0) ? 0.f : g_BD[((size_t)bh * SEG + a) * KL + (p - 1)];
        float s = (ac[j] + bd) * SCALE;
        if (mask[(size_t)i * KL + j]) s = -INFINITY;
        vals[r2] = s;
        mx = fmaxf(mx, s);
    }
    __shared__ float red[256];
    red[t] = mx; __syncthreads();
    for (int s2 = 128; s2 > 0; s2 >>= 1) { if (t < s2) red[t] = fmaxf(red[t], red[t+s2]); __syncthreads(); }
    float rowmax = red[0]; __syncthreads();
    float sum = 0.f;
#pragma unroll
    for (int r2 = 0; r2 < 8; r2++) { vals[r2] = __expf(vals[r2] - rowmax); sum += vals[r2]; }
    red[t] = sum; __syncthreads();
    for (int s2 = 128; s2 > 0; s2 >>= 1) { if (t < s2) red[t] += red[t+s2]; __syncthreads(); }
    float inv = 1.f / red[0];
#pragma unroll
    for (int r2 = 0; r2 < 8; r2++) ac[t + r2*256] = vals[r2] * inv;
}

// ---------------- tf32 PV split-K: partial over j-range, write g_pvp[js] ----------------
// BM=64, BN=32, BK=32, 128 threads (4 warps, each 16 rows). grid (SEG/64, BSZ*NH, 4).
__global__ void k_pv_tf32() {
    int bh = blockIdx.y, b = bh >> 3, h = bh & 7;
    int i0 = blockIdx.x * 64;
    int js = blockIdx.z;
    const float* P = g_AC + (size_t)bh * SEG * KL;
    const float* V = g_heads + (size_t)b * H3 + 2*DM + h*DHH;
    const int sV = BSZ*H3;
    float* Out = g_pvp + (size_t)js * CORE_N;

    __shared__ unsigned Ps[64][36];
    __shared__ unsigned Vst[32][36];   // transposed: Vst[d][j_rel]
    int t = threadIdx.x;
    int lane = t & 31, g = lane >> 2, tg = lane & 3;
    int w = t >> 5;
    int wm = w * 16;

    float c[4][4];
#pragma unroll
    for (int j = 0; j < 4; j++)
#pragma unroll
        for (int q = 0; q < 4; q++) c[j][q] = 0.f;

    int jb = js * (KL/4), je = jb + (KL/4);
    for (int j0 = jb; j0 < je; j0 += 32) {
#pragma unroll
        for (int i = 0; i < 4; i++) {
            int f = t + i * 128;
            int r = f >> 3, c4 = (f & 7) * 4;
            float4 v = *(const float4*)(P + (size_t)(i0 + r) * KL + j0 + c4);
            Ps[r][c4]   = f2tf(v.x); Ps[r][c4+1] = f2tf(v.y);
            Ps[r][c4+2] = f2tf(v.z); Ps[r][c4+3] = f2tf(v.w);
        }
#pragma unroll
        for (int i = 0; i < 2; i++) {
            int f = t + i * 128;
            int jr = f >> 3, c4 = (f & 7) * 4;
            float4 v = *(const float4*)(V + (size_t)(j0 + jr) * sV + c4);
            Vst[c4][jr]   = f2tf(v.x); Vst[c4+1][jr] = f2tf(v.y);
            Vst[c4+2][jr] = f2tf(v.z); Vst[c4+3][jr] = f2tf(v.w);
        }
        __syncthreads();
#pragma unroll
        for (int ks = 0; ks < 32; ks += 8) {
            unsigned a0 = Ps[wm + g][ks + tg];
            unsigned a1 = Ps[wm + g + 8][ks + tg];
            unsigned a2 = Ps[wm + g][ks + tg + 4];
            unsigned a3 = Ps[wm + g + 8][ks + tg + 4];
#pragma unroll
            for (int nt = 0; nt < 4; nt++) {
                unsigned b0 = Vst[nt * 8 + g][ks + tg];
                unsigned b1 = Vst[nt * 8 + g][ks + tg + 4];
                mma_tf32(c[nt][0], c[nt][1], c[nt][2], c[nt][3], a0, a1, a2, a3, b0, b1);
            }
        }
        __syncthreads();
    }
#pragma unroll
    for (int nt = 0; nt < 4; nt++) {
        int row = i0 + wm + g;
        int col = h*DHH + nt * 8 + 2 * tg;
        *(float2*)(Out + (size_t)(row * BSZ + b) * DM + col)       = make_float2(c[nt][0], c[nt][1]);
        *(float2*)(Out + (size_t)((row + 8) * BSZ + b) * DM + col) = make_float2(c[nt][2], c[nt][3]);
    }
}

// ---------------- PV split-K reduction: g_vec = sum of 4 partials ----------------
__global__ void k_pvred() {
    int idx = blockIdx.x * blockDim.x + threadIdx.x;
    if (idx >= CORE_N) return;
    g_vec[idx] = g_pvp[idx] + g_pvp[CORE_N + idx] + g_pvp[2*CORE_N + idx] + g_pvp[3*CORE_N + idx];
}

// ---------------- residual add + LayerNorm; optional write to mems output ----------------
__global__ void k_addln(int did, const float* __restrict__ gamma, const float* __restrict__ beta,
                        float* __restrict__ memout) {
    const float* delta = bufsel(did);
    int row = blockIdx.x, d = threadIdx.x;
    size_t off = (size_t)row * DM + d;
    float x = g_core[off] + delta[off];
    __shared__ float red[DM];
    red[d] = x; __syncthreads();
    for (int s = 128; s > 0; s >>= 1) { if (d < s) red[d] += red[d+s]; __syncthreads(); }
    float mu = red[0] * (1.f/DM); __syncthreads();
    float c = x - mu;
    red[d] = c * c; __syncthreads();
    for (int s = 128; s > 0; s >>= 1) { if (d < s) red[d] += red[d+s]; __syncthreads(); }
    float var = red[0] * (1.f/DM);
    float y = c * (1.f / sqrtf(var + 1e-5f)) * gamma[d] + beta[d];
    g_core[off] = y;
    if (memout) memout[off] = y;
}

// ---------------- decoder ----------------
__global__ void k_dec(const float* __restrict__ Wd, const float* __restrict__ bd,
                      float* __restrict__ pred) {
    __shared__ float Wds[DM * NLD];
    int t = threadIdx.x;
    for (int i = t; i < DM * NLD; i += 256) Wds[i] = Wd[i];
    __syncthreads();
    int lane = t & 31, w = t >> 5;
    int row = blockIdx.x * 8 + w;          // row = s*BSZ + b
    int b = row & 1, s = row >> 1;
    const float* crow = g_core + (size_t)row * DM;
    float v[8];
#pragma unroll
    for (int i = 0; i < 8; i++) v[i] = crow[lane + i * 32];
#pragma unroll
    for (int l = 0; l < NLD; l++) {
        float acc = 0.f;
#pragma unroll
        for (int i = 0; i < 8; i++) acc += v[i] * Wds[(lane + i * 32) * NLD + l];
#pragma unroll
        for (int o = 16; o > 0; o >>= 1) acc += __shfl_down_sync(0xffffffffu, acc, o);
        if (lane == 0)
            pred[((size_t)b * NLD + l) * SEG + s] = acc + bd[l];
    }
}

// ---------------- host launcher ----------------
extern "C" void kernel_launch(void* const* d_in, const int* in_sizes, int n_in,
                              void* d_out, int out_size) {
    (void)in_sizes; (void)n_in; (void)out_size;
    const float* src      = (const float*)d_in[0];
    const float* mems     = (const float*)d_in[1];
    const unsigned char* mask = (const unsigned char*)d_in[2];
    const float* W_in     = (const float*)d_in[3];
    const float* b_in     = (const float*)d_in[4];
    const float* qkv_w    = (const float*)d_in[5];
    const float* r_net_w  = (const float*)d_in[6];
    const float* o_w      = (const float*)d_in[7];
    const float* ln1_g    = (const float*)d_in[8];
    const float* ln1_b    = (const float*)d_in[9];
    const float* ff_w1    = (const float*)d_in[10];
    const float* ff_b1    = (const float*)d_in[11];
    const float* ff_w2    = (const float*)d_in[12];
    const float* ff_b2    = (const float*)d_in[13];
    const float* ln2_g    = (const float*)d_in[14];
    const float* ln2_b    = (const float*)d_in[15];
    const float* W_dec    = (const float*)d_in[16];
    const float* b_dec    = (const float*)d_in[17];
    const float* r_w_bias = (const float*)d_in[18];
    const float* r_r_bias = (const float*)d_in[19];

    float* out    = (float*)d_out;
    float* pred   = out;
    float* memout = out + PRED_N;

    k_input_proj<<<(CORE_N + 255)/256, 256>>>(src, W_in, b_in, memout);
    k_pos<<<(KL*DM + 255)/256, 256>>>();

    // rk for ALL layers in one z-batched GEMM: g_rk[l] = r @ r_net_w[l]
    k_gemm_tf32<64><<<dim3(DM/64, KL/64, LNUM), 256>>>(nullptr, 1, r_net_w, 6,
                                                       KL, DM, DM, nullptr, 0,
                                                       (size_t)DM*DM, (size_t)KL*DM);

    // rk device pointer (for k_qk): resolve g_rk symbol address once per launch call.
    // kernel_launch may be called during graph capture; cudaGetSymbolAddress is allowed
    // (no alloc, host-side query).
    static float* rk_dev = nullptr;
    if (!rk_dev) cudaGetSymbolAddress((void**)&rk_dev, g_rk);

    for (int i = 0; i < LNUM; i++) {
        // heads = [mems_i ; core] @ qkv_w[i]   [4096 x 768 x 256], cat fused
        k_gemm_tf32<128><<<dim3(H3/64, (KL*BSZ)/128, 1), 256>>>(mems + (size_t)i * MEML*BSZ*DM, 100,
                                                                qkv_w + (size_t)i*DM*H3, 5,
                                                                KL*BSZ, H3, DM, nullptr, 0, 0, 0);
        // AC and BDpre in one launch (z = bh*2+mode)
        k_qk_tf32<<<dim3(KL/64, SEG/128, BSZ*NH*2), 256>>>(r_w_bias, r_r_bias,
                                                           rk_dev + (size_t)i*KL*DM);
        // shift + combine + mask + softmax (prob in place)
        k_softmax<<<dim3(SEG, BSZ*NH), 256>>>(mask);
        // PV split-K + reduce
        k_pv_tf32<<<dim3(SEG/64, BSZ*NH, 4), 128>>>();
        k_pvred<<<(CORE_N + 255)/256, 256>>>();
        // attn output projection     [2048 x 256 x 256]
        k_gemm_tf32<64><<<dim3(DM/64, (SEG*BSZ)/64, 1), 256>>>(nullptr, 2, o_w + (size_t)i*DM*DM, 4,
                                                               SEG*BSZ, DM, DM, nullptr, 0, 0, 0);
        k_addln<<<SEG*BSZ, DM>>>(4, ln1_g + i*DM, ln1_b + i*DM, nullptr);
        // ff1 + bias + relu          [2048 x 1024 x 256]
        k_gemm_tf32<128><<<dim3(DI/64, (SEG*BSZ)/128, 1), 256>>>(nullptr, 3, ff_w1 + (size_t)i*DM*DI, 4,
                                                                 SEG*BSZ, DI, DM, ff_b1 + i*DI, 1, 0, 0);
        // ff2 + bias                 [2048 x 256 x 1024]
        k_gemm_tf32<64><<<dim3(DM/64, (SEG*BSZ)/64, 1), 256>>>(nullptr, 4, ff_w2 + (size_t)i*DI*DM, 2,
                                                               SEG*BSZ, DM, DI, ff_b2 + i*DM, 0, 0, 0);
        k_addln<<<SEG*BSZ, DM>>>(2, ln2_g + i*DM, ln2_b + i*DM,
                                 memout + (size_t)(i+1)*CORE_N);
    }
    k_dec<<<(SEG*BSZ)/8, 256>>>(W_dec, b_dec, pred);
}

// round 7
// speedup vs baseline: 1.5428x; 1.0559x over previous
#include <cuda_runtime.h>
#include <cuda_fp16.h>
#include <math.h>

#define LNUM 4
#define DM   256
#define NH   8
#define DHH  32
#define DI   1024
#define SEG  1024
#define MEML 1024
#define KL   2048
#define BSZ  2
#define NLD  12
#define H3   768          // 3*H*DH
#define PRED_N (BSZ*NLD*SEG)
#define CORE_N (SEG*BSZ*DM)
#define SCALE 0.17677669529663687f   // 1/sqrt(32)

// ---------------- scratch (static device globals; no runtime allocation) ----------------
__device__ float  g_core [CORE_N];
__device__ float  g_heads[KL*BSZ*H3];
__device__ float  g_r    [KL*DM];
__device__ float  g_rk   [LNUM*KL*DM];              // all layers, batched upfront
__device__ float  g_vec  [CORE_N];
__device__ float  g_mid  [SEG*BSZ*DI];
__device__ __half g_AC   [(size_t)BSZ*NH*SEG*KL];   // AC scores / probs (in-place, fp16)
__device__ __half g_BD   [(size_t)BSZ*NH*SEG*KL];   // pre-shift BD (fp16)
__device__ float  g_pvp  [4*CORE_N];                // PV split-K partials

__device__ __forceinline__ float* bufsel(int id) {
    switch (id) {
        case 1: return g_r;
        case 2: return g_vec;
        case 3: return g_core;
        case 4: return g_mid;
        case 5: return g_heads;
        case 6: return g_rk;
    }
    return g_core;
}

// ---------------- tf32 helpers ----------------
__device__ __forceinline__ unsigned f2tf(float x) {
    unsigned u;
    asm("cvt.rna.tf32.f32 %0, %1;" : "=r"(u) : "f"(x));
    return u;
}
__device__ __forceinline__ void mma_tf32(float& c0, float& c1, float& c2, float& c3,
                                         unsigned a0, unsigned a1, unsigned a2, unsigned a3,
                                         unsigned b0, unsigned b1) {
    asm volatile(
        "mma.sync.aligned.m16n8k8.row.col.f32.tf32.tf32.f32 "
        "{%0,%1,%2,%3},{%4,%5,%6,%7},{%8,%9},{%0,%1,%2,%3};\n"
        : "+f"(c0), "+f"(c1), "+f"(c2), "+f"(c3)
        : "r"(a0), "r"(a1), "r"(a2), "r"(a3), "r"(b0), "r"(b1));
}

// ---------------- input projection: core = src^T @ W_in + b_in ; also mems_out[0] ----------------
__global__ void k_input_proj(const float* __restrict__ src, const float* __restrict__ W_in,
                             const float* __restrict__ b_in, float* __restrict__ memout) {
    int idx = blockIdx.x * blockDim.x + threadIdx.x;
    if (idx >= CORE_N) return;
    int d  = idx & (DM - 1);
    int sb = idx >> 8;
    int b  = sb & 1;
    int s  = sb >> 1;
    float acc = b_in[d];
#pragma unroll
    for (int l = 0; l < NLD; l++)
        acc += src[((size_t)b * NLD + l) * SEG + s] * W_in[l * DM + d];
    g_core[idx] = acc;
    memout[idx] = acc;   // new_mems[0] == hids[0]
}

// ---------------- positional embedding r[KLEN, D] ----------------
__global__ void k_pos() {
    int idx = blockIdx.x * blockDim.x + threadIdx.x;
    if (idx >= KL * DM) return;
    int d = idx & (DM - 1);
    int j = idx >> 8;
    float pos = (float)(KL - 1 - j);
    int f = (d < 128) ? d : d - 128;
    float inv = powf(10000.f, -(float)f / 128.f);
    float v = pos * inv;
    g_r[idx] = (d < 128) ? sinf(v) : cosf(v);
}

// ---------------- tf32 GEMM: C[M,N] = A[M,K] @ B[K,N] (+bias)(+relu) ----------------
// BM in {128,64}, BN=64, BK=16, 256 threads (8 warps: 4(M) x 2(N)).
// aid==100: virtual cat A (rows < MEML*BSZ from mems_i, else g_core).
// aid==101: A = sum of the 4 PV split-K partials (g_pvp), layout [row][DM].
// blockIdx.z batches B/C by bstride/cstride (for the rk all-layers GEMM).
template<int BM>
__global__ void k_gemm_tf32(const float* __restrict__ mems_i, int aid,
                            const float* __restrict__ Bw, int cid,
                            int M, int N, int K,
                            const float* __restrict__ bias, int relu,
                            size_t bstride, size_t cstride) {
    constexpr int MT = BM / 64;
    const float* A = bufsel(aid);
    float* C = bufsel(cid) + (size_t)blockIdx.z * cstride;
    Bw += (size_t)blockIdx.z * bstride;
    __shared__ unsigned As[BM][20];
    __shared__ unsigned Bs[16][72];
    int t = threadIdx.x;
    int m0 = blockIdx.y * BM, n0 = blockIdx.x * 64;
    int lane = t & 31, g = lane >> 2, tg = lane & 3;
    int w = t >> 5;
    int wm = (w >> 1) * 16 * MT, wn = (w & 1) * 32;
    float c[MT][4][4];
#pragma unroll
    for (int i = 0; i < MT; i++)
#pragma unroll
        for (int j = 0; j < 4; j++)
#pragma unroll
            for (int q = 0; q < 4; q++) c[i][j][q] = 0.f;

    for (int k0 = 0; k0 < K; k0 += 16) {
#pragma unroll
        for (int i = 0; i < MT; i++) {
            int f = t + i * 256;
            int r = f >> 2, c4 = (f & 3) * 4;
            int rg = m0 + r;
            float4 v;
            if (aid == 101) {
                size_t off = (size_t)rg * K + k0 + c4;
                float4 v0 = *(const float4*)(g_pvp + off);
                float4 v1 = *(const float4*)(g_pvp + CORE_N + off);
                float4 v2 = *(const float4*)(g_pvp + 2*(size_t)CORE_N + off);
                float4 v3 = *(const float4*)(g_pvp + 3*(size_t)CORE_N + off);
                v.x = v0.x + v1.x + v2.x + v3.x;
                v.y = v0.y + v1.y + v2.y + v3.y;
                v.z = v0.z + v1.z + v2.z + v3.z;
                v.w = v0.w + v1.w + v2.w + v3.w;
            } else if (aid == 100) {
                const float* Arow = (rg < MEML*BSZ) ? (mems_i + (size_t)rg * K)
                                                    : (g_core + (size_t)(rg - MEML*BSZ) * K);
                v = *(const float4*)(Arow + k0 + c4);
            } else {
                v = *(const float4*)(A + (size_t)rg * K + k0 + c4);
            }
            As[r][c4]   = f2tf(v.x); As[r][c4+1] = f2tf(v.y);
            As[r][c4+2] = f2tf(v.z); As[r][c4+3] = f2tf(v.w);
        }
        {
            int br = t >> 4, bc4 = (t & 15) * 4;
            float4 v = *(const float4*)(Bw + (size_t)(k0 + br) * N + n0 + bc4);
            Bs[br][bc4]   = f2tf(v.x); Bs[br][bc4+1] = f2tf(v.y);
            Bs[br][bc4+2] = f2tf(v.z); Bs[br][bc4+3] = f2tf(v.w);
        }
        __syncthreads();
#pragma unroll
        for (int ks = 0; ks < 16; ks += 8) {
            unsigned a[MT][4], bfrag[4][2];
#pragma unroll
            for (int mt = 0; mt < MT; mt++) {
                int r = wm + mt * 16 + g;
                a[mt][0] = As[r][ks + tg];
                a[mt][1] = As[r + 8][ks + tg];
                a[mt][2] = As[r][ks + tg + 4];
                a[mt][3] = As[r + 8][ks + tg + 4];
            }
#pragma unroll
            for (int nt = 0; nt < 4; nt++) {
                int col = wn + nt * 8 + g;
                bfrag[nt][0] = Bs[ks + tg][col];
                bfrag[nt][1] = Bs[ks + tg + 4][col];
            }
#pragma unroll
            for (int mt = 0; mt < MT; mt++)
#pragma unroll
                for (int nt = 0; nt < 4; nt++)
                    mma_tf32(c[mt][nt][0], c[mt][nt][1], c[mt][nt][2], c[mt][nt][3],
                             a[mt][0], a[mt][1], a[mt][2], a[mt][3],
                             bfrag[nt][0], bfrag[nt][1]);
        }
        __syncthreads();
    }
#pragma unroll
    for (int mt = 0; mt < MT; mt++) {
#pragma unroll
        for (int nt = 0; nt < 4; nt++) {
            int row = m0 + wm + mt * 16 + g;
            int col = n0 + wn + nt * 8 + 2 * tg;
            float b0 = 0.f, b1 = 0.f;
            if (bias) { b0 = bias[col]; b1 = bias[col + 1]; }
            float v0 = c[mt][nt][0] + b0, v1 = c[mt][nt][1] + b1;
            float v2 = c[mt][nt][2] + b0, v3 = c[mt][nt][3] + b1;
            if (relu) {
                v0 = fmaxf(v0, 0.f); v1 = fmaxf(v1, 0.f);
                v2 = fmaxf(v2, 0.f); v3 = fmaxf(v3, 0.f);
            }
            *(float2*)(C + (size_t)row * N + col)       = make_float2(v0, v1);
            *(float2*)(C + (size_t)(row + 8) * N + col) = make_float2(v2, v3);
        }
    }
}

// ---------------- tf32 QK^T: z = bh*2 + mode; mode 0 -> AC, mode 1 -> BDpre (fp16 out) ----------------
__global__ void k_qk_tf32(const float* __restrict__ rwb, const float* __restrict__ rrb,
                          const float* __restrict__ rk_l) {
    int z = blockIdx.z;
    int mode = z & 1, bh = z >> 1, b = bh >> 3, h = bh & 7;
    int i0 = blockIdx.y * 128, j0 = blockIdx.x * 64;
    const float* Qp = g_heads + (size_t)(MEML*BSZ + b) * H3 + h*DHH;
    const float* Kp; int kstr;
    __half* Cp;
    const float* qb;
    if (mode == 0) { Kp = g_heads + (size_t)b*H3 + DM + h*DHH; kstr = BSZ*H3; Cp = g_AC; qb = rwb + h*DHH; }
    else           { Kp = rk_l + h*DHH;                        kstr = DM;     Cp = g_BD; qb = rrb + h*DHH; }
    Cp += (size_t)bh * SEG * KL;

    __shared__ unsigned Qs[128][36];
    __shared__ unsigned Ks[64][36];
    int t = threadIdx.x;
    int lane = t & 31, g = lane >> 2, tg = lane & 3;
    int w = t >> 5;
    int wm = (w >> 1) * 32, wn = (w & 1) * 32;

#pragma unroll
    for (int i = 0; i < 4; i++) {
        int f = t + i * 256;
        int r = f >> 3, c4 = (f & 7) * 4;
        float4 v = *(const float4*)(Qp + (size_t)(i0 + r) * (BSZ*H3) + c4);
        Qs[r][c4]   = f2tf(v.x + qb[c4]);   Qs[r][c4+1] = f2tf(v.y + qb[c4+1]);
        Qs[r][c4+2] = f2tf(v.z + qb[c4+2]); Qs[r][c4+3] = f2tf(v.w + qb[c4+3]);
    }
#pragma unroll
    for (int i = 0; i < 2; i++) {
        int f = t + i * 256;
        int r = f >> 3, c4 = (f & 7) * 4;
        float4 v = *(const float4*)(Kp + (size_t)(j0 + r) * kstr + c4);
        Ks[r][c4]   = f2tf(v.x); Ks[r][c4+1] = f2tf(v.y);
        Ks[r][c4+2] = f2tf(v.z); Ks[r][c4+3] = f2tf(v.w);
    }
    __syncthreads();

    float c[2][4][4];
#pragma unroll
    for (int i = 0; i < 2; i++)
#pragma unroll
        for (int j = 0; j < 4; j++)
#pragma unroll
            for (int q = 0; q < 4; q++) c[i][j][q] = 0.f;

#pragma unroll
    for (int ks = 0; ks < 32; ks += 8) {
        unsigned a[2][4], bfrag[4][2];
#pragma unroll
        for (int mt = 0; mt < 2; mt++) {
            int r = wm + mt * 16 + g;
            a[mt][0] = Qs[r][ks + tg];
            a[mt][1] = Qs[r + 8][ks + tg];
            a[mt][2] = Qs[r][ks + tg + 4];
            a[mt][3] = Qs[r + 8][ks + tg + 4];
        }
#pragma unroll
        for (int nt = 0; nt < 4; nt++) {
            int col = wn + nt * 8 + g;
            bfrag[nt][0] = Ks[col][ks + tg];
            bfrag[nt][1] = Ks[col][ks + tg + 4];
        }
#pragma unroll
        for (int mt = 0; mt < 2; mt++)
#pragma unroll
            for (int nt = 0; nt < 4; nt++)
                mma_tf32(c[mt][nt][0], c[mt][nt][1], c[mt][nt][2], c[mt][nt][3],
                         a[mt][0], a[mt][1], a[mt][2], a[mt][3],
                         bfrag[nt][0], bfrag[nt][1]);
    }
#pragma unroll
    for (int mt = 0; mt < 2; mt++)
#pragma unroll
        for (int nt = 0; nt < 4; nt++) {
            int row = i0 + wm + mt * 16 + g;
            int col = j0 + wn + nt * 8 + 2 * tg;
            *(__half2*)(Cp + (size_t)row * KL + col)       = __floats2half2_rn(c[mt][nt][0], c[mt][nt][1]);
            *(__half2*)(Cp + (size_t)(row + 8) * KL + col) = __floats2half2_rn(c[mt][nt][2], c[mt][nt][3]);
        }
}

// ---------------- fused rel_shift + combine + mask + softmax (fp16 in/out, in-place) ----------------
__global__ void k_softmax(const unsigned char* __restrict__ mask) {
    int i = blockIdx.x, bh = blockIdx.y;
    int t = threadIdx.x;
    __half* ac = g_AC + ((size_t)bh * SEG + i) * KL;
    float vals[8];
    float mx = -INFINITY;
#pragma unroll
    for (int r2 = 0; r2 < 4; r2++) {
        int j0 = 2*t + r2 * 512;
        float2 a2 = __half22float2(*(const __half2*)(ac + j0));
#pragma unroll
        for (int q = 0; q < 2; q++) {
            int j = j0 + q;
            int f = SEG + i * KL + j;              // rel_shift flat index
            int a = f / (KL + 1);
            int p = f - a * (KL + 1);
            float bd = (p == 0) ? 0.f : __half2float(g_BD[((size_t)bh * SEG + a) * KL + (p - 1)]);
            float s = ((q ? a2.y : a2.x) + bd) * SCALE;
            if (mask[(size_t)i * KL + j]) s = -INFINITY;
            vals[r2*2 + q] = s;
            mx = fmaxf(mx, s);
        }
    }
    __shared__ float red[256];
    red[t] = mx; __syncthreads();
    for (int s2 = 128; s2 > 0; s2 >>= 1) { if (t < s2) red[t] = fmaxf(red[t], red[t+s2]); __syncthreads(); }
    float rowmax = red[0]; __syncthreads();
    float sum = 0.f;
#pragma unroll
    for (int r2 = 0; r2 < 8; r2++) { vals[r2] = __expf(vals[r2] - rowmax); sum += vals[r2]; }
    red[t] = sum; __syncthreads();
    for (int s2 = 128; s2 > 0; s2 >>= 1) { if (t < s2) red[t] += red[t+s2]; __syncthreads(); }
    float inv = 1.f / red[0];
#pragma unroll
    for (int r2 = 0; r2 < 4; r2++)
        *(__half2*)(ac + 2*t + r2*512) =
            __floats2half2_rn(vals[r2*2] * inv, vals[r2*2+1] * inv);
}

// ---------------- tf32 PV split-K: P fp16 in; partial over j-range -> g_pvp[js] ----------------
// BM=64, BN=32, BK=32, 128 threads (4 warps, each 16 rows). grid (SEG/64, BSZ*NH, 4).
__global__ void k_pv_tf32() {
    int bh = blockIdx.y, b = bh >> 3, h = bh & 7;
    int i0 = blockIdx.x * 64;
    int js = blockIdx.z;
    const __half* P = g_AC + (size_t)bh * SEG * KL;
    const float* V = g_heads + (size_t)b * H3 + 2*DM + h*DHH;
    const int sV = BSZ*H3;
    float* Out = g_pvp + (size_t)js * CORE_N;

    __shared__ unsigned Ps[64][36];
    __shared__ unsigned Vst[32][36];   // transposed: Vst[d][j_rel]
    int t = threadIdx.x;
    int lane = t & 31, g = lane >> 2, tg = lane & 3;
    int w = t >> 5;
    int wm = w * 16;

    float c[4][4];
#pragma unroll
    for (int j = 0; j < 4; j++)
#pragma unroll
        for (int q = 0; q < 4; q++) c[j][q] = 0.f;

    int jb = js * (KL/4), je = jb + (KL/4);
    for (int j0 = jb; j0 < je; j0 += 32) {
        // P tile 64x32 halves: 256 chunks of 8 halves
#pragma unroll
        for (int i = 0; i < 2; i++) {
            int f = t + i * 128;
            int r = f >> 2, c8 = (f & 3) * 8;
            float4 raw = *(const float4*)(P + (size_t)(i0 + r) * KL + j0 + c8);
            const __half2* hp = (const __half2*)&raw;
#pragma unroll
            for (int q = 0; q < 4; q++) {
                float2 fv = __half22float2(hp[q]);
                Ps[r][c8 + 2*q]     = f2tf(fv.x);
                Ps[r][c8 + 2*q + 1] = f2tf(fv.y);
            }
        }
#pragma unroll
        for (int i = 0; i < 2; i++) {
            int f = t + i * 128;
            int jr = f >> 3, c4 = (f & 7) * 4;
            float4 v = *(const float4*)(V + (size_t)(j0 + jr) * sV + c4);
            Vst[c4][jr]   = f2tf(v.x); Vst[c4+1][jr] = f2tf(v.y);
            Vst[c4+2][jr] = f2tf(v.z); Vst[c4+3][jr] = f2tf(v.w);
        }
        __syncthreads();
#pragma unroll
        for (int ks = 0; ks < 32; ks += 8) {
            unsigned a0 = Ps[wm + g][ks + tg];
            unsigned a1 = Ps[wm + g + 8][ks + tg];
            unsigned a2 = Ps[wm + g][ks + tg + 4];
            unsigned a3 = Ps[wm + g + 8][ks + tg + 4];
#pragma unroll
            for (int nt = 0; nt < 4; nt++) {
                unsigned b0 = Vst[nt * 8 + g][ks + tg];
                unsigned b1 = Vst[nt * 8 + g][ks + tg + 4];
                mma_tf32(c[nt][0], c[nt][1], c[nt][2], c[nt][3], a0, a1, a2, a3, b0, b1);
            }
        }
        __syncthreads();
    }
#pragma unroll
    for (int nt = 0; nt < 4; nt++) {
        int row = i0 + wm + g;
        int col = h*DHH + nt * 8 + 2 * tg;
        *(float2*)(Out + (size_t)(row * BSZ + b) * DM + col)       = make_float2(c[nt][0], c[nt][1]);
        *(float2*)(Out + (size_t)((row + 8) * BSZ + b) * DM + col) = make_float2(c[nt][2], c[nt][3]);
    }
}

// ---------------- residual add + LayerNorm; optional write to mems output ----------------
__global__ void k_addln(int did, const float* __restrict__ gamma, const float* __restrict__ beta,
                        float* __restrict__ memout) {
    const float* delta = bufsel(did);
    int row = blockIdx.x, d = threadIdx.x;
    size_t off = (size_t)row * DM + d;
    float x = g_core[off] + delta[off];
    __shared__ float red[DM];
    red[d] = x; __syncthreads();
    for (int s = 128; s > 0; s >>= 1) { if (d < s) red[d] += red[d+s]; __syncthreads(); }
    float mu = red[0] * (1.f/DM); __syncthreads();
    float c = x - mu;
    red[d] = c * c; __syncthreads();
    for (int s = 128; s > 0; s >>= 1) { if (d < s) red[d] += red[d+s]; __syncthreads(); }
    float var = red[0] * (1.f/DM);
    float y = c * (1.f / sqrtf(var + 1e-5f)) * gamma[d] + beta[d];
    g_core[off] = y;
    if (memout) memout[off] = y;
}

// ---------------- decoder ----------------
__global__ void k_dec(const float* __restrict__ Wd, const float* __restrict__ bd,
                      float* __restrict__ pred) {
    __shared__ float Wds[DM * NLD];
    int t = threadIdx.x;
    for (int i = t; i < DM * NLD; i += 256) Wds[i] = Wd[i];
    __syncthreads();
    int lane = t & 31, w = t >> 5;
    int row = blockIdx.x * 8 + w;          // row = s*BSZ + b
    int b = row & 1, s = row >> 1;
    const float* crow = g_core + (size_t)row * DM;
    float v[8];
#pragma unroll
    for (int i = 0; i < 8; i++) v[i] = crow[lane + i * 32];
#pragma unroll
    for (int l = 0; l < NLD; l++) {
        float acc = 0.f;
#pragma unroll
        for (int i = 0; i < 8; i++) acc += v[i] * Wds[(lane + i * 32) * NLD + l];
#pragma unroll
        for (int o = 16; o > 0; o >>= 1) acc += __shfl_down_sync(0xffffffffu, acc, o);
        if (lane == 0)
            pred[((size_t)b * NLD + l) * SEG + s] = acc + bd[l];
    }
}

// ---------------- host launcher ----------------
extern "C" void kernel_launch(void* const* d_in, const int* in_sizes, int n_in,
                              void* d_out, int out_size) {
    (void)in_sizes; (void)n_in; (void)out_size;
    const float* src      = (const float*)d_in[0];
    const float* mems     = (const float*)d_in[1];
    const unsigned char* mask = (const unsigned char*)d_in[2];
    const float* W_in     = (const float*)d_in[3];
    const float* b_in     = (const float*)d_in[4];
    const float* qkv_w    = (const float*)d_in[5];
    const float* r_net_w  = (const float*)d_in[6];
    const float* o_w      = (const float*)d_in[7];
    const float* ln1_g    = (const float*)d_in[8];
    const float* ln1_b    = (const float*)d_in[9];
    const float* ff_w1    = (const float*)d_in[10];
    const float* ff_b1    = (const float*)d_in[11];
    const float* ff_w2    = (const float*)d_in[12];
    const float* ff_b2    = (const float*)d_in[13];
    const float* ln2_g    = (const float*)d_in[14];
    const float* ln2_b    = (const float*)d_in[15];
    const float* W_dec    = (const float*)d_in[16];
    const float* b_dec    = (const float*)d_in[17];
    const float* r_w_bias = (const float*)d_in[18];
    const float* r_r_bias = (const float*)d_in[19];

    float* out    = (float*)d_out;
    float* pred   = out;
    float* memout = out + PRED_N;

    k_input_proj<<<(CORE_N + 255)/256, 256>>>(src, W_in, b_in, memout);
    k_pos<<<(KL*DM + 255)/256, 256>>>();

    // rk for ALL layers in one z-batched GEMM: g_rk[l] = r @ r_net_w[l]
    k_gemm_tf32<64><<<dim3(DM/64, KL/64, LNUM), 256>>>(nullptr, 1, r_net_w, 6,
                                                       KL, DM, DM, nullptr, 0,
                                                       (size_t)DM*DM, (size_t)KL*DM);

    static float* rk_dev = nullptr;
    if (!rk_dev) cudaGetSymbolAddress((void**)&rk_dev, g_rk);

    for (int i = 0; i < LNUM; i++) {
        // heads = [mems_i ; core] @ qkv_w[i]   [4096 x 768 x 256], cat fused
        k_gemm_tf32<128><<<dim3(H3/64, (KL*BSZ)/128, 1), 256>>>(mems + (size_t)i * MEML*BSZ*DM, 100,
                                                                qkv_w + (size_t)i*DM*H3, 5,
                                                                KL*BSZ, H3, DM, nullptr, 0, 0, 0);
        // AC and BDpre in one launch (z = bh*2+mode), fp16 outputs
        k_qk_tf32<<<dim3(KL/64, SEG/128, BSZ*NH*2), 256>>>(r_w_bias, r_r_bias,
                                                           rk_dev + (size_t)i*KL*DM);
        // shift + combine + mask + softmax (fp16 in place)
        k_softmax<<<dim3(SEG, BSZ*NH), 256>>>(mask);
        // PV split-K (partials; reduction folded into the o-proj GEMM A-load)
        k_pv_tf32<<<dim3(SEG/64, BSZ*NH, 4), 128>>>();
        // attn output projection     [2048 x 256 x 256], A = sum of PV partials
        k_gemm_tf32<64><<<dim3(DM/64, (SEG*BSZ)/64, 1), 256>>>(nullptr, 101, o_w + (size_t)i*DM*DM, 4,
                                                               SEG*BSZ, DM, DM, nullptr, 0, 0, 0);
        k_addln<<<SEG*BSZ, DM>>>(4, ln1_g + i*DM, ln1_b + i*DM, nullptr);
        // ff1 + bias + relu          [2048 x 1024 x 256]
        k_gemm_tf32<128><<<dim3(DI/64, (SEG*BSZ)/128, 1), 256>>>(nullptr, 3, ff_w1 + (size_t)i*DM*DI, 4,
                                                                 SEG*BSZ, DI, DM, ff_b1 + i*DI, 1, 0, 0);
        // ff2 + bias                 [2048 x 256 x 1024]
        k_gemm_tf32<64><<<dim3(DM/64, (SEG*BSZ)/64, 1), 256>>>(nullptr, 4, ff_w2 + (size_t)i*DI*DM, 2,
                                                               SEG*BSZ, DM, DI, ff_b2 + i*DM, 0, 0, 0);
        k_addln<<<SEG*BSZ, DM>>>(2, ln2_g + i*DM, ln2_b + i*DM,
                                 memout + (size_t)(i+1)*CORE_N);
    }
    k_dec<<<(SEG*BSZ)/8, 256>>>(W_dec, b_dec, pred);
}

// round 8
// speedup vs baseline: 1.7665x; 1.1450x over previous
#include <cuda_runtime.h>
#include <cuda_fp16.h>
#include <math.h>

#define LNUM 4
#define DM   256
#define NH   8
#define DHH  32
#define DI   1024
#define SEG  1024
#define MEML 1024
#define KL   2048
#define BSZ  2
#define NLD  12
#define H3   768          // 3*H*DH
#define PRED_N (BSZ*NLD*SEG)
#define CORE_N (SEG*BSZ*DM)
#define SCALE 0.17677669529663687f   // 1/sqrt(32)

// ---------------- scratch (static device globals; no runtime allocation) ----------------
__device__ float  g_core [CORE_N];
__device__ float  g_heads[KL*BSZ*H3];
__device__ float  g_r    [KL*DM];
__device__ float  g_rk   [LNUM*KL*DM];              // all layers, batched upfront
__device__ float  g_vec  [CORE_N];
__device__ float  g_mid  [SEG*BSZ*DI];
__device__ __half g_AC   [(size_t)BSZ*NH*SEG*KL];   // AC scores / probs (in-place, fp16)
__device__ __half g_BD   [(size_t)BSZ*NH*SEG*KL];   // pre-shift BD (fp16)
__device__ float  g_pvp  [4*CORE_N];                // PV split-K partials

__device__ __forceinline__ float* bufsel(int id) {
    switch (id) {
        case 1: return g_r;
        case 2: return g_vec;
        case 3: return g_core;
        case 4: return g_mid;
        case 5: return g_heads;
        case 6: return g_rk;
    }
    return g_core;
}

// ---------------- tf32 helpers ----------------
__device__ __forceinline__ unsigned f2tf(float x) {
    unsigned u;
    asm("cvt.rna.tf32.f32 %0, %1;" : "=r"(u) : "f"(x));
    return u;
}
__device__ __forceinline__ void mma_tf32(float& c0, float& c1, float& c2, float& c3,
                                         unsigned a0, unsigned a1, unsigned a2, unsigned a3,
                                         unsigned b0, unsigned b1) {
    asm volatile(
        "mma.sync.aligned.m16n8k8.row.col.f32.tf32.tf32.f32 "
        "{%0,%1,%2,%3},{%4,%5,%6,%7},{%8,%9},{%0,%1,%2,%3};\n"
        : "+f"(c0), "+f"(c1), "+f"(c2), "+f"(c3)
        : "r"(a0), "r"(a1), "r"(a2), "r"(a3), "r"(b0), "r"(b1));
}
__device__ __forceinline__ void cp16(void* smem_dst, const void* gsrc) {
    unsigned dst = (unsigned)__cvta_generic_to_shared(smem_dst);
    asm volatile("cp.async.ca.shared.global [%0], [%1], 16;\n" :: "r"(dst), "l"(gsrc));
}

// ---------------- input projection: core = src^T @ W_in + b_in ; also mems_out[0] ----------------
__global__ void k_input_proj(const float* __restrict__ src, const float* __restrict__ W_in,
                             const float* __restrict__ b_in, float* __restrict__ memout) {
    int idx = blockIdx.x * blockDim.x + threadIdx.x;
    if (idx >= CORE_N) return;
    int d  = idx & (DM - 1);
    int sb = idx >> 8;
    int b  = sb & 1;
    int s  = sb >> 1;
    float acc = b_in[d];
#pragma unroll
    for (int l = 0; l < NLD; l++)
        acc += src[((size_t)b * NLD + l) * SEG + s] * W_in[l * DM + d];
    g_core[idx] = acc;
    memout[idx] = acc;   // new_mems[0] == hids[0]
}

// ---------------- positional embedding r[KLEN, D] ----------------
__global__ void k_pos() {
    int idx = blockIdx.x * blockDim.x + threadIdx.x;
    if (idx >= KL * DM) return;
    int d = idx & (DM - 1);
    int j = idx >> 8;
    float pos = (float)(KL - 1 - j);
    int f = (d < 128) ? d : d - 128;
    float inv = powf(10000.f, -(float)f / 128.f);
    float v = pos * inv;
    g_r[idx] = (d < 128) ? sinf(v) : cosf(v);
}

// ---------------- tf32 GEMM, cp.async 2-stage pipelined ----------------
// BM in {128,64}, BN=64, BK=16, 256 threads (8 warps: 4(M) x 2(N)).
// aid==100: virtual cat A (rows < MEML*BSZ from mems_i, else g_core).
// aid==101: A = sum of the 4 PV split-K partials (sync path).
// blockIdx.z batches B/C by bstride/cstride.
template<int BM>
__global__ void __launch_bounds__(256) k_gemm_tf32(
        const float* __restrict__ mems_i, int aid,
        const float* __restrict__ Bw, int cid,
        int M, int N, int K,
        const float* __restrict__ bias, int relu,
        size_t bstride, size_t cstride) {
    constexpr int MT = BM / 64;
    const float* A = bufsel(aid);
    float* C = bufsel(cid) + (size_t)blockIdx.z * cstride;
    Bw += (size_t)blockIdx.z * bstride;
    __shared__ float As[2][BM][20];   // raw fp32; stride 20 floats (80B, 16B-aligned rows)
    __shared__ float Bs[2][16][72];   // stride 72 floats (288B, 16B-aligned)
    int t = threadIdx.x;
    int m0 = blockIdx.y * BM, n0 = blockIdx.x * 64;
    int lane = t & 31, g = lane >> 2, tg = lane & 3;
    int w = t >> 5;
    int wm = (w >> 1) * 16 * MT, wn = (w & 1) * 32;

    float c[MT][4][4];
#pragma unroll
    for (int i = 0; i < MT; i++)
#pragma unroll
        for (int j = 0; j < 4; j++)
#pragma unroll
            for (int q = 0; q < 4; q++) c[i][j][q] = 0.f;

    // per-thread stage addressing
    int ar[MT], ac4[MT];
#pragma unroll
    for (int i = 0; i < MT; i++) { int f = t + i * 256; ar[i] = f >> 2; ac4[i] = (f & 3) * 4; }
    int br = t >> 4, bc4 = (t & 15) * 4;

    auto stage = [&](int k0, int s) {
#pragma unroll
        for (int i = 0; i < MT; i++) {
            int rg = m0 + ar[i];
            if (aid == 101) {
                size_t off = (size_t)rg * K + k0 + ac4[i];
                float4 v0 = *(const float4*)(g_pvp + off);
                float4 v1 = *(const float4*)(g_pvp + CORE_N + off);
                float4 v2 = *(const float4*)(g_pvp + 2*(size_t)CORE_N + off);
                float4 v3 = *(const float4*)(g_pvp + 3*(size_t)CORE_N + off);
                float4 v;
                v.x = v0.x + v1.x + v2.x + v3.x;
                v.y = v0.y + v1.y + v2.y + v3.y;
                v.z = v0.z + v1.z + v2.z + v3.z;
                v.w = v0.w + v1.w + v2.w + v3.w;
                *(float4*)(&As[s][ar[i]][ac4[i]]) = v;
            } else {
                const float* src;
                if (aid == 100)
                    src = (rg < MEML*BSZ) ? (mems_i + (size_t)rg * K + k0 + ac4[i])
                                          : (g_core + (size_t)(rg - MEML*BSZ) * K + k0 + ac4[i]);
                else
                    src = A + (size_t)rg * K + k0 + ac4[i];
                cp16(&As[s][ar[i]][ac4[i]], src);
            }
        }
        cp16(&Bs[s][br][bc4], Bw + (size_t)(k0 + br) * N + n0 + bc4);
        asm volatile("cp.async.commit_group;\n");
    };

    int KT = K / 16;
    stage(0, 0);
    for (int kt = 0; kt < KT; kt++) {
        int s = kt & 1;
        if (kt + 1 < KT) {
            stage((kt + 1) * 16, (kt + 1) & 1);
            asm volatile("cp.async.wait_group 1;\n");
        } else {
            asm volatile("cp.async.wait_group 0;\n");
        }
        __syncthreads();
#pragma unroll
        for (int ks = 0; ks < 16; ks += 8) {
            unsigned a[MT][4], bfrag[4][2];
#pragma unroll
            for (int mt = 0; mt < MT; mt++) {
                int r = wm + mt * 16 + g;
                a[mt][0] = f2tf(As[s][r][ks + tg]);
                a[mt][1] = f2tf(As[s][r + 8][ks + tg]);
                a[mt][2] = f2tf(As[s][r][ks + tg + 4]);
                a[mt][3] = f2tf(As[s][r + 8][ks + tg + 4]);
            }
#pragma unroll
            for (int nt = 0; nt < 4; nt++) {
                int col = wn + nt * 8 + g;
                bfrag[nt][0] = f2tf(Bs[s][ks + tg][col]);
                bfrag[nt][1] = f2tf(Bs[s][ks + tg + 4][col]);
            }
#pragma unroll
            for (int mt = 0; mt < MT; mt++)
#pragma unroll
                for (int nt = 0; nt < 4; nt++)
                    mma_tf32(c[mt][nt][0], c[mt][nt][1], c[mt][nt][2], c[mt][nt][3],
                             a[mt][0], a[mt][1], a[mt][2], a[mt][3],
                             bfrag[nt][0], bfrag[nt][1]);
        }
        __syncthreads();
    }
#pragma unroll
    for (int mt = 0; mt < MT; mt++) {
#pragma unroll
        for (int nt = 0; nt < 4; nt++) {
            int row = m0 + wm + mt * 16 + g;
            int col = n0 + wn + nt * 8 + 2 * tg;
            float b0 = 0.f, b1 = 0.f;
            if (bias) { b0 = bias[col]; b1 = bias[col + 1]; }
            float v0 = c[mt][nt][0] + b0, v1 = c[mt][nt][1] + b1;
            float v2 = c[mt][nt][2] + b0, v3 = c[mt][nt][3] + b1;
            if (relu) {
                v0 = fmaxf(v0, 0.f); v1 = fmaxf(v1, 0.f);
                v2 = fmaxf(v2, 0.f); v3 = fmaxf(v3, 0.f);
            }
            *(float2*)(C + (size_t)row * N + col)       = make_float2(v0, v1);
            *(float2*)(C + (size_t)(row + 8) * N + col) = make_float2(v2, v3);
        }
    }
}

// ---------------- tf32 QK^T 128x128: z = bh*2 + mode; mode 0 -> AC, mode 1 -> BDpre ----------------
// warp layout 4(M) x 2(N), warp tile 32x64. K=DH=32 single smem shot. fp16 out.
__global__ void __launch_bounds__(256) k_qk_tf32(
        const float* __restrict__ rwb, const float* __restrict__ rrb,
        const float* __restrict__ rk_l) {
    int z = blockIdx.z;
    int mode = z & 1, bh = z >> 1, b = bh >> 3, h = bh & 7;
    int i0 = blockIdx.y * 128, j0 = blockIdx.x * 128;
    const float* Qp = g_heads + (size_t)(MEML*BSZ + b) * H3 + h*DHH;
    const float* Kp; int kstr;
    __half* Cp;
    const float* qb;
    if (mode == 0) { Kp = g_heads + (size_t)b*H3 + DM + h*DHH; kstr = BSZ*H3; Cp = g_AC; qb = rwb + h*DHH; }
    else           { Kp = rk_l + h*DHH;                        kstr = DM;     Cp = g_BD; qb = rrb + h*DHH; }
    Cp += (size_t)bh * SEG * KL;

    __shared__ unsigned Qs[128][36];
    __shared__ unsigned Ks[128][36];
    int t = threadIdx.x;
    int lane = t & 31, g = lane >> 2, tg = lane & 3;
    int w = t >> 5;
    int wm = (w >> 1) * 32, wn = (w & 1) * 64;

#pragma unroll
    for (int i = 0; i < 4; i++) {
        int f = t + i * 256;
        int r = f >> 3, c4 = (f & 7) * 4;
        float4 v = *(const float4*)(Qp + (size_t)(i0 + r) * (BSZ*H3) + c4);
        Qs[r][c4]   = f2tf(v.x + qb[c4]);   Qs[r][c4+1] = f2tf(v.y + qb[c4+1]);
        Qs[r][c4+2] = f2tf(v.z + qb[c4+2]); Qs[r][c4+3] = f2tf(v.w + qb[c4+3]);
    }
#pragma unroll
    for (int i = 0; i < 4; i++) {
        int f = t + i * 256;
        int r = f >> 3, c4 = (f & 7) * 4;
        float4 v = *(const float4*)(Kp + (size_t)(j0 + r) * kstr + c4);
        Ks[r][c4]   = f2tf(v.x); Ks[r][c4+1] = f2tf(v.y);
        Ks[r][c4+2] = f2tf(v.z); Ks[r][c4+3] = f2tf(v.w);
    }
    __syncthreads();

    float c[2][8][4];
#pragma unroll
    for (int i = 0; i < 2; i++)
#pragma unroll
        for (int j = 0; j < 8; j++)
#pragma unroll
            for (int q = 0; q < 4; q++) c[i][j][q] = 0.f;

#pragma unroll
    for (int ks = 0; ks < 32; ks += 8) {
        unsigned a[2][4], bfrag[8][2];
#pragma unroll
        for (int mt = 0; mt < 2; mt++) {
            int r = wm + mt * 16 + g;
            a[mt][0] = Qs[r][ks + tg];
            a[mt][1] = Qs[r + 8][ks + tg];
            a[mt][2] = Qs[r][ks + tg + 4];
            a[mt][3] = Qs[r + 8][ks + tg + 4];
        }
#pragma unroll
        for (int nt = 0; nt < 8; nt++) {
            int col = wn + nt * 8 + g;
            bfrag[nt][0] = Ks[col][ks + tg];
            bfrag[nt][1] = Ks[col][ks + tg + 4];
        }
#pragma unroll
        for (int mt = 0; mt < 2; mt++)
#pragma unroll
            for (int nt = 0; nt < 8; nt++)
                mma_tf32(c[mt][nt][0], c[mt][nt][1], c[mt][nt][2], c[mt][nt][3],
                         a[mt][0], a[mt][1], a[mt][2], a[mt][3],
                         bfrag[nt][0], bfrag[nt][1]);
    }
#pragma unroll
    for (int mt = 0; mt < 2; mt++)
#pragma unroll
        for (int nt = 0; nt < 8; nt++) {
            int row = i0 + wm + mt * 16 + g;
            int col = j0 + wn + nt * 8 + 2 * tg;
            *(__half2*)(Cp + (size_t)row * KL + col)       = __floats2half2_rn(c[mt][nt][0], c[mt][nt][1]);
            *(__half2*)(Cp + (size_t)(row + 8) * KL + col) = __floats2half2_rn(c[mt][nt][2], c[mt][nt][3]);
        }
}

// ---------------- fused rel_shift + combine + mask + softmax (fp16 in/out, in-place) ----------------
__global__ void k_softmax(const unsigned char* __restrict__ mask) {
    int i = blockIdx.x, bh = blockIdx.y;
    int t = threadIdx.x;
    __half* ac = g_AC + ((size_t)bh * SEG + i) * KL;
    float vals[8];
    float mx = -INFINITY;
#pragma unroll
    for (int r2 = 0; r2 < 4; r2++) {
        int j0 = 2*t + r2 * 512;
        float2 a2 = __half22float2(*(const __half2*)(ac + j0));
#pragma unroll
        for (int q = 0; q < 2; q++) {
            int j = j0 + q;
            int f = SEG + i * KL + j;              // rel_shift flat index
            int a = f / (KL + 1);
            int p = f - a * (KL + 1);
            float bd = (p == 0) ? 0.f : __half2float(g_BD[((size_t)bh * SEG + a) * KL + (p - 1)]);
            float s = ((q ? a2.y : a2.x) + bd) * SCALE;
            if (mask[(size_t)i * KL + j]) s = -INFINITY;
            vals[r2*2 + q] = s;
            mx = fmaxf(mx, s);
        }
    }
    __shared__ float red[256];
    red[t] = mx; __syncthreads();
    for (int s2 = 128; s2 > 0; s2 >>= 1) { if (t < s2) red[t] = fmaxf(red[t], red[t+s2]); __syncthreads(); }
    float rowmax = red[0]; __syncthreads();
    float sum = 0.f;
#pragma unroll
    for (int r2 = 0; r2 < 8; r2++) { vals[r2] = __expf(vals[r2] - rowmax); sum += vals[r2]; }
    red[t] = sum; __syncthreads();
    for (int s2 = 128; s2 > 0; s2 >>= 1) { if (t < s2) red[t] += red[t+s2]; __syncthreads(); }
    float inv = 1.f / red[0];
#pragma unroll
    for (int r2 = 0; r2 < 4; r2++)
        *(__half2*)(ac + 2*t + r2*512) =
            __floats2half2_rn(vals[r2*2] * inv, vals[r2*2+1] * inv);
}

// ---------------- tf32 PV split-K: P fp16 in; partial over j-range -> g_pvp[js] ----------------
__global__ void k_pv_tf32() {
    int bh = blockIdx.y, b = bh >> 3, h = bh & 7;
    int i0 = blockIdx.x * 64;
    int js = blockIdx.z;
    const __half* P = g_AC + (size_t)bh * SEG * KL;
    const float* V = g_heads + (size_t)b * H3 + 2*DM + h*DHH;
    const int sV = BSZ*H3;
    float* Out = g_pvp + (size_t)js * CORE_N;

    __shared__ unsigned Ps[64][36];
    __shared__ unsigned Vst[32][36];   // transposed: Vst[d][j_rel]
    int t = threadIdx.x;
    int lane = t & 31, g = lane >> 2, tg = lane & 3;
    int w = t >> 5;
    int wm = w * 16;

    float c[4][4];
#pragma unroll
    for (int j = 0; j < 4; j++)
#pragma unroll
        for (int q = 0; q < 4; q++) c[j][q] = 0.f;

    int jb = js * (KL/4), je = jb + (KL/4);
    for (int j0 = jb; j0 < je; j0 += 32) {
#pragma unroll
        for (int i = 0; i < 2; i++) {
            int f = t + i * 128;
            int r = f >> 2, c8 = (f & 3) * 8;
            float4 raw = *(const float4*)(P + (size_t)(i0 + r) * KL + j0 + c8);
            const __half2* hp = (const __half2*)&raw;
#pragma unroll
            for (int q = 0; q < 4; q++) {
                float2 fv = __half22float2(hp[q]);
                Ps[r][c8 + 2*q]     = f2tf(fv.x);
                Ps[r][c8 + 2*q + 1] = f2tf(fv.y);
            }
        }
#pragma unroll
        for (int i = 0; i < 2; i++) {
            int f = t + i * 128;
            int jr = f >> 3, c4 = (f & 7) * 4;
            float4 v = *(const float4*)(V + (size_t)(j0 + jr) * sV + c4);
            Vst[c4][jr]   = f2tf(v.x); Vst[c4+1][jr] = f2tf(v.y);
            Vst[c4+2][jr] = f2tf(v.z); Vst[c4+3][jr] = f2tf(v.w);
        }
        __syncthreads();
#pragma unroll
        for (int ks = 0; ks < 32; ks += 8) {
            unsigned a0 = Ps[wm + g][ks + tg];
            unsigned a1 = Ps[wm + g + 8][ks + tg];
            unsigned a2 = Ps[wm + g][ks + tg + 4];
            unsigned a3 = Ps[wm + g + 8][ks + tg + 4];
#pragma unroll
            for (int nt = 0; nt < 4; nt++) {
                unsigned b0 = Vst[nt * 8 + g][ks + tg];
                unsigned b1 = Vst[nt * 8 + g][ks + tg + 4];
                mma_tf32(c[nt][0], c[nt][1], c[nt][2], c[nt][3], a0, a1, a2, a3, b0, b1);
            }
        }
        __syncthreads();
    }
#pragma unroll
    for (int nt = 0; nt < 4; nt++) {
        int row = i0 + wm + g;
        int col = h*DHH + nt * 8 + 2 * tg;
        *(float2*)(Out + (size_t)(row * BSZ + b) * DM + col)       = make_float2(c[nt][0], c[nt][1]);
        *(float2*)(Out + (size_t)((row + 8) * BSZ + b) * DM + col) = make_float2(c[nt][2], c[nt][3]);
    }
}

// ---------------- residual add + LayerNorm; optional write to mems output ----------------
__global__ void k_addln(int did, const float* __restrict__ gamma, const float* __restrict__ beta,
                        float* __restrict__ memout) {
    const float* delta = bufsel(did);
    int row = blockIdx.x, d = threadIdx.x;
    size_t off = (size_t)row * DM + d;
    float x = g_core[off] + delta[off];
    __shared__ float red[DM];
    red[d] = x; __syncthreads();
    for (int s = 128; s > 0; s >>= 1) { if (d < s) red[d] += red[d+s]; __syncthreads(); }
    float mu = red[0] * (1.f/DM); __syncthreads();
    float c = x - mu;
    red[d] = c * c; __syncthreads();
    for (int s = 128; s > 0; s >>= 1) { if (d < s) red[d] += red[d+s]; __syncthreads(); }
    float var = red[0] * (1.f/DM);
    float y = c * (1.f / sqrtf(var + 1e-5f)) * gamma[d] + beta[d];
    g_core[off] = y;
    if (memout) memout[off] = y;
}

// ---------------- decoder ----------------
__global__ void k_dec(const float* __restrict__ Wd, const float* __restrict__ bd,
                      float* __restrict__ pred) {
    __shared__ float Wds[DM * NLD];
    int t = threadIdx.x;
    for (int i = t; i < DM * NLD; i += 256) Wds[i] = Wd[i];
    __syncthreads();
    int lane = t & 31, w = t >> 5;
    int row = blockIdx.x * 8 + w;          // row = s*BSZ + b
    int b = row & 1, s = row >> 1;
    const float* crow = g_core + (size_t)row * DM;
    float v[8];
#pragma unroll
    for (int i = 0; i < 8; i++) v[i] = crow[lane + i * 32];
#pragma unroll
    for (int l = 0; l < NLD; l++) {
        float acc = 0.f;
#pragma unroll
        for (int i = 0; i < 8; i++) acc += v[i] * Wds[(lane + i * 32) * NLD + l];
#pragma unroll
        for (int o = 16; o > 0; o >>= 1) acc += __shfl_down_sync(0xffffffffu, acc, o);
        if (lane == 0)
            pred[((size_t)b * NLD + l) * SEG + s] = acc + bd[l];
    }
}

// ---------------- host launcher ----------------
extern "C" void kernel_launch(void* const* d_in, const int* in_sizes, int n_in,
                              void* d_out, int out_size) {
    (void)in_sizes; (void)n_in; (void)out_size;
    const float* src      = (const float*)d_in[0];
    const float* mems     = (const float*)d_in[1];
    const unsigned char* mask = (const unsigned char*)d_in[2];
    const float* W_in     = (const float*)d_in[3];
    const float* b_in     = (const float*)d_in[4];
    const float* qkv_w    = (const float*)d_in[5];
    const float* r_net_w  = (const float*)d_in[6];
    const float* o_w      = (const float*)d_in[7];
    const float* ln1_g    = (const float*)d_in[8];
    const float* ln1_b    = (const float*)d_in[9];
    const float* ff_w1    = (const float*)d_in[10];
    const float* ff_b1    = (const float*)d_in[11];
    const float* ff_w2    = (const float*)d_in[12];
    const float* ff_b2    = (const float*)d_in[13];
    const float* ln2_g    = (const float*)d_in[14];
    const float* ln2_b    = (const float*)d_in[15];
    const float* W_dec    = (const float*)d_in[16];
    const float* b_dec    = (const float*)d_in[17];
    const float* r_w_bias = (const float*)d_in[18];
    const float* r_r_bias = (const float*)d_in[19];

    float* out    = (float*)d_out;
    float* pred   = out;
    float* memout = out + PRED_N;

    k_input_proj<<<(CORE_N + 255)/256, 256>>>(src, W_in, b_in, memout);
    k_pos<<<(KL*DM + 255)/256, 256>>>();

    // rk for ALL layers in one z-batched GEMM: g_rk[l] = r @ r_net_w[l]
    k_gemm_tf32<64><<<dim3(DM/64, KL/64, LNUM), 256>>>(nullptr, 1, r_net_w, 6,
                                                       KL, DM, DM, nullptr, 0,
                                                       (size_t)DM*DM, (size_t)KL*DM);

    static float* rk_dev = nullptr;
    if (!rk_dev) cudaGetSymbolAddress((void**)&rk_dev, g_rk);

    for (int i = 0; i < LNUM; i++) {
        // heads = [mems_i ; core] @ qkv_w[i]   [4096 x 768 x 256], cat fused
        k_gemm_tf32<128><<<dim3(H3/64, (KL*BSZ)/128, 1), 256>>>(mems + (size_t)i * MEML*BSZ*DM, 100,
                                                                qkv_w + (size_t)i*DM*H3, 5,
                                                                KL*BSZ, H3, DM, nullptr, 0, 0, 0);
        // AC and BDpre in one launch (z = bh*2+mode), 128x128 tiles, fp16 outputs
        k_qk_tf32<<<dim3(KL/128, SEG/128, BSZ*NH*2), 256>>>(r_w_bias, r_r_bias,
                                                            rk_dev + (size_t)i*KL*DM);
        // shift + combine + mask + softmax (fp16 in place)
        k_softmax<<<dim3(SEG, BSZ*NH), 256>>>(mask);
        // PV split-K (partials; reduction folded into the o-proj GEMM A-load)
        k_pv_tf32<<<dim3(SEG/64, BSZ*NH, 4), 128>>>();
        // attn output projection     [2048 x 256 x 256], A = sum of PV partials
        k_gemm_tf32<64><<<dim3(DM/64, (SEG*BSZ)/64, 1), 256>>>(nullptr, 101, o_w + (size_t)i*DM*DM, 4,
                                                               SEG*BSZ, DM, DM, nullptr, 0, 0, 0);
        k_addln<<<SEG*BSZ, DM>>>(4, ln1_g + i*DM, ln1_b + i*DM, nullptr);
        // ff1 + bias + relu          [2048 x 1024 x 256]
        k_gemm_tf32<128><<<dim3(DI/64, (SEG*BSZ)/128, 1), 256>>>(nullptr, 3, ff_w1 + (size_t)i*DM*DI, 4,
                                                                 SEG*BSZ, DI, DM, ff_b1 + i*DI, 1, 0, 0);
        // ff2 + bias                 [2048 x 256 x 1024]
        k_gemm_tf32<64><<<dim3(DM/64, (SEG*BSZ)/64, 1), 256>>>(nullptr, 4, ff_w2 + (size_t)i*DI*DM, 2,
                                                               SEG*BSZ, DM, DI, ff_b2 + i*DM, 0, 0, 0);
        k_addln<<<SEG*BSZ, DM>>>(2, ln2_g + i*DM, ln2_b + i*DM,
                                 memout + (size_t)(i+1)*CORE_N);
    }
    k_dec<<<(SEG*BSZ)/8, 256>>>(W_dec, b_dec, pred);
}

// round 9
// speedup vs baseline: 1.8067x; 1.0228x over previous
#include <cuda_runtime.h>
#include <cuda_fp16.h>
#include <math.h>

#define LNUM 4
#define DM   256
#define NH   8
#define DHH  32
#define DI   1024
#define SEG  1024
#define MEML 1024
#define KL   2048
#define BSZ  2
#define NLD  12
#define H3   768          // 3*H*DH
#define PRED_N (BSZ*NLD*SEG)
#define CORE_N (SEG*BSZ*DM)
#define SCALE 0.17677669529663687f   // 1/sqrt(32)

// ---------------- scratch (static device globals; no runtime allocation) ----------------
__device__ float  g_core [CORE_N];
__device__ float  g_heads[KL*BSZ*H3];
__device__ float  g_r    [KL*DM];
__device__ float  g_rk   [LNUM*KL*DM];              // all layers, batched upfront
__device__ float  g_vec  [CORE_N];
__device__ float  g_mid  [SEG*BSZ*DI];
__device__ __half g_AC   [(size_t)BSZ*NH*SEG*KL];   // AC scores / probs (in-place, fp16)
__device__ __half g_BD   [(size_t)BSZ*NH*SEG*KL];   // pre-shift BD (fp16)
__device__ float  g_pvp  [4*CORE_N];                // PV split-K partials

__device__ __forceinline__ float* bufsel(int id) {
    switch (id) {
        case 1: return g_r;
        case 2: return g_vec;
        case 3: return g_core;
        case 4: return g_mid;
        case 5: return g_heads;
        case 6: return g_rk;
    }
    return g_core;
}

// ---------------- tf32 mma; operands carry raw fp32 bits (HW uses tf32 field; RZ on low bits) ----------------
__device__ __forceinline__ void mma_tf32(float& c0, float& c1, float& c2, float& c3,
                                         unsigned a0, unsigned a1, unsigned a2, unsigned a3,
                                         unsigned b0, unsigned b1) {
    asm volatile(
        "mma.sync.aligned.m16n8k8.row.col.f32.tf32.tf32.f32 "
        "{%0,%1,%2,%3},{%4,%5,%6,%7},{%8,%9},{%0,%1,%2,%3};\n"
        : "+f"(c0), "+f"(c1), "+f"(c2), "+f"(c3)
        : "r"(a0), "r"(a1), "r"(a2), "r"(a3), "r"(b0), "r"(b1));
}
__device__ __forceinline__ void cp16(void* smem_dst, const void* gsrc) {
    unsigned dst = (unsigned)__cvta_generic_to_shared(smem_dst);
    asm volatile("cp.async.ca.shared.global [%0], [%1], 16;\n" :: "r"(dst), "l"(gsrc));
}

// ---------------- input projection: core = src^T @ W_in + b_in ; also mems_out[0] ----------------
__global__ void k_input_proj(const float* __restrict__ src, const float* __restrict__ W_in,
                             const float* __restrict__ b_in, float* __restrict__ memout) {
    int idx = blockIdx.x * blockDim.x + threadIdx.x;
    if (idx >= CORE_N) return;
    int d  = idx & (DM - 1);
    int sb = idx >> 8;
    int b  = sb & 1;
    int s  = sb >> 1;
    float acc = b_in[d];
#pragma unroll
    for (int l = 0; l < NLD; l++)
        acc += src[((size_t)b * NLD + l) * SEG + s] * W_in[l * DM + d];
    g_core[idx] = acc;
    memout[idx] = acc;   // new_mems[0] == hids[0]
}

// ---------------- positional embedding r[KLEN, D] ----------------
__global__ void k_pos() {
    int idx = blockIdx.x * blockDim.x + threadIdx.x;
    if (idx >= KL * DM) return;
    int d = idx & (DM - 1);
    int j = idx >> 8;
    float pos = (float)(KL - 1 - j);
    int f = (d < 128) ? d : d - 128;
    float inv = powf(10000.f, -(float)f / 128.f);
    float v = pos * inv;
    g_r[idx] = (d < 128) ? sinf(v) : cosf(v);
}

// ---------------- tf32 GEMM, cp.async 2-stage pipelined, no-convert operands ----------------
// BM in {128,64}, BN=64, BK=16, 256 threads (8 warps: 4(M) x 2(N)).
// aid==100: virtual cat A (rows < MEML*BSZ from mems_i, else g_core).
// aid==101: A = sum of the 4 PV split-K partials (sync path).
// blockIdx.z batches B/C by bstride/cstride.
template<int BM>
__global__ void __launch_bounds__(256) k_gemm_tf32(
        const float* __restrict__ mems_i, int aid,
        const float* __restrict__ Bw, int cid,
        int M, int N, int K,
        const float* __restrict__ bias, int relu,
        size_t bstride, size_t cstride) {
    constexpr int MT = BM / 64;
    const float* A = bufsel(aid);
    float* C = bufsel(cid) + (size_t)blockIdx.z * cstride;
    Bw += (size_t)blockIdx.z * bstride;
    __shared__ float As[2][BM][20];   // raw fp32; stride 20 floats (80B, 16B-aligned rows)
    __shared__ float Bs[2][16][72];   // stride 72 floats (288B, 16B-aligned)
    int t = threadIdx.x;
    int m0 = blockIdx.y * BM, n0 = blockIdx.x * 64;
    int lane = t & 31, g = lane >> 2, tg = lane & 3;
    int w = t >> 5;
    int wm = (w >> 1) * 16 * MT, wn = (w & 1) * 32;

    float c[MT][4][4];
#pragma unroll
    for (int i = 0; i < MT; i++)
#pragma unroll
        for (int j = 0; j < 4; j++)
#pragma unroll
            for (int q = 0; q < 4; q++) c[i][j][q] = 0.f;

    int ar[MT], ac4[MT];
#pragma unroll
    for (int i = 0; i < MT; i++) { int f = t + i * 256; ar[i] = f >> 2; ac4[i] = (f & 3) * 4; }
    int br = t >> 4, bc4 = (t & 15) * 4;

    auto stage = [&](int k0, int s) {
#pragma unroll
        for (int i = 0; i < MT; i++) {
            int rg = m0 + ar[i];
            if (aid == 101) {
                size_t off = (size_t)rg * K + k0 + ac4[i];
                float4 v0 = *(const float4*)(g_pvp + off);
                float4 v1 = *(const float4*)(g_pvp + CORE_N + off);
                float4 v2 = *(const float4*)(g_pvp + 2*(size_t)CORE_N + off);
                float4 v3 = *(const float4*)(g_pvp + 3*(size_t)CORE_N + off);
                float4 v;
                v.x = v0.x + v1.x + v2.x + v3.x;
                v.y = v0.y + v1.y + v2.y + v3.y;
                v.z = v0.z + v1.z + v2.z + v3.z;
                v.w = v0.w + v1.w + v2.w + v3.w;
                *(float4*)(&As[s][ar[i]][ac4[i]]) = v;
            } else {
                const float* src;
                if (aid == 100)
                    src = (rg < MEML*BSZ) ? (mems_i + (size_t)rg * K + k0 + ac4[i])
                                          : (g_core + (size_t)(rg - MEML*BSZ) * K + k0 + ac4[i]);
                else
                    src = A + (size_t)rg * K + k0 + ac4[i];
                cp16(&As[s][ar[i]][ac4[i]], src);
            }
        }
        cp16(&Bs[s][br][bc4], Bw + (size_t)(k0 + br) * N + n0 + bc4);
        asm volatile("cp.async.commit_group;\n");
    };

    int KT = K / 16;
    stage(0, 0);
    for (int kt = 0; kt < KT; kt++) {
        int s = kt & 1;
        if (kt + 1 < KT) {
            stage((kt + 1) * 16, (kt + 1) & 1);
            asm volatile("cp.async.wait_group 1;\n");
        } else {
            asm volatile("cp.async.wait_group 0;\n");
        }
        __syncthreads();
#pragma unroll
        for (int ks = 0; ks < 16; ks += 8) {
            unsigned a[MT][4], bfrag[4][2];
#pragma unroll
            for (int mt = 0; mt < MT; mt++) {
                int r = wm + mt * 16 + g;
                a[mt][0] = __float_as_uint(As[s][r][ks + tg]);
                a[mt][1] = __float_as_uint(As[s][r + 8][ks + tg]);
                a[mt][2] = __float_as_uint(As[s][r][ks + tg + 4]);
                a[mt][3] = __float_as_uint(As[s][r + 8][ks + tg + 4]);
            }
#pragma unroll
            for (int nt = 0; nt < 4; nt++) {
                int col = wn + nt * 8 + g;
                bfrag[nt][0] = __float_as_uint(Bs[s][ks + tg][col]);
                bfrag[nt][1] = __float_as_uint(Bs[s][ks + tg + 4][col]);
            }
#pragma unroll
            for (int mt = 0; mt < MT; mt++)
#pragma unroll
                for (int nt = 0; nt < 4; nt++)
                    mma_tf32(c[mt][nt][0], c[mt][nt][1], c[mt][nt][2], c[mt][nt][3],
                             a[mt][0], a[mt][1], a[mt][2], a[mt][3],
                             bfrag[nt][0], bfrag[nt][1]);
        }
        __syncthreads();
    }
#pragma unroll
    for (int mt = 0; mt < MT; mt++) {
#pragma unroll
        for (int nt = 0; nt < 4; nt++) {
            int row = m0 + wm + mt * 16 + g;
            int col = n0 + wn + nt * 8 + 2 * tg;
            float b0 = 0.f, b1 = 0.f;
            if (bias) { b0 = bias[col]; b1 = bias[col + 1]; }
            float v0 = c[mt][nt][0] + b0, v1 = c[mt][nt][1] + b1;
            float v2 = c[mt][nt][2] + b0, v3 = c[mt][nt][3] + b1;
            if (relu) {
                v0 = fmaxf(v0, 0.f); v1 = fmaxf(v1, 0.f);
                v2 = fmaxf(v2, 0.f); v3 = fmaxf(v3, 0.f);
            }
            *(float2*)(C + (size_t)row * N + col)       = make_float2(v0, v1);
            *(float2*)(C + (size_t)(row + 8) * N + col) = make_float2(v2, v3);
        }
    }
}

// ---------------- tf32 QK^T 128x128: z = bh*2 + mode; mode 0 -> AC, mode 1 -> BDpre ----------------
// warp layout 4(M) x 2(N), warp tile 32x64. K=DH=32 single smem shot. fp16 out.
__global__ void __launch_bounds__(256) k_qk_tf32(
        const float* __restrict__ rwb, const float* __restrict__ rrb,
        const float* __restrict__ rk_l) {
    int z = blockIdx.z;
    int mode = z & 1, bh = z >> 1, b = bh >> 3, h = bh & 7;
    int i0 = blockIdx.y * 128, j0 = blockIdx.x * 128;
    const float* Qp = g_heads + (size_t)(MEML*BSZ + b) * H3 + h*DHH;
    const float* Kp; int kstr;
    __half* Cp;
    const float* qb;
    if (mode == 0) { Kp = g_heads + (size_t)b*H3 + DM + h*DHH; kstr = BSZ*H3; Cp = g_AC; qb = rwb + h*DHH; }
    else           { Kp = rk_l + h*DHH;                        kstr = DM;     Cp = g_BD; qb = rrb + h*DHH; }
    Cp += (size_t)bh * SEG * KL;

    __shared__ float Qs[128][36];
    __shared__ float Ks[128][36];
    int t = threadIdx.x;
    int lane = t & 31, g = lane >> 2, tg = lane & 3;
    int w = t >> 5;
    int wm = (w >> 1) * 32, wn = (w & 1) * 64;

#pragma unroll
    for (int i = 0; i < 4; i++) {
        int f = t + i * 256;
        int r = f >> 3, c4 = (f & 7) * 4;
        float4 v = *(const float4*)(Qp + (size_t)(i0 + r) * (BSZ*H3) + c4);
        Qs[r][c4]   = v.x + qb[c4];   Qs[r][c4+1] = v.y + qb[c4+1];
        Qs[r][c4+2] = v.z + qb[c4+2]; Qs[r][c4+3] = v.w + qb[c4+3];
    }
#pragma unroll
    for (int i = 0; i < 4; i++) {
        int f = t + i * 256;
        int r = f >> 3, c4 = (f & 7) * 4;
        float4 v = *(const float4*)(Kp + (size_t)(j0 + r) * kstr + c4);
        *(float4*)(&Ks[r][c4]) = v;
    }
    __syncthreads();

    float c[2][8][4];
#pragma unroll
    for (int i = 0; i < 2; i++)
#pragma unroll
        for (int j = 0; j < 8; j++)
#pragma unroll
            for (int q = 0; q < 4; q++) c[i][j][q] = 0.f;

#pragma unroll
    for (int ks = 0; ks < 32; ks += 8) {
        unsigned a[2][4], bfrag[8][2];
#pragma unroll
        for (int mt = 0; mt < 2; mt++) {
            int r = wm + mt * 16 + g;
            a[mt][0] = __float_as_uint(Qs[r][ks + tg]);
            a[mt][1] = __float_as_uint(Qs[r + 8][ks + tg]);
            a[mt][2] = __float_as_uint(Qs[r][ks + tg + 4]);
            a[mt][3] = __float_as_uint(Qs[r + 8][ks + tg + 4]);
        }
#pragma unroll
        for (int nt = 0; nt < 8; nt++) {
            int col = wn + nt * 8 + g;
            bfrag[nt][0] = __float_as_uint(Ks[col][ks + tg]);
            bfrag[nt][1] = __float_as_uint(Ks[col][ks + tg + 4]);
        }
#pragma unroll
        for (int mt = 0; mt < 2; mt++)
#pragma unroll
            for (int nt = 0; nt < 8; nt++)
                mma_tf32(c[mt][nt][0], c[mt][nt][1], c[mt][nt][2], c[mt][nt][3],
                         a[mt][0], a[mt][1], a[mt][2], a[mt][3],
                         bfrag[nt][0], bfrag[nt][1]);
    }
#pragma unroll
    for (int mt = 0; mt < 2; mt++)
#pragma unroll
        for (int nt = 0; nt < 8; nt++) {
            int row = i0 + wm + mt * 16 + g;
            int col = j0 + wn + nt * 8 + 2 * tg;
            *(__half2*)(Cp + (size_t)row * KL + col)       = __floats2half2_rn(c[mt][nt][0], c[mt][nt][1]);
            *(__half2*)(Cp + (size_t)(row + 8) * KL + col) = __floats2half2_rn(c[mt][nt][2], c[mt][nt][3]);
        }
}

// ---------------- fused rel_shift + combine + mask + softmax (fp16 in/out, in-place) ----------------
__global__ void k_softmax(const unsigned char* __restrict__ mask) {
    int i = blockIdx.x, bh = blockIdx.y;
    int t = threadIdx.x;
    __half* ac = g_AC + ((size_t)bh * SEG + i) * KL;
    float vals[8];
    float mx = -INFINITY;
#pragma unroll
    for (int r2 = 0; r2 < 4; r2++) {
        int j0 = 2*t + r2 * 512;
        float2 a2 = __half22float2(*(const __half2*)(ac + j0));
#pragma unroll
        for (int q = 0; q < 2; q++) {
            int j = j0 + q;
            int f = SEG + i * KL + j;              // rel_shift flat index
            int a = f / (KL + 1);
            int p = f - a * (KL + 1);
            float bd = (p == 0) ? 0.f : __half2float(g_BD[((size_t)bh * SEG + a) * KL + (p - 1)]);
            float s = ((q ? a2.y : a2.x) + bd) * SCALE;
            if (mask[(size_t)i * KL + j]) s = -INFINITY;
            vals[r2*2 + q] = s;
            mx = fmaxf(mx, s);
        }
    }
    __shared__ float red[256];
    red[t] = mx; __syncthreads();
    for (int s2 = 128; s2 > 0; s2 >>= 1) { if (t < s2) red[t] = fmaxf(red[t], red[t+s2]); __syncthreads(); }
    float rowmax = red[0]; __syncthreads();
    float sum = 0.f;
#pragma unroll
    for (int r2 = 0; r2 < 8; r2++) { vals[r2] = __expf(vals[r2] - rowmax); sum += vals[r2]; }
    red[t] = sum; __syncthreads();
    for (int s2 = 128; s2 > 0; s2 >>= 1) { if (t < s2) red[t] += red[t+s2]; __syncthreads(); }
    float inv = 1.f / red[0];
#pragma unroll
    for (int r2 = 0; r2 < 4; r2++)
        *(__half2*)(ac + 2*t + r2*512) =
            __floats2half2_rn(vals[r2*2] * inv, vals[r2*2+1] * inv);
}

// ---------------- tf32 PV split-K: P fp16 in; partial over j-range -> g_pvp[js] ----------------
__global__ void k_pv_tf32() {
    int bh = blockIdx.y, b = bh >> 3, h = bh & 7;
    int i0 = blockIdx.x * 64;
    int js = blockIdx.z;
    const __half* P = g_AC + (size_t)bh * SEG * KL;
    const float* V = g_heads + (size_t)b * H3 + 2*DM + h*DHH;
    const int sV = BSZ*H3;
    float* Out = g_pvp + (size_t)js * CORE_N;

    __shared__ float Ps[64][36];
    __shared__ float Vst[32][36];   // transposed: Vst[d][j_rel]
    int t = threadIdx.x;
    int lane = t & 31, g = lane >> 2, tg = lane & 3;
    int w = t >> 5;
    int wm = w * 16;

    float c[4][4];
#pragma unroll
    for (int j = 0; j < 4; j++)
#pragma unroll
        for (int q = 0; q < 4; q++) c[j][q] = 0.f;

    int jb = js * (KL/4), je = jb + (KL/4);
    for (int j0 = jb; j0 < je; j0 += 32) {
#pragma unroll
        for (int i = 0; i < 2; i++) {
            int f = t + i * 128;
            int r = f >> 2, c8 = (f & 3) * 8;
            float4 raw = *(const float4*)(P + (size_t)(i0 + r) * KL + j0 + c8);
            const __half2* hp = (const __half2*)&raw;
#pragma unroll
            for (int q = 0; q < 4; q++) {
                float2 fv = __half22float2(hp[q]);
                Ps[r][c8 + 2*q]     = fv.x;
                Ps[r][c8 + 2*q + 1] = fv.y;
            }
        }
#pragma unroll
        for (int i = 0; i < 2; i++) {
            int f = t + i * 128;
            int jr = f >> 3, c4 = (f & 7) * 4;
            float4 v = *(const float4*)(V + (size_t)(j0 + jr) * sV + c4);
            Vst[c4][jr]   = v.x; Vst[c4+1][jr] = v.y;
            Vst[c4+2][jr] = v.z; Vst[c4+3][jr] = v.w;
        }
        __syncthreads();
#pragma unroll
        for (int ks = 0; ks < 32; ks += 8) {
            unsigned a0 = __float_as_uint(Ps[wm + g][ks + tg]);
            unsigned a1 = __float_as_uint(Ps[wm + g + 8][ks + tg]);
            unsigned a2 = __float_as_uint(Ps[wm + g][ks + tg + 4]);
            unsigned a3 = __float_as_uint(Ps[wm + g + 8][ks + tg + 4]);
#pragma unroll
            for (int nt = 0; nt < 4; nt++) {
                unsigned b0 = __float_as_uint(Vst[nt * 8 + g][ks + tg]);
                unsigned b1 = __float_as_uint(Vst[nt * 8 + g][ks + tg + 4]);
                mma_tf32(c[nt][0], c[nt][1], c[nt][2], c[nt][3], a0, a1, a2, a3, b0, b1);
            }
        }
        __syncthreads();
    }
#pragma unroll
    for (int nt = 0; nt < 4; nt++) {
        int row = i0 + wm + g;
        int col = h*DHH + nt * 8 + 2 * tg;
        *(float2*)(Out + (size_t)(row * BSZ + b) * DM + col)       = make_float2(c[nt][0], c[nt][1]);
        *(float2*)(Out + (size_t)((row + 8) * BSZ + b) * DM + col) = make_float2(c[nt][2], c[nt][3]);
    }
}

// ---------------- residual add + LayerNorm; optional write to mems output ----------------
__global__ void k_addln(int did, const float* __restrict__ gamma, const float* __restrict__ beta,
                        float* __restrict__ memout) {
    const float* delta = bufsel(did);
    int row = blockIdx.x, d = threadIdx.x;
    size_t off = (size_t)row * DM + d;
    float x = g_core[off] + delta[off];
    __shared__ float red[DM];
    red[d] = x; __syncthreads();
    for (int s = 128; s > 0; s >>= 1) { if (d < s) red[d] += red[d+s]; __syncthreads(); }
    float mu = red[0] * (1.f/DM); __syncthreads();
    float c = x - mu;
    red[d] = c * c; __syncthreads();
    for (int s = 128; s > 0; s >>= 1) { if (d < s) red[d] += red[d+s]; __syncthreads(); }
    float var = red[0] * (1.f/DM);
    float y = c * (1.f / sqrtf(var + 1e-5f)) * gamma[d] + beta[d];
    g_core[off] = y;
    if (memout) memout[off] = y;
}

// ---------------- decoder ----------------
__global__ void k_dec(const float* __restrict__ Wd, const float* __restrict__ bd,
                      float* __restrict__ pred) {
    __shared__ float Wds[DM * NLD];
    int t = threadIdx.x;
    for (int i = t; i < DM * NLD; i += 256) Wds[i] = Wd[i];
    __syncthreads();
    int lane = t & 31, w = t >> 5;
    int row = blockIdx.x * 8 + w;          // row = s*BSZ + b
    int b = row & 1, s = row >> 1;
    const float* crow = g_core + (size_t)row * DM;
    float v[8];
#pragma unroll
    for (int i = 0; i < 8; i++) v[i] = crow[lane + i * 32];
#pragma unroll
    for (int l = 0; l < NLD; l++) {
        float acc = 0.f;
#pragma unroll
        for (int i = 0; i < 8; i++) acc += v[i] * Wds[(lane + i * 32) * NLD + l];
#pragma unroll
        for (int o = 16; o > 0; o >>= 1) acc += __shfl_down_sync(0xffffffffu, acc, o);
        if (lane == 0)
            pred[((size_t)b * NLD + l) * SEG + s] = acc + bd[l];
    }
}

// ---------------- host launcher ----------------
extern "C" void kernel_launch(void* const* d_in, const int* in_sizes, int n_in,
                              void* d_out, int out_size) {
    (void)in_sizes; (void)n_in; (void)out_size;
    const float* src      = (const float*)d_in[0];
    const float* mems     = (const float*)d_in[1];
    const unsigned char* mask = (const unsigned char*)d_in[2];
    const float* W_in     = (const float*)d_in[3];
    const float* b_in     = (const float*)d_in[4];
    const float* qkv_w    = (const float*)d_in[5];
    const float* r_net_w  = (const float*)d_in[6];
    const float* o_w      = (const float*)d_in[7];
    const float* ln1_g    = (const float*)d_in[8];
    const float* ln1_b    = (const float*)d_in[9];
    const float* ff_w1    = (const float*)d_in[10];
    const float* ff_b1    = (const float*)d_in[11];
    const float* ff_w2    = (const float*)d_in[12];
    const float* ff_b2    = (const float*)d_in[13];
    const float* ln2_g    = (const float*)d_in[14];
    const float* ln2_b    = (const float*)d_in[15];
    const float* W_dec    = (const float*)d_in[16];
    const float* b_dec    = (const float*)d_in[17];
    const float* r_w_bias = (const float*)d_in[18];
    const float* r_r_bias = (const float*)d_in[19];

    float* out    = (float*)d_out;
    float* pred   = out;
    float* memout = out + PRED_N;

    k_input_proj<<<(CORE_N + 255)/256, 256>>>(src, W_in, b_in, memout);
    k_pos<<<(KL*DM + 255)/256, 256>>>();

    // rk for ALL layers in one z-batched GEMM: g_rk[l] = r @ r_net_w[l]
    k_gemm_tf32<64><<<dim3(DM/64, KL/64, LNUM), 256>>>(nullptr, 1, r_net_w, 6,
                                                       KL, DM, DM, nullptr, 0,
                                                       (size_t)DM*DM, (size_t)KL*DM);

    static float* rk_dev = nullptr;
    if (!rk_dev) cudaGetSymbolAddress((void**)&rk_dev, g_rk);

    for (int i = 0; i < LNUM; i++) {
        // heads = [mems_i ; core] @ qkv_w[i]   [4096 x 768 x 256], cat fused
        k_gemm_tf32<128><<<dim3(H3/64, (KL*BSZ)/128, 1), 256>>>(mems + (size_t)i * MEML*BSZ*DM, 100,
                                                                qkv_w + (size_t)i*DM*H3, 5,
                                                                KL*BSZ, H3, DM, nullptr, 0, 0, 0);
        // AC and BDpre in one launch (z = bh*2+mode), 128x128 tiles, fp16 outputs
        k_qk_tf32<<<dim3(KL/128, SEG/128, BSZ*NH*2), 256>>>(r_w_bias, r_r_bias,
                                                            rk_dev + (size_t)i*KL*DM);
        // shift + combine + mask + softmax (fp16 in place)
        k_softmax<<<dim3(SEG, BSZ*NH), 256>>>(mask);
        // PV split-K (partials; reduction folded into the o-proj GEMM A-load)
        k_pv_tf32<<<dim3(SEG/64, BSZ*NH, 4), 128>>>();
        // attn output projection     [2048 x 256 x 256], A = sum of PV partials
        k_gemm_tf32<64><<<dim3(DM/64, (SEG*BSZ)/64, 1), 256>>>(nullptr, 101, o_w + (size_t)i*DM*DM, 4,
                                                               SEG*BSZ, DM, DM, nullptr, 0, 0, 0);
        k_addln<<<SEG*BSZ, DM>>>(4, ln1_g + i*DM, ln1_b + i*DM, nullptr);
        // ff1 + bias + relu          [2048 x 1024 x 256]
        k_gemm_tf32<128><<<dim3(DI/64, (SEG*BSZ)/128, 1), 256>>>(nullptr, 3, ff_w1 + (size_t)i*DM*DI, 4,
                                                                 SEG*BSZ, DI, DM, ff_b1 + i*DI, 1, 0, 0);
        // ff2 + bias                 [2048 x 256 x 1024]
        k_gemm_tf32<64><<<dim3(DM/64, (SEG*BSZ)/64, 1), 256>>>(nullptr, 4, ff_w2 + (size_t)i*DI*DM, 2,
                                                               SEG*BSZ, DM, DI, ff_b2 + i*DM, 0, 0, 0);
        k_addln<<<SEG*BSZ, DM>>>(2, ln2_g + i*DM, ln2_b + i*DM,
                                 memout + (size_t)(i+1)*CORE_N);
    }
    k_dec<<<(SEG*BSZ)/8, 256>>>(W_dec, b_dec, pred);
}

// round 10
// speedup vs baseline: 1.9419x; 1.0749x over previous
#include <cuda_runtime.h>
#include <cuda_fp16.h>
#include <math.h>

#define LNUM 4
#define DM   256
#define NH   8
#define DHH  32
#define DI   1024
#define SEG  1024
#define MEML 1024
#define KL   2048
#define BSZ  2
#define NLD  12
#define H3   768          // 3*H*DH
#define PRED_N (BSZ*NLD*SEG)
#define CORE_N (SEG*BSZ*DM)
#define SCALE 0.17677669529663687f   // 1/sqrt(32)

// ---------------- scratch (static device globals; no runtime allocation) ----------------
__device__ float  g_core   [CORE_N];
__device__ __half g_heads_h[KL*BSZ*H3];              // qkv heads, fp16
__device__ float  g_r      [KL*DM];
__device__ __half g_rk_h   [LNUM*KL*DM];             // all layers, fp16
__device__ float  g_vec    [CORE_N];
__device__ float  g_mid    [SEG*BSZ*DI];
__device__ __half g_AC     [(size_t)BSZ*NH*SEG*KL];  // AC scores / probs (in-place, fp16)
__device__ __half g_BD     [(size_t)BSZ*NH*SEG*KL];  // pre-shift BD (fp16)
__device__ float  g_pvp    [4*CORE_N];               // PV split-K partials

__device__ __forceinline__ float* bufsel(int id) {
    switch (id) {
        case 1: return g_r;
        case 2: return g_vec;
        case 3: return g_core;
        case 4: return g_mid;
    }
    return g_core;
}

// ---------------- mma helpers ----------------
// tf32 mma; operands carry raw fp32 bits (HW uses tf32 field; RZ on low bits)
__device__ __forceinline__ void mma_tf32(float& c0, float& c1, float& c2, float& c3,
                                         unsigned a0, unsigned a1, unsigned a2, unsigned a3,
                                         unsigned b0, unsigned b1) {
    asm volatile(
        "mma.sync.aligned.m16n8k8.row.col.f32.tf32.tf32.f32 "
        "{%0,%1,%2,%3},{%4,%5,%6,%7},{%8,%9},{%0,%1,%2,%3};\n"
        : "+f"(c0), "+f"(c1), "+f"(c2), "+f"(c3)
        : "r"(a0), "r"(a1), "r"(a2), "r"(a3), "r"(b0), "r"(b1));
}
// fp16 mma m16n8k16, fp32 accumulate
__device__ __forceinline__ void mma_f16(float& c0, float& c1, float& c2, float& c3,
                                        unsigned a0, unsigned a1, unsigned a2, unsigned a3,
                                        unsigned b0, unsigned b1) {
    asm volatile(
        "mma.sync.aligned.m16n8k16.row.col.f32.f16.f16.f32 "
        "{%0,%1,%2,%3},{%4,%5,%6,%7},{%8,%9},{%0,%1,%2,%3};\n"
        : "+f"(c0), "+f"(c1), "+f"(c2), "+f"(c3)
        : "r"(a0), "r"(a1), "r"(a2), "r"(a3), "r"(b0), "r"(b1));
}
__device__ __forceinline__ void cp16(void* smem_dst, const void* gsrc) {
    unsigned dst = (unsigned)__cvta_generic_to_shared(smem_dst);
    asm volatile("cp.async.ca.shared.global [%0], [%1], 16;\n" :: "r"(dst), "l"(gsrc));
}

// ---------------- input projection ----------------
__global__ void k_input_proj(const float* __restrict__ src, const float* __restrict__ W_in,
                             const float* __restrict__ b_in, float* __restrict__ memout) {
    int idx = blockIdx.x * blockDim.x + threadIdx.x;
    if (idx >= CORE_N) return;
    int d  = idx & (DM - 1);
    int sb = idx >> 8;
    int b  = sb & 1;
    int s  = sb >> 1;
    float acc = b_in[d];
#pragma unroll
    for (int l = 0; l < NLD; l++)
        acc += src[((size_t)b * NLD + l) * SEG + s] * W_in[l * DM + d];
    g_core[idx] = acc;
    memout[idx] = acc;   // new_mems[0] == hids[0]
}

// ---------------- positional embedding r[KLEN, D] ----------------
__global__ void k_pos() {
    int idx = blockIdx.x * blockDim.x + threadIdx.x;
    if (idx >= KL * DM) return;
    int d = idx & (DM - 1);
    int j = idx >> 8;
    float pos = (float)(KL - 1 - j);
    int f = (d < 128) ? d : d - 128;
    float inv = powf(10000.f, -(float)f / 128.f);
    float v = pos * inv;
    g_r[idx] = (d < 128) ? sinf(v) : cosf(v);
}

// ---------------- tf32 GEMM, cp.async 2-stage pipelined ----------------
// BM in {128,64}, BN=64, BK=16, 256 threads (8 warps: 4(M) x 2(N)).
// aid==100: virtual cat A (rows < MEML*BSZ from mems_i, else g_core).
// aid==101: A = sum of the 4 PV split-K partials.
// Ch != nullptr: write fp16 output to Ch (+ z*cstride), else fp32 to bufsel(cid).
template<int BM>
__global__ void __launch_bounds__(256) k_gemm_tf32(
        const float* __restrict__ mems_i, int aid,
        const float* __restrict__ Bw, int cid,
        int M, int N, int K,
        const float* __restrict__ bias, int relu,
        size_t bstride, size_t cstride, __half* Ch) {
    constexpr int MT = BM / 64;
    const float* A = bufsel(aid);
    float* C = bufsel(cid) + (size_t)blockIdx.z * cstride;
    if (Ch) Ch += (size_t)blockIdx.z * cstride;
    Bw += (size_t)blockIdx.z * bstride;
    __shared__ float As[2][BM][20];
    __shared__ float Bs[2][16][72];
    int t = threadIdx.x;
    int m0 = blockIdx.y * BM, n0 = blockIdx.x * 64;
    int lane = t & 31, g = lane >> 2, tg = lane & 3;
    int w = t >> 5;
    int wm = (w >> 1) * 16 * MT, wn = (w & 1) * 32;

    float c[MT][4][4];
#pragma unroll
    for (int i = 0; i < MT; i++)
#pragma unroll
        for (int j = 0; j < 4; j++)
#pragma unroll
            for (int q = 0; q < 4; q++) c[i][j][q] = 0.f;

    int ar[MT], ac4[MT];
#pragma unroll
    for (int i = 0; i < MT; i++) { int f = t + i * 256; ar[i] = f >> 2; ac4[i] = (f & 3) * 4; }
    int br = t >> 4, bc4 = (t & 15) * 4;

    auto stage = [&](int k0, int s) {
#pragma unroll
        for (int i = 0; i < MT; i++) {
            int rg = m0 + ar[i];
            if (aid == 101) {
                size_t off = (size_t)rg * K + k0 + ac4[i];
                float4 v0 = *(const float4*)(g_pvp + off);
                float4 v1 = *(const float4*)(g_pvp + CORE_N + off);
                float4 v2 = *(const float4*)(g_pvp + 2*(size_t)CORE_N + off);
                float4 v3 = *(const float4*)(g_pvp + 3*(size_t)CORE_N + off);
                float4 v;
                v.x = v0.x + v1.x + v2.x + v3.x;
                v.y = v0.y + v1.y + v2.y + v3.y;
                v.z = v0.z + v1.z + v2.z + v3.z;
                v.w = v0.w + v1.w + v2.w + v3.w;
                *(float4*)(&As[s][ar[i]][ac4[i]]) = v;
            } else {
                const float* src;
                if (aid == 100)
                    src = (rg < MEML*BSZ) ? (mems_i + (size_t)rg * K + k0 + ac4[i])
                                          : (g_core + (size_t)(rg - MEML*BSZ) * K + k0 + ac4[i]);
                else
                    src = A + (size_t)rg * K + k0 + ac4[i];
                cp16(&As[s][ar[i]][ac4[i]], src);
            }
        }
        cp16(&Bs[s][br][bc4], Bw + (size_t)(k0 + br) * N + n0 + bc4);
        asm volatile("cp.async.commit_group;\n");
    };

    int KT = K / 16;
    stage(0, 0);
    for (int kt = 0; kt < KT; kt++) {
        int s = kt & 1;
        if (kt + 1 < KT) {
            stage((kt + 1) * 16, (kt + 1) & 1);
            asm volatile("cp.async.wait_group 1;\n");
        } else {
            asm volatile("cp.async.wait_group 0;\n");
        }
        __syncthreads();
#pragma unroll
        for (int ks = 0; ks < 16; ks += 8) {
            unsigned a[MT][4], bfrag[4][2];
#pragma unroll
            for (int mt = 0; mt < MT; mt++) {
                int r = wm + mt * 16 + g;
                a[mt][0] = __float_as_uint(As[s][r][ks + tg]);
                a[mt][1] = __float_as_uint(As[s][r + 8][ks + tg]);
                a[mt][2] = __float_as_uint(As[s][r][ks + tg + 4]);
                a[mt][3] = __float_as_uint(As[s][r + 8][ks + tg + 4]);
            }
#pragma unroll
            for (int nt = 0; nt < 4; nt++) {
                int col = wn + nt * 8 + g;
                bfrag[nt][0] = __float_as_uint(Bs[s][ks + tg][col]);
                bfrag[nt][1] = __float_as_uint(Bs[s][ks + tg + 4][col]);
            }
#pragma unroll
            for (int mt = 0; mt < MT; mt++)
#pragma unroll
                for (int nt = 0; nt < 4; nt++)
                    mma_tf32(c[mt][nt][0], c[mt][nt][1], c[mt][nt][2], c[mt][nt][3],
                             a[mt][0], a[mt][1], a[mt][2], a[mt][3],
                             bfrag[nt][0], bfrag[nt][1]);
        }
        __syncthreads();
    }
#pragma unroll
    for (int mt = 0; mt < MT; mt++) {
#pragma unroll
        for (int nt = 0; nt < 4; nt++) {
            int row = m0 + wm + mt * 16 + g;
            int col = n0 + wn + nt * 8 + 2 * tg;
            float b0 = 0.f, b1 = 0.f;
            if (bias) { b0 = bias[col]; b1 = bias[col + 1]; }
            float v0 = c[mt][nt][0] + b0, v1 = c[mt][nt][1] + b1;
            float v2 = c[mt][nt][2] + b0, v3 = c[mt][nt][3] + b1;
            if (relu) {
                v0 = fmaxf(v0, 0.f); v1 = fmaxf(v1, 0.f);
                v2 = fmaxf(v2, 0.f); v3 = fmaxf(v3, 0.f);
            }
            if (Ch) {
                *(__half2*)(Ch + (size_t)row * N + col)       = __floats2half2_rn(v0, v1);
                *(__half2*)(Ch + (size_t)(row + 8) * N + col) = __floats2half2_rn(v2, v3);
            } else {
                *(float2*)(C + (size_t)row * N + col)       = make_float2(v0, v1);
                *(float2*)(C + (size_t)(row + 8) * N + col) = make_float2(v2, v3);
            }
        }
    }
}

// ---------------- fp16 QK^T 128x128: z = bh*2 + mode; mode 0 -> AC, mode 1 -> BDpre ----------------
// warp layout 4(M) x 2(N), warp tile 32x64. K=DH=32, 2 mma K-steps. fp16 in/out, fp32 accum.
__global__ void __launch_bounds__(256) k_qk_f16(
        const float* __restrict__ rwb, const float* __restrict__ rrb,
        const __half* __restrict__ rk_l) {
    int z = blockIdx.z;
    int mode = z & 1, bh = z >> 1, b = bh >> 3, h = bh & 7;
    int i0 = blockIdx.y * 128, j0 = blockIdx.x * 128;
    const __half* Qp = g_heads_h + (size_t)(MEML*BSZ + b) * H3 + h*DHH;
    const __half* Kp; int kstr;
    __half* Cp;
    const float* qb;
    if (mode == 0) { Kp = g_heads_h + (size_t)b*H3 + DM + h*DHH; kstr = BSZ*H3; Cp = g_AC; qb = rwb + h*DHH; }
    else           { Kp = rk_l + h*DHH;                          kstr = DM;     Cp = g_BD; qb = rrb + h*DHH; }
    Cp += (size_t)bh * SEG * KL;

    __shared__ __half Qs[128][40];
    __shared__ __half Ks[128][40];
    int t = threadIdx.x;
    int lane = t & 31, g = lane >> 2, tg = lane & 3;
    int w = t >> 5;
    int wm = (w >> 1) * 32, wn = (w & 1) * 64;

    // Q: 128x32 halves, + fp32 bias
#pragma unroll
    for (int i = 0; i < 2; i++) {
        int f = t + i * 256;
        int r = f >> 2, c8 = (f & 3) * 8;
        float4 raw = *(const float4*)(Qp + (size_t)(i0 + r) * (BSZ*H3) + c8);
        const __half2* hp = (const __half2*)&raw;
#pragma unroll
        for (int q = 0; q < 4; q++) {
            float2 fv = __half22float2(hp[q]);
            *(__half2*)(&Qs[r][c8 + 2*q]) =
                __floats2half2_rn(fv.x + qb[c8 + 2*q], fv.y + qb[c8 + 2*q + 1]);
        }
    }
    // K: 128x32 halves, raw copy
#pragma unroll
    for (int i = 0; i < 2; i++) {
        int f = t + i * 256;
        int r = f >> 2, c8 = (f & 3) * 8;
        float4 raw = *(const float4*)(Kp + (size_t)(j0 + r) * kstr + c8);
        *(float4*)(&Ks[r][c8]) = raw;
    }
    __syncthreads();

    float c[2][8][4];
#pragma unroll
    for (int i = 0; i < 2; i++)
#pragma unroll
        for (int j = 0; j < 8; j++)
#pragma unroll
            for (int q = 0; q < 4; q++) c[i][j][q] = 0.f;

#pragma unroll
    for (int ks = 0; ks < 32; ks += 16) {
        unsigned a[2][4], bfrag[8][2];
#pragma unroll
        for (int mt = 0; mt < 2; mt++) {
            int r = wm + mt * 16 + g;
            a[mt][0] = *(const unsigned*)(&Qs[r][ks + 2*tg]);
            a[mt][1] = *(const unsigned*)(&Qs[r + 8][ks + 2*tg]);
            a[mt][2] = *(const unsigned*)(&Qs[r][ks + 2*tg + 8]);
            a[mt][3] = *(const unsigned*)(&Qs[r + 8][ks + 2*tg + 8]);
        }
#pragma unroll
        for (int nt = 0; nt < 8; nt++) {
            int col = wn + nt * 8 + g;
            bfrag[nt][0] = *(const unsigned*)(&Ks[col][ks + 2*tg]);
            bfrag[nt][1] = *(const unsigned*)(&Ks[col][ks + 2*tg + 8]);
        }
#pragma unroll
        for (int mt = 0; mt < 2; mt++)
#pragma unroll
            for (int nt = 0; nt < 8; nt++)
                mma_f16(c[mt][nt][0], c[mt][nt][1], c[mt][nt][2], c[mt][nt][3],
                        a[mt][0], a[mt][1], a[mt][2], a[mt][3],
                        bfrag[nt][0], bfrag[nt][1]);
    }
#pragma unroll
    for (int mt = 0; mt < 2; mt++)
#pragma unroll
        for (int nt = 0; nt < 8; nt++) {
            int row = i0 + wm + mt * 16 + g;
            int col = j0 + wn + nt * 8 + 2 * tg;
            *(__half2*)(Cp + (size_t)row * KL + col)       = __floats2half2_rn(c[mt][nt][0], c[mt][nt][1]);
            *(__half2*)(Cp + (size_t)(row + 8) * KL + col) = __floats2half2_rn(c[mt][nt][2], c[mt][nt][3]);
        }
}

// ---------------- fused rel_shift + combine + mask + softmax (fp16 in/out, in-place) ----------------
__global__ void k_softmax(const unsigned char* __restrict__ mask) {
    int i = blockIdx.x, bh = blockIdx.y;
    int t = threadIdx.x;
    __half* ac = g_AC + ((size_t)bh * SEG + i) * KL;
    float vals[8];
    float mx = -INFINITY;
#pragma unroll
    for (int r2 = 0; r2 < 4; r2++) {
        int j0 = 2*t + r2 * 512;
        float2 a2 = __half22float2(*(const __half2*)(ac + j0));
#pragma unroll
        for (int q = 0; q < 2; q++) {
            int j = j0 + q;
            int f = SEG + i * KL + j;              // rel_shift flat index
            int a = f / (KL + 1);
            int p = f - a * (KL + 1);
            float bd = (p == 0) ? 0.f : __half2float(g_BD[((size_t)bh * SEG + a) * KL + (p - 1)]);
            float s = ((q ? a2.y : a2.x) + bd) * SCALE;
            if (mask[(size_t)i * KL + j]) s = -INFINITY;
            vals[r2*2 + q] = s;
            mx = fmaxf(mx, s);
        }
    }
    __shared__ float red[256];
    red[t] = mx; __syncthreads();
    for (int s2 = 128; s2 > 0; s2 >>= 1) { if (t < s2) red[t] = fmaxf(red[t], red[t+s2]); __syncthreads(); }
    float rowmax = red[0]; __syncthreads();
    float sum = 0.f;
#pragma unroll
    for (int r2 = 0; r2 < 8; r2++) { vals[r2] = __expf(vals[r2] - rowmax); sum += vals[r2]; }
    red[t] = sum; __syncthreads();
    for (int s2 = 128; s2 > 0; s2 >>= 1) { if (t < s2) red[t] += red[t+s2]; __syncthreads(); }
    float inv = 1.f / red[0];
#pragma unroll
    for (int r2 = 0; r2 < 4; r2++)
        *(__half2*)(ac + 2*t + r2*512) =
            __floats2half2_rn(vals[r2*2] * inv, vals[r2*2+1] * inv);
}

// ---------------- fp16 PV split-K: partial over j-range -> g_pvp[js] ----------------
// BM=64, BN=32, j-chunk 32, 128 threads (4 warps, each 16 rows). grid (SEG/64, BSZ*NH, 4).
__global__ void k_pv_f16() {
    int bh = blockIdx.y, b = bh >> 3, h = bh & 7;
    int i0 = blockIdx.x * 64;
    int js = blockIdx.z;
    const __half* P = g_AC + (size_t)bh * SEG * KL;
    const __half* V = g_heads_h + (size_t)b * H3 + 2*DM + h*DHH;
    const int sV = BSZ*H3;
    float* Out = g_pvp + (size_t)js * CORE_N;

    __shared__ __half Ps[64][40];
    __shared__ __half Vst[32][40];   // transposed: Vst[d][j_rel]
    int t = threadIdx.x;
    int lane = t & 31, g = lane >> 2, tg = lane & 3;
    int w = t >> 5;
    int wm = w * 16;

    float c[4][4];
#pragma unroll
    for (int j = 0; j < 4; j++)
#pragma unroll
        for (int q = 0; q < 4; q++) c[j][q] = 0.f;

    int jb = js * (KL/4), je = jb + (KL/4);
    for (int j0 = jb; j0 < je; j0 += 32) {
        // P tile 64x32 halves, raw copy
#pragma unroll
        for (int i = 0; i < 2; i++) {
            int f = t + i * 128;
            int r = f >> 2, c8 = (f & 3) * 8;
            float4 raw = *(const float4*)(P + (size_t)(i0 + r) * KL + j0 + c8);
            *(float4*)(&Ps[r][c8]) = raw;
        }
        // V tile 32x32 halves -> transposed
        {
            int jr = t >> 2, c8 = (t & 3) * 8;
            float4 raw = *(const float4*)(V + (size_t)(j0 + jr) * sV + c8);
            const __half* hv = (const __half*)&raw;
#pragma unroll
            for (int q = 0; q < 8; q++) Vst[c8 + q][jr] = hv[q];
        }
        __syncthreads();
#pragma unroll
        for (int ks = 0; ks < 32; ks += 16) {
            unsigned a0 = *(const unsigned*)(&Ps[wm + g][ks + 2*tg]);
            unsigned a1 = *(const unsigned*)(&Ps[wm + g + 8][ks + 2*tg]);
            unsigned a2 = *(const unsigned*)(&Ps[wm + g][ks + 2*tg + 8]);
            unsigned a3 = *(const unsigned*)(&Ps[wm + g + 8][ks + 2*tg + 8]);
#pragma unroll
            for (int nt = 0; nt < 4; nt++) {
                int col = nt * 8 + g;
                unsigned b0 = *(const unsigned*)(&Vst[col][ks + 2*tg]);
                unsigned b1 = *(const unsigned*)(&Vst[col][ks + 2*tg + 8]);
                mma_f16(c[nt][0], c[nt][1], c[nt][2], c[nt][3], a0, a1, a2, a3, b0, b1);
            }
        }
        __syncthreads();
    }
#pragma unroll
    for (int nt = 0; nt < 4; nt++) {
        int row = i0 + wm + g;
        int col = h*DHH + nt * 8 + 2 * tg;
        *(float2*)(Out + (size_t)(row * BSZ + b) * DM + col)       = make_float2(c[nt][0], c[nt][1]);
        *(float2*)(Out + (size_t)((row + 8) * BSZ + b) * DM + col) = make_float2(c[nt][2], c[nt][3]);
    }
}

// ---------------- residual add + LayerNorm; optional write to mems output ----------------
__global__ void k_addln(int did, const float* __restrict__ gamma, const float* __restrict__ beta,
                        float* __restrict__ memout) {
    const float* delta = bufsel(did);
    int row = blockIdx.x, d = threadIdx.x;
    size_t off = (size_t)row * DM + d;
    float x = g_core[off] + delta[off];
    __shared__ float red[DM];
    red[d] = x; __syncthreads();
    for (int s = 128; s > 0; s >>= 1) { if (d < s) red[d] += red[d+s]; __syncthreads(); }
    float mu = red[0] * (1.f/DM); __syncthreads();
    float c = x - mu;
    red[d] = c * c; __syncthreads();
    for (int s = 128; s > 0; s >>= 1) { if (d < s) red[d] += red[d+s]; __syncthreads(); }
    float var = red[0] * (1.f/DM);
    float y = c * (1.f / sqrtf(var + 1e-5f)) * gamma[d] + beta[d];
    g_core[off] = y;
    if (memout) memout[off] = y;
}

// ---------------- decoder ----------------
__global__ void k_dec(const float* __restrict__ Wd, const float* __restrict__ bd,
                      float* __restrict__ pred) {
    __shared__ float Wds[DM * NLD];
    int t = threadIdx.x;
    for (int i = t; i < DM * NLD; i += 256) Wds[i] = Wd[i];
    __syncthreads();
    int lane = t & 31, w = t >> 5;
    int row = blockIdx.x * 8 + w;          // row = s*BSZ + b
    int b = row & 1, s = row >> 1;
    const float* crow = g_core + (size_t)row * DM;
    float v[8];
#pragma unroll
    for (int i = 0; i < 8; i++) v[i] = crow[lane + i * 32];
#pragma unroll
    for (int l = 0; l < NLD; l++) {
        float acc = 0.f;
#pragma unroll
        for (int i = 0; i < 8; i++) acc += v[i] * Wds[(lane + i * 32) * NLD + l];
#pragma unroll
        for (int o = 16; o > 0; o >>= 1) acc += __shfl_down_sync(0xffffffffu, acc, o);
        if (lane == 0)
            pred[((size_t)b * NLD + l) * SEG + s] = acc + bd[l];
    }
}

// ---------------- host launcher ----------------
extern "C" void kernel_launch(void* const* d_in, const int* in_sizes, int n_in,
                              void* d_out, int out_size) {
    (void)in_sizes; (void)n_in; (void)out_size;
    const float* src      = (const float*)d_in[0];
    const float* mems     = (const float*)d_in[1];
    const unsigned char* mask = (const unsigned char*)d_in[2];
    const float* W_in     = (const float*)d_in[3];
    const float* b_in     = (const float*)d_in[4];
    const float* qkv_w    = (const float*)d_in[5];
    const float* r_net_w  = (const float*)d_in[6];
    const float* o_w      = (const float*)d_in[7];
    const float* ln1_g    = (const float*)d_in[8];
    const float* ln1_b    = (const float*)d_in[9];
    const float* ff_w1    = (const float*)d_in[10];
    const float* ff_b1    = (const float*)d_in[11];
    const float* ff_w2    = (const float*)d_in[12];
    const float* ff_b2    = (const float*)d_in[13];
    const float* ln2_g    = (const float*)d_in[14];
    const float* ln2_b    = (const float*)d_in[15];
    const float* W_dec    = (const float*)d_in[16];
    const float* b_dec    = (const float*)d_in[17];
    const float* r_w_bias = (const float*)d_in[18];
    const float* r_r_bias = (const float*)d_in[19];

    float* out    = (float*)d_out;
    float* pred   = out;
    float* memout = out + PRED_N;

    static __half* heads_dev = nullptr;
    static __half* rkh_dev = nullptr;
    if (!heads_dev) cudaGetSymbolAddress((void**)&heads_dev, g_heads_h);
    if (!rkh_dev)   cudaGetSymbolAddress((void**)&rkh_dev, g_rk_h);

    k_input_proj<<<(CORE_N + 255)/256, 256>>>(src, W_in, b_in, memout);
    k_pos<<<(KL*DM + 255)/256, 256>>>();

    // rk for ALL layers in one z-batched GEMM (fp16 out): g_rk_h[l] = r @ r_net_w[l]
    k_gemm_tf32<64><<<dim3(DM/64, KL/64, LNUM), 256>>>(nullptr, 1, r_net_w, 0,
                                                       KL, DM, DM, nullptr, 0,
                                                       (size_t)DM*DM, (size_t)KL*DM, rkh_dev);

    for (int i = 0; i < LNUM; i++) {
        // heads = [mems_i ; core] @ qkv_w[i]   [4096 x 768 x 256], cat fused, fp16 out
        k_gemm_tf32<128><<<dim3(H3/64, (KL*BSZ)/128, 1), 256>>>(mems + (size_t)i * MEML*BSZ*DM, 100,
                                                                qkv_w + (size_t)i*DM*H3, 0,
                                                                KL*BSZ, H3, DM, nullptr, 0, 0, 0,
                                                                heads_dev);
        // AC and BDpre in one launch (z = bh*2+mode), 128x128 tiles, fp16 mma
        k_qk_f16<<<dim3(KL/128, SEG/128, BSZ*NH*2), 256>>>(r_w_bias, r_r_bias,
                                                           rkh_dev + (size_t)i*KL*DM);
        // shift + combine + mask + softmax (fp16 in place)
        k_softmax<<<dim3(SEG, BSZ*NH), 256>>>(mask);
        // PV split-K (partials; reduction folded into the o-proj GEMM A-load)
        k_pv_f16<<<dim3(SEG/64, BSZ*NH, 4), 128>>>();
        // attn output projection     [2048 x 256 x 256], A = sum of PV partials
        k_gemm_tf32<64><<<dim3(DM/64, (SEG*BSZ)/64, 1), 256>>>(nullptr, 101, o_w + (size_t)i*DM*DM, 4,
                                                               SEG*BSZ, DM, DM, nullptr, 0, 0, 0, nullptr);
        k_addln<<<SEG*BSZ, DM>>>(4, ln1_g + i*DM, ln1_b + i*DM, nullptr);
        // ff1 + bias + relu          [2048 x 1024 x 256]
        k_gemm_tf32<128><<<dim3(DI/64, (SEG*BSZ)/128, 1), 256>>>(nullptr, 3, ff_w1 + (size_t)i*DM*DI, 4,
                                                                 SEG*BSZ, DI, DM, ff_b1 + i*DI, 1, 0, 0, nullptr);
        // ff2 + bias                 [2048 x 256 x 1024]
        k_gemm_tf32<64><<<dim3(DM/64, (SEG*BSZ)/64, 1), 256>>>(nullptr, 4, ff_w2 + (size_t)i*DI*DM, 2,
                                                               SEG*BSZ, DM, DI, ff_b2 + i*DM, 0, 0, 0, nullptr);
        k_addln<<<SEG*BSZ, DM>>>(2, ln2_g + i*DM, ln2_b + i*DM,
                                 memout + (size_t)(i+1)*CORE_N);
    }
    k_dec<<<(SEG*BSZ)/8, 256>>>(W_dec, b_dec, pred);
}

// round 11
// speedup vs baseline: 2.1915x; 1.1285x over previous
#include <cuda_runtime.h>
#include <cuda_fp16.h>
#include <math.h>

#define LNUM 4
#define DM   256
#define NH   8
#define DHH  32
#define DI   1024
#define SEG  1024
#define MEML 1024
#define KL   2048
#define BSZ  2
#define NLD  12
#define H3   768          // 3*H*DH
#define PRED_N (BSZ*NLD*SEG)
#define CORE_N (SEG*BSZ*DM)
#define SCALE 0.17677669529663687f   // 1/sqrt(32)

// ---------------- scratch (static device globals; no runtime allocation) ----------------
__device__ float  g_core   [CORE_N];
__device__ __half g_core_h [CORE_N];
__device__ __half g_heads_h[KL*BSZ*H3];              // qkv heads, fp16
__device__ __half g_r_h    [KL*DM];
__device__ __half g_rk_h   [LNUM*KL*DM];             // all layers, fp16
__device__ float  g_vec    [CORE_N];
__device__ __half g_mid_h  [SEG*BSZ*DI];
__device__ __half g_AC     [(size_t)BSZ*NH*SEG*KL];  // AC scores / probs (in-place, fp16)
__device__ __half g_BD     [(size_t)BSZ*NH*SEG*KL];  // pre-shift BD (fp16)
__device__ float  g_pvp    [4*CORE_N];               // PV split-K partials
// transposed fp16 weights, [N][K] layout
__device__ __half g_wqkv_h [LNUM*H3*DM];
__device__ __half g_wrnet_h[LNUM*DM*DM];
__device__ __half g_wo_h   [LNUM*DM*DM];
__device__ __half g_wff1_h [LNUM*DI*DM];
__device__ __half g_wff2_h [LNUM*DM*DI];
__device__ __half g_mems_h [LNUM*MEML*BSZ*DM];

// ---------------- mma helpers ----------------
// fp16 mma m16n8k16, fp32 accumulate
__device__ __forceinline__ void mma_f16(float& c0, float& c1, float& c2, float& c3,
                                        unsigned a0, unsigned a1, unsigned a2, unsigned a3,
                                        unsigned b0, unsigned b1) {
    asm volatile(
        "mma.sync.aligned.m16n8k16.row.col.f32.f16.f16.f32 "
        "{%0,%1,%2,%3},{%4,%5,%6,%7},{%8,%9},{%0,%1,%2,%3};\n"
        : "+f"(c0), "+f"(c1), "+f"(c2), "+f"(c3)
        : "r"(a0), "r"(a1), "r"(a2), "r"(a3), "r"(b0), "r"(b1));
}
__device__ __forceinline__ void cp16(void* smem_dst, const void* gsrc) {
    unsigned dst = (unsigned)__cvta_generic_to_shared(smem_dst);
    asm volatile("cp.async.ca.shared.global [%0], [%1], 16;\n" :: "r"(dst), "l"(gsrc));
}

// ---------------- weight prep: W[K][N] fp32 -> Wt[N][K] fp16; z batches matrices ----------------
__global__ void k_transp(const float* __restrict__ W, __half* __restrict__ Wt, int K, int N) {
    __shared__ float tile[32][33];
    W  += (size_t)blockIdx.z * K * N;
    Wt += (size_t)blockIdx.z * K * N;
    int n0 = blockIdx.x * 32, k0 = blockIdx.y * 32;
    int tx = threadIdx.x, ty = threadIdx.y;   // 32 x 8
    for (int r = ty; r < 32; r += 8)
        tile[r][tx] = W[(size_t)(k0 + r) * N + n0 + tx];
    __syncthreads();
    for (int r = ty; r < 32; r += 8)
        Wt[(size_t)(n0 + r) * K + k0 + tx] = __float2half_rn(tile[tx][r]);
}

// ---------------- fp32 -> fp16 elementwise ----------------
__global__ void k_cvt(const float* __restrict__ in, __half* __restrict__ out, int n) {
    int i = (blockIdx.x * blockDim.x + threadIdx.x) * 4;
    if (i >= n) return;
    float4 v = *(const float4*)(in + i);
    __half2* o = (__half2*)(out + i);
    o[0] = __floats2half2_rn(v.x, v.y);
    o[1] = __floats2half2_rn(v.z, v.w);
}

// ---------------- input projection ----------------
__global__ void k_input_proj(const float* __restrict__ src, const float* __restrict__ W_in,
                             const float* __restrict__ b_in, float* __restrict__ memout) {
    int idx = blockIdx.x * blockDim.x + threadIdx.x;
    if (idx >= CORE_N) return;
    int d  = idx & (DM - 1);
    int sb = idx >> 8;
    int b  = sb & 1;
    int s  = sb >> 1;
    float acc = b_in[d];
#pragma unroll
    for (int l = 0; l < NLD; l++)
        acc += src[((size_t)b * NLD + l) * SEG + s] * W_in[l * DM + d];
    g_core[idx] = acc;
    g_core_h[idx] = __float2half_rn(acc);
    memout[idx] = acc;   // new_mems[0] == hids[0]
}

// ---------------- positional embedding r[KLEN, D] (fp16) ----------------
__global__ void k_pos() {
    int idx = blockIdx.x * blockDim.x + threadIdx.x;
    if (idx >= KL * DM) return;
    int d = idx & (DM - 1);
    int j = idx >> 8;
    float pos = (float)(KL - 1 - j);
    int f = (d < 128) ? d : d - 128;
    float inv = powf(10000.f, -(float)f / 128.f);
    float v = pos * inv;
    g_r_h[idx] = __float2half_rn((d < 128) ? sinf(v) : cosf(v));
}

// ---------------- fp16 GEMM, cp.async 2-stage, BK=32 ----------------
// BM in {128,64}, BN=64, 256 threads (8 warps: 4(M) x 2(N)).
// Bh is [N][K] fp16 (pre-transposed). amode: 0 normal Ah, 100 cat(memsh, g_core_h),
// 101 A = fp32 sum of 4 PV partials (converted at stage).
// Output: Cf fp32 or Chh fp16 (one non-null). blockIdx.z batches B/C by strides.
template<int BM>
__global__ void __launch_bounds__(256) k_gemm_f16(
        const __half* __restrict__ Ah, int amode, const __half* __restrict__ memsh,
        const __half* __restrict__ Bh, float* Cf, __half* Chh,
        int M, int N, int K,
        const float* __restrict__ bias, int relu,
        size_t bstride, size_t cstride) {
    constexpr int MT = BM / 64;
    Bh += (size_t)blockIdx.z * bstride;
    if (Cf)  Cf  += (size_t)blockIdx.z * cstride;
    if (Chh) Chh += (size_t)blockIdx.z * cstride;
    __shared__ __half As[2][BM][40];
    __shared__ __half Bs[2][64][40];
    int t = threadIdx.x;
    int m0 = blockIdx.y * BM, n0 = blockIdx.x * 64;
    int lane = t & 31, g = lane >> 2, tg = lane & 3;
    int w = t >> 5;
    int wm = (w >> 1) * 16 * MT, wn = (w & 1) * 32;

    float c[MT][4][4];
#pragma unroll
    for (int i = 0; i < MT; i++)
#pragma unroll
        for (int j = 0; j < 4; j++)
#pragma unroll
            for (int q = 0; q < 4; q++) c[i][j][q] = 0.f;

    auto stage = [&](int k0, int s) {
#pragma unroll
        for (int i = 0; i < MT; i++) {
            int f = t + i * 256;
            int r = f >> 2, c8 = (f & 3) * 8;
            int rg = m0 + r;
            if (amode == 101) {
                size_t off = (size_t)rg * K + k0 + c8;
                float4 u0 = *(const float4*)(g_pvp + off);
                float4 u1 = *(const float4*)(g_pvp + off + 4);
#pragma unroll
                for (int p = 1; p < 4; p++) {
                    size_t o2 = (size_t)p * CORE_N + off;
                    float4 w0 = *(const float4*)(g_pvp + o2);
                    float4 w1 = *(const float4*)(g_pvp + o2 + 4);
                    u0.x += w0.x; u0.y += w0.y; u0.z += w0.z; u0.w += w0.w;
                    u1.x += w1.x; u1.y += w1.y; u1.z += w1.z; u1.w += w1.w;
                }
                __half2* dst = (__half2*)(&As[s][r][c8]);
                dst[0] = __floats2half2_rn(u0.x, u0.y);
                dst[1] = __floats2half2_rn(u0.z, u0.w);
                dst[2] = __floats2half2_rn(u1.x, u1.y);
                dst[3] = __floats2half2_rn(u1.z, u1.w);
            } else {
                const __half* src;
                if (amode == 100)
                    src = (rg < MEML*BSZ) ? (memsh + (size_t)rg * K + k0 + c8)
                                          : (g_core_h + (size_t)(rg - MEML*BSZ) * K + k0 + c8);
                else
                    src = Ah + (size_t)rg * K + k0 + c8;
                cp16(&As[s][r][c8], src);
            }
        }
        {
            int r = t >> 2, c8 = (t & 3) * 8;
            cp16(&Bs[s][r][c8], Bh + (size_t)(n0 + r) * K + k0 + c8);
        }
        asm volatile("cp.async.commit_group;\n");
    };

    int KT = K / 32;
    stage(0, 0);
    for (int kt = 0; kt < KT; kt++) {
        int s = kt & 1;
        if (kt + 1 < KT) {
            stage((kt + 1) * 32, (kt + 1) & 1);
            asm volatile("cp.async.wait_group 1;\n");
        } else {
            asm volatile("cp.async.wait_group 0;\n");
        }
        __syncthreads();
#pragma unroll
        for (int ks = 0; ks < 32; ks += 16) {
            unsigned a[MT][4], bfrag[4][2];
#pragma unroll
            for (int mt = 0; mt < MT; mt++) {
                int r = wm + mt * 16 + g;
                a[mt][0] = *(const unsigned*)(&As[s][r][ks + 2*tg]);
                a[mt][1] = *(const unsigned*)(&As[s][r + 8][ks + 2*tg]);
                a[mt][2] = *(const unsigned*)(&As[s][r][ks + 2*tg + 8]);
                a[mt][3] = *(const unsigned*)(&As[s][r + 8][ks + 2*tg + 8]);
            }
#pragma unroll
            for (int nt = 0; nt < 4; nt++) {
                int col = wn + nt * 8 + g;
                bfrag[nt][0] = *(const unsigned*)(&Bs[s][col][ks + 2*tg]);
                bfrag[nt][1] = *(const unsigned*)(&Bs[s][col][ks + 2*tg + 8]);
            }
#pragma unroll
            for (int mt = 0; mt < MT; mt++)
#pragma unroll
                for (int nt = 0; nt < 4; nt++)
                    mma_f16(c[mt][nt][0], c[mt][nt][1], c[mt][nt][2], c[mt][nt][3],
                            a[mt][0], a[mt][1], a[mt][2], a[mt][3],
                            bfrag[nt][0], bfrag[nt][1]);
        }
        __syncthreads();
    }
#pragma unroll
    for (int mt = 0; mt < MT; mt++) {
#pragma unroll
        for (int nt = 0; nt < 4; nt++) {
            int row = m0 + wm + mt * 16 + g;
            int col = n0 + wn + nt * 8 + 2 * tg;
            float b0 = 0.f, b1 = 0.f;
            if (bias) { b0 = bias[col]; b1 = bias[col + 1]; }
            float v0 = c[mt][nt][0] + b0, v1 = c[mt][nt][1] + b1;
            float v2 = c[mt][nt][2] + b0, v3 = c[mt][nt][3] + b1;
            if (relu) {
                v0 = fmaxf(v0, 0.f); v1 = fmaxf(v1, 0.f);
                v2 = fmaxf(v2, 0.f); v3 = fmaxf(v3, 0.f);
            }
            if (Chh) {
                *(__half2*)(Chh + (size_t)row * N + col)       = __floats2half2_rn(v0, v1);
                *(__half2*)(Chh + (size_t)(row + 8) * N + col) = __floats2half2_rn(v2, v3);
            } else {
                *(float2*)(Cf + (size_t)row * N + col)       = make_float2(v0, v1);
                *(float2*)(Cf + (size_t)(row + 8) * N + col) = make_float2(v2, v3);
            }
        }
    }
}

// ---------------- fp16 QK^T 128x128: z = bh*2 + mode; mode 0 -> AC, mode 1 -> BDpre ----------------
__global__ void __launch_bounds__(256) k_qk_f16(
        const float* __restrict__ rwb, const float* __restrict__ rrb,
        const __half* __restrict__ rk_l) {
    int z = blockIdx.z;
    int mode = z & 1, bh = z >> 1, b = bh >> 3, h = bh & 7;
    int i0 = blockIdx.y * 128, j0 = blockIdx.x * 128;
    const __half* Qp = g_heads_h + (size_t)(MEML*BSZ + b) * H3 + h*DHH;
    const __half* Kp; int kstr;
    __half* Cp;
    const float* qb;
    if (mode == 0) { Kp = g_heads_h + (size_t)b*H3 + DM + h*DHH; kstr = BSZ*H3; Cp = g_AC; qb = rwb + h*DHH; }
    else           { Kp = rk_l + h*DHH;                          kstr = DM;     Cp = g_BD; qb = rrb + h*DHH; }
    Cp += (size_t)bh * SEG * KL;

    __shared__ __half Qs[128][40];
    __shared__ __half Ks[128][40];
    int t = threadIdx.x;
    int lane = t & 31, g = lane >> 2, tg = lane & 3;
    int w = t >> 5;
    int wm = (w >> 1) * 32, wn = (w & 1) * 64;

#pragma unroll
    for (int i = 0; i < 2; i++) {
        int f = t + i * 256;
        int r = f >> 2, c8 = (f & 3) * 8;
        float4 raw = *(const float4*)(Qp + (size_t)(i0 + r) * (BSZ*H3) + c8);
        const __half2* hp = (const __half2*)&raw;
#pragma unroll
        for (int q = 0; q < 4; q++) {
            float2 fv = __half22float2(hp[q]);
            *(__half2*)(&Qs[r][c8 + 2*q]) =
                __floats2half2_rn(fv.x + qb[c8 + 2*q], fv.y + qb[c8 + 2*q + 1]);
        }
    }
#pragma unroll
    for (int i = 0; i < 2; i++) {
        int f = t + i * 256;
        int r = f >> 2, c8 = (f & 3) * 8;
        float4 raw = *(const float4*)(Kp + (size_t)(j0 + r) * kstr + c8);
        *(float4*)(&Ks[r][c8]) = raw;
    }
    __syncthreads();

    float c[2][8][4];
#pragma unroll
    for (int i = 0; i < 2; i++)
#pragma unroll
        for (int j = 0; j < 8; j++)
#pragma unroll
            for (int q = 0; q < 4; q++) c[i][j][q] = 0.f;

#pragma unroll
    for (int ks = 0; ks < 32; ks += 16) {
        unsigned a[2][4], bfrag[8][2];
#pragma unroll
        for (int mt = 0; mt < 2; mt++) {
            int r = wm + mt * 16 + g;
            a[mt][0] = *(const unsigned*)(&Qs[r][ks + 2*tg]);
            a[mt][1] = *(const unsigned*)(&Qs[r + 8][ks + 2*tg]);
            a[mt][2] = *(const unsigned*)(&Qs[r][ks + 2*tg + 8]);
            a[mt][3] = *(const unsigned*)(&Qs[r + 8][ks + 2*tg + 8]);
        }
#pragma unroll
        for (int nt = 0; nt < 8; nt++) {
            int col = wn + nt * 8 + g;
            bfrag[nt][0] = *(const unsigned*)(&Ks[col][ks + 2*tg]);
            bfrag[nt][1] = *(const unsigned*)(&Ks[col][ks + 2*tg + 8]);
        }
#pragma unroll
        for (int mt = 0; mt < 2; mt++)
#pragma unroll
            for (int nt = 0; nt < 8; nt++)
                mma_f16(c[mt][nt][0], c[mt][nt][1], c[mt][nt][2], c[mt][nt][3],
                        a[mt][0], a[mt][1], a[mt][2], a[mt][3],
                        bfrag[nt][0], bfrag[nt][1]);
    }
#pragma unroll
    for (int mt = 0; mt < 2; mt++)
#pragma unroll
        for (int nt = 0; nt < 8; nt++) {
            int row = i0 + wm + mt * 16 + g;
            int col = j0 + wn + nt * 8 + 2 * tg;
            *(__half2*)(Cp + (size_t)row * KL + col)       = __floats2half2_rn(c[mt][nt][0], c[mt][nt][1]);
            *(__half2*)(Cp + (size_t)(row + 8) * KL + col) = __floats2half2_rn(c[mt][nt][2], c[mt][nt][3]);
        }
}

// ---------------- fused rel_shift + combine + mask + softmax (fp16 in/out, in-place) ----------------
__global__ void k_softmax(const unsigned char* __restrict__ mask) {
    int i = blockIdx.x, bh = blockIdx.y;
    int t = threadIdx.x;
    __half* ac = g_AC + ((size_t)bh * SEG + i) * KL;
    float vals[8];
    float mx = -INFINITY;
#pragma unroll
    for (int r2 = 0; r2 < 4; r2++) {
        int j0 = 2*t + r2 * 512;
        float2 a2 = __half22float2(*(const __half2*)(ac + j0));
#pragma unroll
        for (int q = 0; q < 2; q++) {
            int j = j0 + q;
            int f = SEG + i * KL + j;              // rel_shift flat index
            int a = f / (KL + 1);
            int p = f - a * (KL + 1);
            float bd = (p == 0) ? 0.f : __half2float(g_BD[((size_t)bh * SEG + a) * KL + (p - 1)]);
            float s = ((q ? a2.y : a2.x) + bd) * SCALE;
            if (mask[(size_t)i * KL + j]) s = -INFINITY;
            vals[r2*2 + q] = s;
            mx = fmaxf(mx, s);
        }
    }
    __shared__ float red[256];
    red[t] = mx; __syncthreads();
    for (int s2 = 128; s2 > 0; s2 >>= 1) { if (t < s2) red[t] = fmaxf(red[t], red[t+s2]); __syncthreads(); }
    float rowmax = red[0]; __syncthreads();
    float sum = 0.f;
#pragma unroll
    for (int r2 = 0; r2 < 8; r2++) { vals[r2] = __expf(vals[r2] - rowmax); sum += vals[r2]; }
    red[t] = sum; __syncthreads();
    for (int s2 = 128; s2 > 0; s2 >>= 1) { if (t < s2) red[t] += red[t+s2]; __syncthreads(); }
    float inv = 1.f / red[0];
#pragma unroll
    for (int r2 = 0; r2 < 4; r2++)
        *(__half2*)(ac + 2*t + r2*512) =
            __floats2half2_rn(vals[r2*2] * inv, vals[r2*2+1] * inv);
}

// ---------------- fp16 PV split-K: partial over j-range -> g_pvp[js] ----------------
__global__ void k_pv_f16() {
    int bh = blockIdx.y, b = bh >> 3, h = bh & 7;
    int i0 = blockIdx.x * 64;
    int js = blockIdx.z;
    const __half* P = g_AC + (size_t)bh * SEG * KL;
    const __half* V = g_heads_h + (size_t)b * H3 + 2*DM + h*DHH;
    const int sV = BSZ*H3;
    float* Out = g_pvp + (size_t)js * CORE_N;

    __shared__ __half Ps[64][40];
    __shared__ __half Vst[32][40];   // transposed: Vst[d][j_rel]
    int t = threadIdx.x;
    int lane = t & 31, g = lane >> 2, tg = lane & 3;
    int w = t >> 5;
    int wm = w * 16;

    float c[4][4];
#pragma unroll
    for (int j = 0; j < 4; j++)
#pragma unroll
        for (int q = 0; q < 4; q++) c[j][q] = 0.f;

    int jb = js * (KL/4), je = jb + (KL/4);
    for (int j0 = jb; j0 < je; j0 += 32) {
#pragma unroll
        for (int i = 0; i < 2; i++) {
            int f = t + i * 128;
            int r = f >> 2, c8 = (f & 3) * 8;
            float4 raw = *(const float4*)(P + (size_t)(i0 + r) * KL + j0 + c8);
            *(float4*)(&Ps[r][c8]) = raw;
        }
        {
            int jr = t >> 2, c8 = (t & 3) * 8;
            float4 raw = *(const float4*)(V + (size_t)(j0 + jr) * sV + c8);
            const __half* hv = (const __half*)&raw;
#pragma unroll
            for (int q = 0; q < 8; q++) Vst[c8 + q][jr] = hv[q];
        }
        __syncthreads();
#pragma unroll
        for (int ks = 0; ks < 32; ks += 16) {
            unsigned a0 = *(const unsigned*)(&Ps[wm + g][ks + 2*tg]);
            unsigned a1 = *(const unsigned*)(&Ps[wm + g + 8][ks + 2*tg]);
            unsigned a2 = *(const unsigned*)(&Ps[wm + g][ks + 2*tg + 8]);
            unsigned a3 = *(const unsigned*)(&Ps[wm + g + 8][ks + 2*tg + 8]);
#pragma unroll
            for (int nt = 0; nt < 4; nt++) {
                int col = nt * 8 + g;
                unsigned b0 = *(const unsigned*)(&Vst[col][ks + 2*tg]);
                unsigned b1 = *(const unsigned*)(&Vst[col][ks + 2*tg + 8]);
                mma_f16(c[nt][0], c[nt][1], c[nt][2], c[nt][3], a0, a1, a2, a3, b0, b1);
            }
        }
        __syncthreads();
    }
#pragma unroll
    for (int nt = 0; nt < 4; nt++) {
        int row = i0 + wm + g;
        int col = h*DHH + nt * 8 + 2 * tg;
        *(float2*)(Out + (size_t)(row * BSZ + b) * DM + col)       = make_float2(c[nt][0], c[nt][1]);
        *(float2*)(Out + (size_t)((row + 8) * BSZ + b) * DM + col) = make_float2(c[nt][2], c[nt][3]);
    }
}

// ---------------- residual add + LayerNorm; writes core, core_h, optional memout ----------------
__global__ void k_addln(const float* __restrict__ gamma, const float* __restrict__ beta,
                        float* __restrict__ memout) {
    int row = blockIdx.x, d = threadIdx.x;
    size_t off = (size_t)row * DM + d;
    float x = g_core[off] + g_vec[off];
    __shared__ float red[DM];
    red[d] = x; __syncthreads();
    for (int s = 128; s > 0; s >>= 1) { if (d < s) red[d] += red[d+s]; __syncthreads(); }
    float mu = red[0] * (1.f/DM); __syncthreads();
    float c = x - mu;
    red[d] = c * c; __syncthreads();
    for (int s = 128; s > 0; s >>= 1) { if (d < s) red[d] += red[d+s]; __syncthreads(); }
    float var = red[0] * (1.f/DM);
    float y = c * (1.f / sqrtf(var + 1e-5f)) * gamma[d] + beta[d];
    g_core[off] = y;
    g_core_h[off] = __float2half_rn(y);
    if (memout) memout[off] = y;
}

// ---------------- decoder ----------------
__global__ void k_dec(const float* __restrict__ Wd, const float* __restrict__ bd,
                      float* __restrict__ pred) {
    __shared__ float Wds[DM * NLD];
    int t = threadIdx.x;
    for (int i = t; i < DM * NLD; i += 256) Wds[i] = Wd[i];
    __syncthreads();
    int lane = t & 31, w = t >> 5;
    int row = blockIdx.x * 8 + w;          // row = s*BSZ + b
    int b = row & 1, s = row >> 1;
    const float* crow = g_core + (size_t)row * DM;
    float v[8];
#pragma unroll
    for (int i = 0; i < 8; i++) v[i] = crow[lane + i * 32];
#pragma unroll
    for (int l = 0; l < NLD; l++) {
        float acc = 0.f;
#pragma unroll
        for (int i = 0; i < 8; i++) acc += v[i] * Wds[(lane + i * 32) * NLD + l];
#pragma unroll
        for (int o = 16; o > 0; o >>= 1) acc += __shfl_down_sync(0xffffffffu, acc, o);
        if (lane == 0)
            pred[((size_t)b * NLD + l) * SEG + s] = acc + bd[l];
    }
}

// ---------------- host launcher ----------------
extern "C" void kernel_launch(void* const* d_in, const int* in_sizes, int n_in,
                              void* d_out, int out_size) {
    (void)in_sizes; (void)n_in; (void)out_size;
    const float* src      = (const float*)d_in[0];
    const float* mems     = (const float*)d_in[1];
    const unsigned char* mask = (const unsigned char*)d_in[2];
    const float* W_in     = (const float*)d_in[3];
    const float* b_in     = (const float*)d_in[4];
    const float* qkv_w    = (const float*)d_in[5];
    const float* r_net_w  = (const float*)d_in[6];
    const float* o_w      = (const float*)d_in[7];
    const float* ln1_g    = (const float*)d_in[8];
    const float* ln1_b    = (const float*)d_in[9];
    const float* ff_w1    = (const float*)d_in[10];
    const float* ff_b1    = (const float*)d_in[11];
    const float* ff_w2    = (const float*)d_in[12];
    const float* ff_b2    = (const float*)d_in[13];
    const float* ln2_g    = (const float*)d_in[14];
    const float* ln2_b    = (const float*)d_in[15];
    const float* W_dec    = (const float*)d_in[16];
    const float* b_dec    = (const float*)d_in[17];
    const float* r_w_bias = (const float*)d_in[18];
    const float* r_r_bias = (const float*)d_in[19];

    float* out    = (float*)d_out;
    float* pred   = out;
    float* memout = out + PRED_N;

    static __half *heads_p=nullptr, *rkh_p=nullptr, *rh_p=nullptr, *coreh_p=nullptr,
                  *midh_p=nullptr, *wqkv_p=nullptr, *wrnet_p=nullptr, *wo_p=nullptr,
                  *wff1_p=nullptr, *wff2_p=nullptr, *memsh_p=nullptr;
    static float *vec_p=nullptr;
    if (!heads_p) {
        cudaGetSymbolAddress((void**)&heads_p, g_heads_h);
        cudaGetSymbolAddress((void**)&rkh_p,   g_rk_h);
        cudaGetSymbolAddress((void**)&rh_p,    g_r_h);
        cudaGetSymbolAddress((void**)&coreh_p, g_core_h);
        cudaGetSymbolAddress((void**)&midh_p,  g_mid_h);
        cudaGetSymbolAddress((void**)&wqkv_p,  g_wqkv_h);
        cudaGetSymbolAddress((void**)&wrnet_p, g_wrnet_h);
        cudaGetSymbolAddress((void**)&wo_p,    g_wo_h);
        cudaGetSymbolAddress((void**)&wff1_p,  g_wff1_h);
        cudaGetSymbolAddress((void**)&wff2_p,  g_wff2_h);
        cudaGetSymbolAddress((void**)&memsh_p, g_mems_h);
        cudaGetSymbolAddress((void**)&vec_p,   g_vec);
    }

    // ---- prep: transpose+convert weights, convert mems, input proj, pos emb ----
    dim3 tb(32, 8);
    k_transp<<<dim3(H3/32, DM/32, LNUM), tb>>>(qkv_w,   wqkv_p,  DM, H3);
    k_transp<<<dim3(DM/32, DM/32, LNUM), tb>>>(r_net_w, wrnet_p, DM, DM);
    k_transp<<<dim3(DM/32, DM/32, LNUM), tb>>>(o_w,     wo_p,    DM, DM);
    k_transp<<<dim3(DI/32, DM/32, LNUM), tb>>>(ff_w1,   wff1_p,  DM, DI);
    k_transp<<<dim3(DM/32, DI/32, LNUM), tb>>>(ff_w2,   wff2_p,  DI, DM);
    k_cvt<<<(LNUM*MEML*BSZ*DM/4 + 255)/256, 256>>>(mems, memsh_p, LNUM*MEML*BSZ*DM);
    k_input_proj<<<(CORE_N + 255)/256, 256>>>(src, W_in, b_in, memout);
    k_pos<<<(KL*DM + 255)/256, 256>>>();

    // rk for ALL layers, z-batched fp16 GEMM: rk_h[l] = r @ r_net_w[l]
    k_gemm_f16<64><<<dim3(DM/64, KL/64, LNUM), 256>>>(rh_p, 0, nullptr, wrnet_p,
                                                      nullptr, rkh_p, KL, DM, DM,
                                                      nullptr, 0, (size_t)DM*DM, (size_t)KL*DM);

    for (int i = 0; i < LNUM; i++) {
        // heads = [mems_h_i ; core_h] @ qkv_w[i]   [4096 x 768 x 256]
        k_gemm_f16<128><<<dim3(H3/64, (KL*BSZ)/128, 1), 256>>>(
            nullptr, 100, memsh_p + (size_t)i * MEML*BSZ*DM, wqkv_p + (size_t)i*H3*DM,
            nullptr, heads_p, KL*BSZ, H3, DM, nullptr, 0, 0, 0);
        // AC and BDpre in one launch (z = bh*2+mode), 128x128 tiles, fp16 mma
        k_qk_f16<<<dim3(KL/128, SEG/128, BSZ*NH*2), 256>>>(r_w_bias, r_r_bias,
                                                           rkh_p + (size_t)i*KL*DM);
        // shift + combine + mask + softmax (fp16 in place)
        k_softmax<<<dim3(SEG, BSZ*NH), 256>>>(mask);
        // PV split-K (partials; reduction folded into the o-proj GEMM A-load)
        k_pv_f16<<<dim3(SEG/64, BSZ*NH, 4), 128>>>();
        // attn output projection [2048 x 256 x 256], A = sum of PV partials -> g_vec fp32
        k_gemm_f16<64><<<dim3(DM/64, (SEG*BSZ)/64, 1), 256>>>(
            nullptr, 101, nullptr, wo_p + (size_t)i*DM*DM,
            vec_p, nullptr, SEG*BSZ, DM, DM, nullptr, 0, 0, 0);
        k_addln<<<SEG*BSZ, DM>>>(ln1_g + i*DM, ln1_b + i*DM, nullptr);
        // ff1 + bias + relu [2048 x 1024 x 256] -> mid_h fp16
        k_gemm_f16<128><<<dim3(DI/64, (SEG*BSZ)/128, 1), 256>>>(
            coreh_p, 0, nullptr, wff1_p + (size_t)i*DI*DM,
            nullptr, midh_p, SEG*BSZ, DI, DM, ff_b1 + i*DI, 1, 0, 0);
        // ff2 + bias [2048 x 256 x 1024] -> g_vec fp32
        k_gemm_f16<64><<<dim3(DM/64, (SEG*BSZ)/64, 1), 256>>>(
            midh_p, 0, nullptr, wff2_p + (size_t)i*DM*DI,
            vec_p, nullptr, SEG*BSZ, DM, DI, ff_b2 + i*DM, 0, 0, 0);
        k_addln<<<SEG*BSZ, DM>>>(ln2_g + i*DM, ln2_b + i*DM,
                                 memout + (size_t)(i+1)*CORE_N);
    }
    k_dec<<<(SEG*BSZ)/8, 256>>>(W_dec, b_dec, pred);
}